// round 13
// baseline (speedup 1.0000x reference)
#include <cuda_runtime.h>
#include <cuda_bf16.h>
#include <math.h>
#include <stdint.h>

#define EPS 1e-4f

#define B_  2048
#define H1_ 23
#define W1_ 31
#define H2_ 11
#define W2_ 15
#define H3_ 5
#define W3_ 7

#define S1 (B_*H1_*W1_)
#define S2 (B_*H2_*W2_)
#define S3 (B_*H3_*W3_)

// ---------------- scratch ----------------
__device__ __align__(16) float g_xm[S1*2];
__device__ __align__(16) float g_m1[S1];
__device__ __align__(16) float g_h1[S1*16];
__device__ __align__(16) __nv_bfloat16 g_h1h[S1*16];
__device__ __align__(16) __nv_bfloat16 g_h1l[S1*16];
__device__ __align__(16) float g_h2[S1*32];
__device__ __align__(16) __nv_bfloat16 g_p1h[S2*32];
__device__ __align__(16) __nv_bfloat16 g_p1l[S2*32];
__device__ __align__(16) float g_m2[S2];
__device__ __align__(16) float g_h3[S2*64];
__device__ __align__(16) int8_t g_h3q0[S2*64], g_h3q1[S2*64];
__device__ __align__(16) float g_h4[S2*128];
__device__ __align__(16) float g_p2f[S3*128];
__device__ __align__(16) int8_t g_p2q0[S3*128], g_p2q1[S3*128];
__device__ __align__(16) float g_m3[S3];
__device__ __align__(16) float g_gates[S3*768];
__device__ __align__(16) float g_flatf[B_*8960];
__device__ __align__(16) int8_t g_fq0[B_*8960], g_fq1[B_*8960];
__device__ __align__(16) __nv_bfloat16 g_y1h[B_*1024];
__device__ __align__(16) __nv_bfloat16 g_y1l[B_*1024];
__device__ __align__(16) float g_stats[560];
// bf16 transposed weights (conv2, conv3, FC2)
__device__ __align__(16) __nv_bfloat16 g_w2h[32*144],   g_w2l[32*144];
__device__ __align__(16) __nv_bfloat16 g_w3h[64*288],   g_w3l[64*288];
__device__ __align__(16) __nv_bfloat16 g_l2h[448*1024], g_l2l[448*1024];
// int8 transposed weights (conv4, gate, FC1)
__device__ __align__(16) int8_t g_w4q0[128*576],   g_w4q1[128*576];
__device__ __align__(16) int8_t g_wlq0[768*1152],  g_wlq1[768*1152];
__device__ __align__(16) int8_t g_l1q0[1024*8960], g_l1q1[1024*8960];

__host__ __device__ constexpr int ilog2c(int x) { return x <= 1 ? 0 : 1 + ilog2c(x >> 1); }

#define FMA2(d, a, b) asm("fma.rn.f32x2 %0, %1, %2, %0;" : "+l"(d) : "l"(a), "l"(b))
#define SWZ128(x) ((x) ^ (((x) >> 3) & 0x70))

__device__ __forceinline__ uint32_t smem_u32(const void* p) {
    uint32_t a;
    asm("{ .reg .u64 t; cvta.to.shared.u64 t, %1; cvt.u32.u64 %0, t; }" : "=r"(a) : "l"(p));
    return a;
}

#define LDSM_X4(r0, r1, r2, r3, addr) \
    asm volatile("ldmatrix.sync.aligned.m8n8.x4.shared.b16 {%0,%1,%2,%3}, [%4];" \
        : "=r"(r0), "=r"(r1), "=r"(r2), "=r"(r3) : "r"(addr))

#define MMA_BF16(d, a0, a1, a2, a3, b0, b1) \
    asm volatile("mma.sync.aligned.m16n8k16.row.col.f32.bf16.bf16.f32 " \
        "{%0,%1,%2,%3}, {%4,%5,%6,%7}, {%8,%9}, {%0,%1,%2,%3};" \
        : "+f"((d)[0]), "+f"((d)[1]), "+f"((d)[2]), "+f"((d)[3]) \
        : "r"(a0), "r"(a1), "r"(a2), "r"(a3), "r"(b0), "r"(b1))

#define MMA_S8(d, a0, a1, a2, a3, b0, b1) \
    asm volatile("mma.sync.aligned.m16n8k32.row.col.s32.s8.s8.s32 " \
        "{%0,%1,%2,%3}, {%4,%5,%6,%7}, {%8,%9}, {%0,%1,%2,%3};" \
        : "+r"((d)[0]), "+r"((d)[1]), "+r"((d)[2]), "+r"((d)[3]) \
        : "r"(a0), "r"(a1), "r"(a2), "r"(a3), "r"(b0), "r"(b1))

__device__ __forceinline__ uint32_t bpack(float a, float b) {
    __nv_bfloat162 t;
    t.x = __float2bfloat16(a);
    t.y = __float2bfloat16(b);
    return *reinterpret_cast<uint32_t*>(&t);
}
__device__ __forceinline__ float bres(float x) {
    return x - __bfloat162float(__float2bfloat16(x));
}

// ---------------- small kernels ----------------
__global__ void k_zero_stats(float* st) {
    if (threadIdx.x < 560) st[threadIdx.x] = 0.f;
}

__global__ void k_prep(const float* __restrict__ x, const int* __restrict__ mask,
                       float* __restrict__ xm, float* __restrict__ m1, float* nP) {
    int s = blockIdx.x * blockDim.x + threadIdx.x;
    int act = 0;
    if (s < S1) {
        float m = (float)mask[s];
        m1[s] = m;
        xm[2*s]   = x[2*s]   * m;
        xm[2*s+1] = x[2*s+1] * m;
        act = (m > 0.f);
    }
    __shared__ int sh[256];
    sh[threadIdx.x] = act; __syncthreads();
    for (int o = 128; o > 0; o >>= 1) { if (threadIdx.x < o) sh[threadIdx.x] += sh[threadIdx.x+o]; __syncthreads(); }
    if (threadIdx.x == 0 && sh[0]) atomicAdd(nP, (float)sh[0]);
}

// weight transpose + bf16 split
template<int REMAP>
__global__ void k_wt(const float* __restrict__ W, __nv_bfloat16* __restrict__ Wh,
                     __nv_bfloat16* __restrict__ Wl, int K, int N, int ldb) {
    __shared__ float t[32][33];
    int k = blockIdx.x*32 + threadIdx.y;
    int n = blockIdx.y*32 + threadIdx.x;
    int nn = (REMAP && n >= 256) ? n + 256 : n;
    t[threadIdx.y][threadIdx.x] = (k < K && n < N) ? W[(size_t)k*ldb + nn] : 0.f;
    __syncthreads();
    int ko = blockIdx.x*32 + threadIdx.x;
    int no = blockIdx.y*32 + threadIdx.y;
    if (ko < K) {
        float v = t[threadIdx.x][threadIdx.y];
        __nv_bfloat16 h = __float2bfloat16(v);
        Wh[(size_t)no*K + ko] = h;
        Wl[(size_t)no*K + ko] = __float2bfloat16(v - __bfloat162float(h));
    }
}

// grid-stride max |W|
__global__ void k_wmax(const float* __restrict__ W, int total, float* outP) {
    float m = 0.f;
    for (int i = blockIdx.x * blockDim.x + threadIdx.x; i < total; i += gridDim.x * blockDim.x)
        m = fmaxf(m, fabsf(W[i]));
    __shared__ float sh[256];
    sh[threadIdx.x] = m; __syncthreads();
    for (int o = 128; o > 0; o >>= 1) { if (threadIdx.x < o) sh[threadIdx.x] = fmaxf(sh[threadIdx.x], sh[threadIdx.x+o]); __syncthreads(); }
    if (threadIdx.x == 0) atomicMax((unsigned*)outP, __float_as_uint(sh[0]));
}

// weight transpose + int8 2-digit quantize
template<int REMAP>
__global__ void k_wq(const float* __restrict__ W, int8_t* __restrict__ d0,
                     int8_t* __restrict__ d1, int K, int N, int ldb,
                     const float* __restrict__ maxP) {
    __shared__ float t[32][33];
    int k = blockIdx.x*32 + threadIdx.y;
    int n = blockIdx.y*32 + threadIdx.x;
    int nn = (REMAP && n >= 256) ? n + 256 : n;
    t[threadIdx.y][threadIdx.x] = (k < K && n < N) ? W[(size_t)k*ldb + nn] : 0.f;
    __syncthreads();
    float Q = 127.f / fmaxf(*maxP, 1e-20f);
    int ko = blockIdx.x*32 + threadIdx.x;
    int no = blockIdx.y*32 + threadIdx.y;
    if (ko < K) {
        float q = t[threadIdx.x][threadIdx.y] * Q;
        int f0 = __float2int_rn(q);
        int f1 = __float2int_rn(128.f * (q - (float)f0));
        d0[(size_t)no*K + ko] = (int8_t)f0;
        d1[(size_t)no*K + ko] = (int8_t)f1;
    }
}

// BN apply -> bf16 hi/lo (layer 1)
template<int CSH>
__global__ void k_apply3(const float* __restrict__ v, const float* __restrict__ mf,
                         int sites,
                         const float* __restrict__ sumP, const float* __restrict__ sqP,
                         const float* __restrict__ nP,
                         const float* __restrict__ gamma, const float* __restrict__ beta,
                         __nv_bfloat16* __restrict__ oh, __nv_bfloat16* __restrict__ ol) {
    constexpr int C = 1 << CSH;
    __shared__ float sc[C], so[C];
    if (threadIdx.x < C) {
        float n = fmaxf(nP[0], 1.f);
        float mean = sumP[threadIdx.x] / n;
        float var  = sqP[threadIdx.x] / n - mean*mean;
        float rs   = rsqrtf(var + EPS) * gamma[threadIdx.x];
        sc[threadIdx.x] = rs;
        so[threadIdx.x] = beta[threadIdx.x] - mean * rs;
    }
    __syncthreads();
    int i = blockIdx.x * blockDim.x + threadIdx.x;
    int total4 = (sites << CSH) >> 2;
    if (i < total4) {
        int e = i * 4;
        int c0 = e & (C-1);
        float m = mf[e >> CSH];
        float4 t = *reinterpret_cast<const float4*>(&v[e]);
        t.x = fmaxf(t.x*sc[c0+0] + so[c0+0], 0.f) * m;
        t.y = fmaxf(t.y*sc[c0+1] + so[c0+1], 0.f) * m;
        t.z = fmaxf(t.z*sc[c0+2] + so[c0+2], 0.f) * m;
        t.w = fmaxf(t.w*sc[c0+3] + so[c0+3], 0.f) * m;
        *reinterpret_cast<uint2*>(&oh[e]) = make_uint2(bpack(t.x, t.y), bpack(t.z, t.w));
        *reinterpret_cast<uint2*>(&ol[e]) =
            make_uint2(bpack(bres(t.x), bres(t.y)), bpack(bres(t.z), bres(t.w)));
    }
}

// BN apply in-place fp32 + tensor max (layer 3)
template<int CSH>
__global__ void k_apply3Q(float* __restrict__ v, const float* __restrict__ mf,
                          int sites,
                          const float* __restrict__ sumP, const float* __restrict__ sqP,
                          const float* __restrict__ nP,
                          const float* __restrict__ gamma, const float* __restrict__ beta,
                          float* __restrict__ maxP) {
    constexpr int C = 1 << CSH;
    __shared__ float sc[C], so[C];
    if (threadIdx.x < C) {
        float n = fmaxf(nP[0], 1.f);
        float mean = sumP[threadIdx.x] / n;
        float var  = sqP[threadIdx.x] / n - mean*mean;
        float rs   = rsqrtf(var + EPS) * gamma[threadIdx.x];
        sc[threadIdx.x] = rs;
        so[threadIdx.x] = beta[threadIdx.x] - mean * rs;
    }
    __syncthreads();
    int i = blockIdx.x * blockDim.x + threadIdx.x;
    int total4 = (sites << CSH) >> 2;
    float lm = 0.f;
    if (i < total4) {
        int e = i * 4;
        int c0 = e & (C-1);
        float m = mf[e >> CSH];
        float4 t = *reinterpret_cast<const float4*>(&v[e]);
        t.x = fmaxf(t.x*sc[c0+0] + so[c0+0], 0.f) * m;
        t.y = fmaxf(t.y*sc[c0+1] + so[c0+1], 0.f) * m;
        t.z = fmaxf(t.z*sc[c0+2] + so[c0+2], 0.f) * m;
        t.w = fmaxf(t.w*sc[c0+3] + so[c0+3], 0.f) * m;
        *reinterpret_cast<float4*>(&v[e]) = t;
        lm = fmaxf(fmaxf(t.x, t.y), fmaxf(t.z, t.w));
    }
    __shared__ float sh[256];
    sh[threadIdx.x] = lm; __syncthreads();
    for (int o = 128; o > 0; o >>= 1) { if (threadIdx.x < o) sh[threadIdx.x] = fmaxf(sh[threadIdx.x], sh[threadIdx.x+o]); __syncthreads(); }
    if (threadIdx.x == 0) atomicMax((unsigned*)maxP, __float_as_uint(sh[0]));
}

// fused BN + pool -> bf16 hi/lo (layer 2)
template<int CSH>
__global__ void k_poolbn(const float* __restrict__ in, const float* __restrict__ mfin,
                         const float* __restrict__ sumP, const float* __restrict__ sqP,
                         const float* __restrict__ nP,
                         const float* __restrict__ gamma, const float* __restrict__ beta,
                         __nv_bfloat16* __restrict__ oh, __nv_bfloat16* __restrict__ ol,
                         float* __restrict__ mfout,
                         int Hi, int Wi, int Ho, int Wo, float* cntP) {
    constexpr int C = 1 << CSH;
    __shared__ float sc[C], so[C];
    if (threadIdx.x < C) {
        float n = fmaxf(nP[0], 1.f);
        float mean = sumP[threadIdx.x] / n;
        float var  = sqP[threadIdx.x] / n - mean*mean;
        float rs   = rsqrtf(var + EPS) * gamma[threadIdx.x];
        sc[threadIdx.x] = rs;
        so[threadIdx.x] = beta[threadIdx.x] - mean * rs;
    }
    __syncthreads();
    int e = blockIdx.x * blockDim.x + threadIdx.x;
    int total = B_ * Ho * Wo * C;
    int newact = 0;
    if (e < total) {
        int c = e & (C-1);
        int s = e >> CSH;
        int b = s / (Ho*Wo); int r = s - b*(Ho*Wo);
        int y = r / Wo;      int xo = r - y*Wo;
        float best = -1e30f, mm = 0.f;
        float fc = sc[c], fo = so[c];
        #pragma unroll
        for (int dy = 0; dy < 3; dy++)
            #pragma unroll
            for (int dx = 0; dx < 3; dx++) {
                int si = (b*Hi + 2*y + dy) * Wi + 2*xo + dx;
                float m = mfin[si];
                mm = fmaxf(mm, m);
                float vv = -1e30f;
                if (m > 0.f) vv = fmaxf(in[(size_t)si * C + c] * fc + fo, 0.f);
                best = fmaxf(best, vv);
            }
        float v = (mm > 0.f) ? best : 0.f;
        __nv_bfloat16 h = __float2bfloat16(v);
        oh[e] = h;
        ol[e] = __float2bfloat16(v - __bfloat162float(h));
        if (c == 0) { mfout[s] = mm; newact = (mm > 0.f); }
    }
    if (cntP) {
        __shared__ int sh[256];
        sh[threadIdx.x] = newact; __syncthreads();
        for (int o = 128; o > 0; o >>= 1) { if (threadIdx.x < o) sh[threadIdx.x] += sh[threadIdx.x+o]; __syncthreads(); }
        if (threadIdx.x == 0 && sh[0]) atomicAdd(cntP, (float)sh[0]);
    }
}

// fused BN + pool -> fp32 + tensor max (layer 4)
template<int CSH>
__global__ void k_poolbnQ(const float* __restrict__ in, const float* __restrict__ mfin,
                          const float* __restrict__ sumP, const float* __restrict__ sqP,
                          const float* __restrict__ nP,
                          const float* __restrict__ gamma, const float* __restrict__ beta,
                          float* __restrict__ outv, float* __restrict__ mfout,
                          int Hi, int Wi, int Ho, int Wo, float* __restrict__ maxP) {
    constexpr int C = 1 << CSH;
    __shared__ float sc[C], so[C];
    if (threadIdx.x < C) {
        float n = fmaxf(nP[0], 1.f);
        float mean = sumP[threadIdx.x] / n;
        float var  = sqP[threadIdx.x] / n - mean*mean;
        float rs   = rsqrtf(var + EPS) * gamma[threadIdx.x];
        sc[threadIdx.x] = rs;
        so[threadIdx.x] = beta[threadIdx.x] - mean * rs;
    }
    __syncthreads();
    int e = blockIdx.x * blockDim.x + threadIdx.x;
    int total = B_ * Ho * Wo * C;
    float lm = 0.f;
    if (e < total) {
        int c = e & (C-1);
        int s = e >> CSH;
        int b = s / (Ho*Wo); int r = s - b*(Ho*Wo);
        int y = r / Wo;      int xo = r - y*Wo;
        float best = -1e30f, mm = 0.f;
        float fc = sc[c], fo = so[c];
        #pragma unroll
        for (int dy = 0; dy < 3; dy++)
            #pragma unroll
            for (int dx = 0; dx < 3; dx++) {
                int si = (b*Hi + 2*y + dy) * Wi + 2*xo + dx;
                float m = mfin[si];
                mm = fmaxf(mm, m);
                float vv = -1e30f;
                if (m > 0.f) vv = fmaxf(in[(size_t)si * C + c] * fc + fo, 0.f);
                best = fmaxf(best, vv);
            }
        float v = (mm > 0.f) ? best : 0.f;
        outv[e] = v;
        lm = v;
        if (c == 0) mfout[s] = mm;
    }
    __shared__ float sh[256];
    sh[threadIdx.x] = lm; __syncthreads();
    for (int o = 128; o > 0; o >>= 1) { if (threadIdx.x < o) sh[threadIdx.x] = fmaxf(sh[threadIdx.x], sh[threadIdx.x+o]); __syncthreads(); }
    if (threadIdx.x == 0) atomicMax((unsigned*)maxP, __float_as_uint(sh[0]));
}

// LSTM -> fp32 flat + max|.|
__global__ void k_lstmQ(const float* __restrict__ gates, const float* __restrict__ m3,
                        float* __restrict__ flat, float* __restrict__ maxP) {
    int e = blockIdx.x * blockDim.x + threadIdx.x;
    float lm = 0.f;
    if (e < S3 * 256) {
        int c = e & 255;
        int s = e >> 8;
        const float* g = gates + (size_t)s * 768;
        float gi = g[c], go = g[256 + c], gg = g[512 + c];
        float si = 1.f / (1.f + __expf(-gi));
        float so = 1.f / (1.f + __expf(-go));
        float cc = si * tanhf(gg);
        float hh = so * tanhf(cc) * m3[s];
        int b = s / (H3_*W3_); int r = s - b*(H3_*W3_);
        flat[b*8960 + c*35 + r] = hh;
        lm = fabsf(hh);
    }
    __shared__ float sh[256];
    sh[threadIdx.x] = lm; __syncthreads();
    for (int o = 128; o > 0; o >>= 1) { if (threadIdx.x < o) sh[threadIdx.x] = fmaxf(sh[threadIdx.x], sh[threadIdx.x+o]); __syncthreads(); }
    if (threadIdx.x == 0) atomicMax((unsigned*)maxP, __float_as_uint(sh[0]));
}

// fp32 -> int8 2-digit quantize (vector 4)
__global__ void k_actq(const float* __restrict__ src, const float* __restrict__ maxP,
                       int8_t* __restrict__ d0, int8_t* __restrict__ d1, int total) {
    int i = (blockIdx.x * blockDim.x + threadIdx.x) * 4;
    if (i >= total) return;
    float Q = 127.f / fmaxf(*maxP, 1e-20f);
    float4 v = *reinterpret_cast<const float4*>(&src[i]);
    int a0 = __float2int_rn(v.x*Q), a1 = __float2int_rn(v.y*Q);
    int a2 = __float2int_rn(v.z*Q), a3 = __float2int_rn(v.w*Q);
    int b0 = __float2int_rn(128.f*(v.x*Q - (float)a0));
    int b1 = __float2int_rn(128.f*(v.y*Q - (float)a1));
    int b2 = __float2int_rn(128.f*(v.z*Q - (float)a2));
    int b3 = __float2int_rn(128.f*(v.w*Q - (float)a3));
    *reinterpret_cast<char4*>(&d0[i]) = make_char4((char)a0, (char)a1, (char)a2, (char)a3);
    *reinterpret_cast<char4*>(&d1[i]) = make_char4((char)b0, (char)b1, (char)b2, (char)b3);
}

// ---------------- param blocks ----------------
struct GemmP {
    const float* A; const float* Bw; const float* bias; float* C;
    int M, N, K, ldb;
    const float* img;
    const float* mf; float* sumP; float* sqP;
};
struct GemmB {
    const __nv_bfloat16 *Ah, *Al;
    const __nv_bfloat16 *Bh, *Bl;
    const float* bias; float* C;
    int M, N, K;
    const float* mf; float* sumP; float* sqP;
    __nv_bfloat16 *oh, *ol;
};
struct GemmQ {
    const int8_t *Ad0, *Ad1;
    const int8_t *Bd0, *Bd1;
    const float* bias; float* C;
    int M, N, K;
    const float* mf; float* sumP; float* sqP;
    __nv_bfloat16 *oh, *ol;
    const float *pmaxA, *pmaxB;
};

// ---------------- HMMA bf16x3 GEMM, TN in {32,64} (conv2, conv3, FC2) ----------------
template<int TN, int MODE, int EPI, int STAT, int IH, int IW, int IC>
__global__ void __launch_bounds__(256) k_hm2(GemmB p) {
    constexpr int TM = 128, BK = 64;
    constexpr int IM = (TN == 64) ? 2 : 1;
    constexpr int LIC = ilog2c(IC);
    constexpr int LTN = ilog2c(TN);
    constexpr int A_BYTES = TM * 128;
    constexpr int B_BYTES = TN * 128;
    constexpr int BUF = 2*A_BYTES + 2*B_BYTES;
    constexpr int BCH = TN * 8 / 256;
    constexpr int CST = TN + 1;

    extern __shared__ char sm[];
    const int tid = threadIdx.x;
    const int wid = tid >> 5, lid = tid & 31;
    const int wm = (TN == 64) ? (wid >> 1) : wid;
    const int wn = (TN == 64) ? (wid & 1) : 0;
    const int m0 = blockIdx.y * TM;
    const int n0 = blockIdx.x * TN;
    const uint32_t sbuf = smem_u32(sm);

    float acc[IM][4][4];
    #pragma unroll
    for (int i = 0; i < IM; i++)
        #pragma unroll
        for (int j = 0; j < 4; j++)
            #pragma unroll
            for (int q = 0; q < 4; q++) acc[i][j][q] = 0.f;

    const int row = tid >> 1;
    const int kt  = (tid & 1) * 32;
    int sbm = 0, sy = 0, sx = 0;
    if (MODE == 1) {
        int m = m0 + row;
        int b = m / (IH*IW);
        int r = m - b*(IH*IW);
        sy = r / IW;
        sx = r - sy*IW;
        sbm = b*IH*IW;
    }

    uint2 ahr[8], alr[8];
    uint4 bhr[BCH], blr[BCH];

    auto load_tile = [&](int k0) {
        #pragma unroll
        for (int j = 0; j < 8; j++) {
            int k = k0 + kt + j*4;
            uint2 vh = make_uint2(0u, 0u), vl = vh;
            if (k < p.K) {
                size_t idx;
                bool ok = true;
                if (MODE == 0) {
                    idx = (size_t)(m0 + row) * p.K + k;
                } else {
                    int t9 = k >> LIC;
                    int c0 = k & (IC-1);
                    int ky = t9 / 3, kx = t9 - 3*ky;
                    int yy = sy + ky - 1, xx = sx + kx - 1;
                    ok = (yy >= 0 && yy < IH && xx >= 0 && xx < IW);
                    idx = (size_t)(sbm + yy*IW + xx) * IC + c0;
                }
                if (ok) {
                    vh = *reinterpret_cast<const uint2*>(&p.Ah[idx]);
                    vl = *reinterpret_cast<const uint2*>(&p.Al[idx]);
                }
            }
            ahr[j] = vh; alr[j] = vl;
        }
        #pragma unroll
        for (int e = 0; e < BCH; e++) {
            int ge = tid + e*256;
            int n  = ge >> 3;
            int kc = ge & 7;
            int k  = k0 + kc*8;
            uint4 vh = make_uint4(0u,0u,0u,0u), vl = vh;
            if (k < p.K) {
                size_t idx = (size_t)(n0 + n) * p.K + k;
                vh = *reinterpret_cast<const uint4*>(&p.Bh[idx]);
                vl = *reinterpret_cast<const uint4*>(&p.Bl[idx]);
            }
            bhr[e] = vh; blr[e] = vl;
        }
    };

    auto store_tile = [&](int bb) {
        char* Ah = sm + bb;
        char* Al = Ah + A_BYTES;
        char* Bh = Ah + 2*A_BYTES;
        char* Bl = Bh + B_BYTES;
        #pragma unroll
        for (int j = 0; j < 8; j++) {
            uint32_t so = SWZ128((uint32_t)(row*128 + (kt + j*4)*2));
            *reinterpret_cast<uint2*>(Ah + so) = ahr[j];
            *reinterpret_cast<uint2*>(Al + so) = alr[j];
        }
        #pragma unroll
        for (int e = 0; e < BCH; e++) {
            int ge = tid + e*256;
            int n  = ge >> 3;
            int kc = ge & 7;
            uint32_t so = SWZ128((uint32_t)(n*128 + kc*16));
            *reinterpret_cast<uint4*>(Bh + so) = bhr[e];
            *reinterpret_cast<uint4*>(Bl + so) = blr[e];
        }
    };

    auto consume = [&](int bb) {
        uint32_t AH = sbuf + bb;
        uint32_t AL = AH + A_BYTES;
        uint32_t BH = AH + 2*A_BYTES;
        uint32_t BL = BH + B_BYTES;
        #pragma unroll
        for (int ks = 0; ks < 4; ks++) {
            uint32_t bh[2][4], bl[2][4];
            #pragma unroll
            for (int jp = 0; jp < 2; jp++) {
                int n_r = wn*32 + jp*16 + (lid & 7) + ((lid >> 4) << 3);
                int kb  = ks*32 + (((lid >> 3) & 1) << 4);
                uint32_t off = SWZ128((uint32_t)(n_r*128 + kb));
                LDSM_X4(bh[jp][0], bh[jp][1], bh[jp][2], bh[jp][3], BH + off);
                LDSM_X4(bl[jp][0], bl[jp][1], bl[jp][2], bl[jp][3], BL + off);
            }
            #pragma unroll
            for (int im = 0; im < IM; im++) {
                int row_a = wm*(16*IM) + im*16 + (lid & 15);
                int kb    = ks*32 + (lid >> 4) * 16;
                uint32_t off = SWZ128((uint32_t)(row_a*128 + kb));
                uint32_t ah[4], al[4];
                LDSM_X4(ah[0], ah[1], ah[2], ah[3], AH + off);
                LDSM_X4(al[0], al[1], al[2], al[3], AL + off);
                #pragma unroll
                for (int jn = 0; jn < 4; jn++) {
                    int jp = jn >> 1, s = (jn & 1) * 2;
                    MMA_BF16(acc[im][jn], ah[0], ah[1], ah[2], ah[3], bh[jp][s], bh[jp][s+1]);
                    MMA_BF16(acc[im][jn], ah[0], ah[1], ah[2], ah[3], bl[jp][s], bl[jp][s+1]);
                    MMA_BF16(acc[im][jn], al[0], al[1], al[2], al[3], bh[jp][s], bh[jp][s+1]);
                }
            }
        }
    };

    const int T = (p.K + BK - 1) / BK;
    load_tile(0);
    store_tile(0);
    __syncthreads();

    for (int t = 0; t < T; t++) {
        if (t + 1 < T) load_tile((t + 1) * BK);
        consume((t & 1) * BUF);
        if (t + 1 < T) store_tile(((t + 1) & 1) * BUF);
        __syncthreads();
    }

    float* cs   = reinterpret_cast<float*>(sm);
    float* mrow = cs + TM*CST;
    float* rs   = mrow + TM;
    float* rq   = rs + 256;
    #pragma unroll
    for (int im = 0; im < IM; im++) {
        int r0 = wm*(16*IM) + im*16 + (lid >> 2);
        #pragma unroll
        for (int jn = 0; jn < 4; jn++) {
            int c = wn*32 + jn*8 + (lid & 3)*2;
            cs[r0*CST + c]       = acc[im][jn][0];
            cs[r0*CST + c + 1]   = acc[im][jn][1];
            cs[(r0+8)*CST + c]   = acc[im][jn][2];
            cs[(r0+8)*CST + c+1] = acc[im][jn][3];
        }
    }
    if (STAT && tid < TM) mrow[tid] = p.mf[m0 + tid];
    __syncthreads();

    float lsum = 0.f, lsq = 0.f;
    for (int e = tid; e < TM*TN; e += 256) {
        int rr = e >> LTN;
        int cc = e & (TN-1);
        int n  = n0 + cc;
        float v = cs[rr*CST + cc];
        if (STAT) {
            float mk = mrow[rr];
            float xv = (mk > 0.f) ? v : 0.f;
            lsum += xv; lsq += xv*xv;
        }
        if (n < p.N) {
            if (EPI == 1 || EPI == 2 || EPI == 3) {
                int nnb = (EPI == 3 && n >= 256) ? n + 256 : n;
                v += p.bias[nnb];
                if (EPI == 2) v = fmaxf(v, 0.f);
                p.C[(size_t)(m0 + rr) * p.N + n] = v;
            } else if (EPI == 4) {
                v = fmaxf(v + p.bias[n], 0.f);
                __nv_bfloat16 h = __float2bfloat16(v);
                p.oh[(size_t)(m0 + rr) * p.N + n] = h;
                p.ol[(size_t)(m0 + rr) * p.N + n] = __float2bfloat16(v - __bfloat162float(h));
            } else {
                p.C[(size_t)(m0 + rr) * p.N + n] = v;
            }
        }
    }
    if (STAT) {
        rs[tid] = lsum; rq[tid] = lsq;
        __syncthreads();
        if (tid < TN) {
            float s = 0.f, q = 0.f;
            #pragma unroll
            for (int g = 0; g < 256/TN; g++) { s += rs[tid + g*TN]; q += rq[tid + g*TN]; }
            if (n0 + tid < p.N) {
                atomicAdd(&p.sumP[n0 + tid], s);
                atomicAdd(&p.sqP[n0 + tid], q);
            }
        }
    }
}

// ---------------- IMMA int8 2-digit GEMM, TM=128 x TN=64, BK=64 (conv4, gate, FC1) ----
// 128B smem row = [d0 64 int8 | d1 64 int8]. acc = main + cross/128, scaled by maxA*maxB/127^2.
template<int MODE, int EPI, int STAT, int IH, int IW, int IC>
__global__ void __launch_bounds__(256, 2) k_im(GemmQ p) {
    constexpr int TM = 128, TN = 64, BK = 64;
    constexpr int LIC = ilog2c(IC);
    constexpr int A_BYTES = TM * 128;          // 16KB
    constexpr int B_BYTES = TN * 128;          // 8KB
    constexpr int STAGE = A_BYTES + B_BYTES;   // 24KB
    constexpr int CST = TN + 1;

    extern __shared__ char sm[];
    const int tid = threadIdx.x;
    const int wid = tid >> 5, lid = tid & 31;
    const int wm = wid >> 1;       // 0..3
    const int wn = wid & 1;        // 0..1
    const int m0 = blockIdx.y * TM;
    const int n0 = blockIdx.x * TN;
    const uint32_t sbuf = smem_u32(sm);

    const float inv = (*p.pmaxA) * (*p.pmaxB) * (1.f/16129.f);

    int mainA[2][4][4], crossA[2][4][4];
    #pragma unroll
    for (int i = 0; i < 2; i++)
        #pragma unroll
        for (int j = 0; j < 4; j++)
            #pragma unroll
            for (int q = 0; q < 4; q++) { mainA[i][j][q] = 0; crossA[i][j][q] = 0; }

    const int row  = tid >> 1;     // 0..127
    const int half = tid & 1;      // digit select
    int sbm = 0, sy = 0, sx = 0;
    if (MODE == 1) {
        int m = m0 + row;
        int b = m / (IH*IW);
        int r = m - b*(IH*IW);
        sy = r / IW;
        sx = r - sy*IW;
        sbm = b*IH*IW;
    }

    uint4 ar[4], br[2];

    auto load_tile = [&](int k0) {
        {
            const int8_t* src = half ? p.Ad1 : p.Ad0;
            bool ok = true;
            size_t idx = 0;
            if (MODE == 0) {
                idx = (size_t)(m0 + row) * p.K + k0;
            } else {
                int t9 = k0 >> LIC;
                int c0 = k0 & (IC-1);
                int ky = t9 / 3, kx = t9 - 3*ky;
                int yy = sy + ky - 1, xx = sx + kx - 1;
                ok = (yy >= 0 && yy < IH && xx >= 0 && xx < IW);
                idx = (size_t)(sbm + yy*IW + xx) * IC + c0;
            }
            if (ok) {
                const uint4* s4 = reinterpret_cast<const uint4*>(&src[idx]);
                #pragma unroll
                for (int j = 0; j < 4; j++) ar[j] = s4[j];
            } else {
                #pragma unroll
                for (int j = 0; j < 4; j++) ar[j] = make_uint4(0u,0u,0u,0u);
            }
        }
        #pragma unroll
        for (int e = 0; e < 2; e++) {
            int ge = tid + e*256;
            int n   = ge >> 3;
            int seg = ge & 7;
            int dig = seg >> 2, quad = seg & 3;
            const int8_t* src = dig ? p.Bd1 : p.Bd0;
            br[e] = *reinterpret_cast<const uint4*>(&src[(size_t)(n0 + n) * p.K + k0 + quad*16]);
        }
    };

    auto store_tile = [&](int bb) {
        char* Ab = sm + bb;
        char* Bb = Ab + A_BYTES;
        #pragma unroll
        for (int j = 0; j < 4; j++)
            *reinterpret_cast<uint4*>(Ab + SWZ128((uint32_t)(row*128 + half*64 + j*16))) = ar[j];
        #pragma unroll
        for (int e = 0; e < 2; e++) {
            int ge = tid + e*256;
            int n   = ge >> 3;
            int seg = ge & 7;
            *reinterpret_cast<uint4*>(Bb + SWZ128((uint32_t)(n*128 + seg*16))) = br[e];
        }
    };

    auto consume = [&](int bb) {
        uint32_t Ab = sbuf + bb;
        uint32_t Bb = Ab + A_BYTES;
        #pragma unroll
        for (int ks = 0; ks < 2; ks++) {
            uint32_t b0[2][4], b1[2][4];
            #pragma unroll
            for (int jp = 0; jp < 2; jp++) {
                int n_r = wn*32 + jp*16 + (lid & 7) + ((lid >> 4) << 3);
                int kb  = ks*32 + (((lid >> 3) & 1) << 4);
                LDSM_X4(b0[jp][0], b0[jp][1], b0[jp][2], b0[jp][3],
                        Bb + SWZ128((uint32_t)(n_r*128 + kb)));
                LDSM_X4(b1[jp][0], b1[jp][1], b1[jp][2], b1[jp][3],
                        Bb + SWZ128((uint32_t)(n_r*128 + 64 + kb)));
            }
            #pragma unroll
            for (int im = 0; im < 2; im++) {
                int row_a = wm*32 + im*16 + (lid & 15);
                int kb    = ks*32 + ((lid >> 4) << 4);
                uint32_t a0[4], a1[4];
                LDSM_X4(a0[0], a0[1], a0[2], a0[3],
                        Ab + SWZ128((uint32_t)(row_a*128 + kb)));
                LDSM_X4(a1[0], a1[1], a1[2], a1[3],
                        Ab + SWZ128((uint32_t)(row_a*128 + 64 + kb)));
                #pragma unroll
                for (int jn = 0; jn < 4; jn++) {
                    int jp = jn >> 1, s = (jn & 1) * 2;
                    MMA_S8(mainA[im][jn],  a0[0], a0[1], a0[2], a0[3], b0[jp][s], b0[jp][s+1]);
                    MMA_S8(crossA[im][jn], a0[0], a0[1], a0[2], a0[3], b1[jp][s], b1[jp][s+1]);
                    MMA_S8(crossA[im][jn], a1[0], a1[1], a1[2], a1[3], b0[jp][s], b0[jp][s+1]);
                }
            }
        }
    };

    const int T = p.K / BK;    // K % 64 == 0 at all call sites
    load_tile(0);
    store_tile(0);
    __syncthreads();

    for (int t = 0; t < T; t++) {
        if (t + 1 < T) load_tile((t + 1) * BK);
        consume((t & 1) * STAGE);
        if (t + 1 < T) store_tile(((t + 1) & 1) * STAGE);
        __syncthreads();
    }

    // epilogue
    float* cs   = reinterpret_cast<float*>(sm);
    float* mrow = cs + TM*CST;
    float* rs   = mrow + TM;
    float* rq   = rs + 256;
    #pragma unroll
    for (int im = 0; im < 2; im++) {
        int r0 = wm*32 + im*16 + (lid >> 2);
        #pragma unroll
        for (int jn = 0; jn < 4; jn++) {
            int c = wn*32 + jn*8 + (lid & 3)*2;
            #pragma unroll
            for (int q = 0; q < 4; q++) {
                float v = ((float)mainA[im][jn][q] + (float)crossA[im][jn][q] * 0.0078125f) * inv;
                int rrow = (q < 2) ? r0 : r0 + 8;
                int ccol = c + (q & 1);
                cs[rrow*CST + ccol] = v;
            }
        }
    }
    if (STAT && tid < TM) mrow[tid] = p.mf[m0 + tid];
    __syncthreads();

    float lsum = 0.f, lsq = 0.f;
    for (int e = tid; e < TM*TN; e += 256) {
        int rr = e >> 6;
        int cc = e & 63;
        int n  = n0 + cc;
        float v = cs[rr*CST + cc];
        if (STAT) {
            float mk = mrow[rr];
            float xv = (mk > 0.f) ? v : 0.f;
            lsum += xv; lsq += xv*xv;
        }
        if (n < p.N) {
            if (EPI == 3) {
                int nnb = (n >= 256) ? n + 256 : n;
                p.C[(size_t)(m0 + rr) * p.N + n] = v + p.bias[nnb];
            } else if (EPI == 4) {
                v = fmaxf(v + p.bias[n], 0.f);
                __nv_bfloat16 h = __float2bfloat16(v);
                p.oh[(size_t)(m0 + rr) * p.N + n] = h;
                p.ol[(size_t)(m0 + rr) * p.N + n] = __float2bfloat16(v - __bfloat162float(h));
            } else {
                p.C[(size_t)(m0 + rr) * p.N + n] = v;
            }
        }
    }
    if (STAT) {
        rs[tid] = lsum; rq[tid] = lsq;
        __syncthreads();
        if (tid < TN) {
            float s = 0.f, q = 0.f;
            #pragma unroll
            for (int g = 0; g < 4; g++) { s += rs[tid + g*TN]; q += rq[tid + g*TN]; }
            if (n0 + tid < p.N) {
                atomicAdd(&p.sumP[n0 + tid], s);
                atomicAdd(&p.sqP[n0 + tid], q);
            }
        }
    }
}

// ---------------- packed-f32x2 GEMM (conv1 only), fused stats ----------------
template<int TN, int MODE, int EPI, int STAT, int IH, int IW, int IC>
__global__ void __launch_bounds__(256) k_gemm3(GemmP p) {
    constexpr int TM = 128, BK = 16;
    constexpr int TX = (TN == 32) ? 8 : 16;
    constexpr int NR = TN / TX;
    constexpr int TY = 256 / TX;
    constexpr int MR = TM / TY;
    constexpr int MP = MR / 2;
    constexpr int LIC = ilog2c(IC);
    constexpr int LTN = ilog2c(TN);
    constexpr int B_EPT = (BK * TN) / 256;

    __shared__ float  As[2][BK][TM];
    __shared__ float2 Bs[2][BK][TN];
    __shared__ float mrow[TM];
    __shared__ float sred[TN], qred[TN];

    const int tid = threadIdx.x;
    const int tx = tid % TX, ty = tid / TX;
    const int m0 = blockIdx.y * TM;
    const int n0 = blockIdx.x * TN;

    unsigned long long acc[MP][NR];
    #pragma unroll
    for (int i = 0; i < MP; i++)
        #pragma unroll
        for (int j = 0; j < NR; j++) acc[i][j] = 0ULL;

    int pm_b[2], pm_y[2], pm_x[2];
    if (MODE == 1) {
        #pragma unroll
        for (int i = 0; i < 2; i++) {
            int m = m0 + ((tid + i*256) >> 2);
            int b = m / (IH*IW);
            int r = m - b*(IH*IW);
            int y = r / IW;
            pm_b[i] = b*IH*IW;
            pm_y[i] = y;
            pm_x[i] = r - y*IW;
        }
    }

    float a_reg[8];
    float b_reg[B_EPT];

    auto load_tile = [&](int k0) {
        if (MODE == 1) {
            #pragma unroll
            for (int i = 0; i < 2; i++) {
                int gq = tid + i*256;
                int kbase = k0 + (gq & 3)*4;
                #pragma unroll
                for (int j = 0; j < 4; j++) {
                    int k = kbase + j;
                    float v = 0.f;
                    if (k < p.K) {
                        int c  = k & (IC-1);
                        int t9 = k >> LIC;
                        int ky = t9 / 3, kx = t9 - 3*ky;
                        int yy = pm_y[i] + ky - 1, xx = pm_x[i] + kx - 1;
                        if (yy >= 0 && yy < IH && xx >= 0 && xx < IW)
                            v = p.img[(size_t)(pm_b[i] + yy*IW + xx) * IC + c];
                    }
                    a_reg[i*4+j] = v;
                }
            }
        } else {
            #pragma unroll
            for (int i = 0; i < 2; i++) {
                int gq = tid + i*256;
                int m = m0 + (gq >> 2);
                int k = k0 + (gq & 3) * 4;
                float4 t = *reinterpret_cast<const float4*>(&p.A[(size_t)m * p.K + k]);
                a_reg[i*4+0] = t.x; a_reg[i*4+1] = t.y;
                a_reg[i*4+2] = t.z; a_reg[i*4+3] = t.w;
            }
        }
        #pragma unroll
        for (int e = 0; e < B_EPT; e++) {
            int ge = tid + e*256;
            int kl = ge >> LTN;
            int n  = ge & (TN-1);
            int k  = k0 + kl;
            int nn = n0 + n;
            float v = 0.f;
            if (k < p.K && nn < p.N) v = p.Bw[(size_t)k * p.ldb + nn];
            b_reg[e] = v;
        }
    };

    auto store_tile = [&](int buf) {
        #pragma unroll
        for (int i = 0; i < 2; i++) {
            int gq = tid + i*256;
            int ml = gq >> 2;
            int kq = (gq & 3) * 4;
            #pragma unroll
            for (int j = 0; j < 4; j++) As[buf][kq+j][ml] = a_reg[i*4+j];
        }
        #pragma unroll
        for (int e = 0; e < B_EPT; e++) {
            int ge = tid + e*256;
            int kl = ge >> LTN;
            int n  = ge & (TN-1);
            Bs[buf][kl][n] = make_float2(b_reg[e], b_reg[e]);
        }
    };

    const int nTiles = (p.K + BK - 1) / BK;
    load_tile(0);
    store_tile(0);
    __syncthreads();

    for (int t = 0; t < nTiles; t++) {
        int cur = t & 1;
        if (t + 1 < nTiles) load_tile((t + 1) * BK);
        #pragma unroll
        for (int kk = 0; kk < BK; kk++) {
            unsigned long long af[MP], bf[NR];
            const ulonglong2* ap = reinterpret_cast<const ulonglong2*>(&As[cur][kk][ty*MR]);
            #pragma unroll
            for (int i = 0; i < MP/2; i++) { ulonglong2 v = ap[i]; af[2*i] = v.x; af[2*i+1] = v.y; }
            const unsigned long long* bp = reinterpret_cast<const unsigned long long*>(&Bs[cur][kk][0]);
            #pragma unroll
            for (int nr = 0; nr < NR; nr++) bf[nr] = bp[tx + nr*TX];
            #pragma unroll
            for (int mp = 0; mp < MP; mp++)
                #pragma unroll
                for (int nr = 0; nr < NR; nr++)
                    FMA2(acc[mp][nr], af[mp], bf[nr]);
        }
        if (t + 1 < nTiles) store_tile(cur ^ 1);
        __syncthreads();
    }

    if (STAT) {
        if (tid < TN) { sred[tid] = 0.f; qred[tid] = 0.f; }
        if (tid < TM) mrow[tid] = p.mf[m0 + tid];
        __syncthreads();
    }

    #pragma unroll
    for (int mp = 0; mp < MP; mp++) {
        int m = m0 + ty*MR + 2*mp;
        #pragma unroll
        for (int nr = 0; nr < NR; nr++) {
            int n = n0 + tx + nr*TX;
            if (n >= p.N) continue;
            float lo = __uint_as_float((unsigned)(acc[mp][nr] & 0xFFFFFFFFULL));
            float hi = __uint_as_float((unsigned)(acc[mp][nr] >> 32));
            if (STAT) {
                float mk0 = mrow[ty*MR + 2*mp], mk1 = mrow[ty*MR + 2*mp + 1];
                float x0 = (mk0 > 0.f) ? lo : 0.f;
                float x1 = (mk1 > 0.f) ? hi : 0.f;
                atomicAdd(&sred[n - n0], x0 + x1);
                atomicAdd(&qred[n - n0], x0*x0 + x1*x1);
            }
            if (EPI >= 1) { float bb = p.bias[n]; lo += bb; hi += bb; }
            if (EPI == 2) { lo = fmaxf(lo, 0.f); hi = fmaxf(hi, 0.f); }
            p.C[(size_t)m       * p.N + n] = lo;
            p.C[(size_t)(m + 1) * p.N + n] = hi;
        }
    }
    if (STAT) {
        __syncthreads();
        if (tid < TN && n0 + tid < p.N) {
            atomicAdd(&p.sumP[n0 + tid], sred[tid]);
            atomicAdd(&p.sqP[n0 + tid], qred[tid]);
        }
    }
}

// ---------------- launcher ----------------
static inline int ceil_div(int a, int b) { return (a + b - 1) / b; }
#define HM_SMEM64 (2 * (2*128*128 + 2*64*128))   // 96 KB
#define HM_SMEM32 (2 * (2*128*128 + 2*32*128))   // 80 KB
#define IM_SMEM   (2 * (128*128 + 64*128))       // 48 KB

extern "C" void kernel_launch(void* const* d_in, const int* in_sizes, int n_in,
                              void* d_out, int out_size) {
    const float* x    = (const float*)d_in[0];
    const int*   mask = (const int*)  d_in[1];
    const float* W1 = (const float*)d_in[2];  const float* ga1 = (const float*)d_in[3];  const float* be1 = (const float*)d_in[4];
    const float* W2 = (const float*)d_in[5];  const float* ga2 = (const float*)d_in[6];  const float* be2 = (const float*)d_in[7];
    const float* W3 = (const float*)d_in[8];  const float* ga3 = (const float*)d_in[9];  const float* be3 = (const float*)d_in[10];
    const float* W4 = (const float*)d_in[11]; const float* ga4 = (const float*)d_in[12]; const float* be4 = (const float*)d_in[13];
    const float* Wl = (const float*)d_in[14]; const float* bl  = (const float*)d_in[15];
    const float* lw1 = (const float*)d_in[16]; const float* lb1 = (const float*)d_in[17];
    const float* lw2 = (const float*)d_in[18]; const float* lb2 = (const float*)d_in[19];
    float* out = (float*)d_out;

    float *xm, *m1, *h1, *h2, *m2, *h3, *h4, *p2f, *m3, *gates, *flatf, *st;
    __nv_bfloat16 *h1h, *h1l, *p1h, *p1l, *y1h, *y1l;
    __nv_bfloat16 *w2h, *w2l, *w3h, *w3l, *l2h, *l2l;
    int8_t *h3q0, *h3q1, *p2q0, *p2q1, *fq0, *fq1;
    int8_t *w4q0, *w4q1, *wlq0, *wlq1, *l1q0, *l1q1;
    cudaGetSymbolAddress((void**)&xm,   g_xm);    cudaGetSymbolAddress((void**)&m1,   g_m1);
    cudaGetSymbolAddress((void**)&h1,   g_h1);    cudaGetSymbolAddress((void**)&h2,   g_h2);
    cudaGetSymbolAddress((void**)&m2,   g_m2);    cudaGetSymbolAddress((void**)&h3,   g_h3);
    cudaGetSymbolAddress((void**)&h4,   g_h4);    cudaGetSymbolAddress((void**)&p2f,  g_p2f);
    cudaGetSymbolAddress((void**)&m3,   g_m3);    cudaGetSymbolAddress((void**)&gates, g_gates);
    cudaGetSymbolAddress((void**)&flatf, g_flatf);cudaGetSymbolAddress((void**)&st,   g_stats);
    cudaGetSymbolAddress((void**)&h1h,  g_h1h);   cudaGetSymbolAddress((void**)&h1l,  g_h1l);
    cudaGetSymbolAddress((void**)&p1h,  g_p1h);   cudaGetSymbolAddress((void**)&p1l,  g_p1l);
    cudaGetSymbolAddress((void**)&y1h,  g_y1h);   cudaGetSymbolAddress((void**)&y1l,  g_y1l);
    cudaGetSymbolAddress((void**)&w2h,  g_w2h);   cudaGetSymbolAddress((void**)&w2l,  g_w2l);
    cudaGetSymbolAddress((void**)&w3h,  g_w3h);   cudaGetSymbolAddress((void**)&w3l,  g_w3l);
    cudaGetSymbolAddress((void**)&l2h,  g_l2h);   cudaGetSymbolAddress((void**)&l2l,  g_l2l);
    cudaGetSymbolAddress((void**)&h3q0, g_h3q0);  cudaGetSymbolAddress((void**)&h3q1, g_h3q1);
    cudaGetSymbolAddress((void**)&p2q0, g_p2q0);  cudaGetSymbolAddress((void**)&p2q1, g_p2q1);
    cudaGetSymbolAddress((void**)&fq0,  g_fq0);   cudaGetSymbolAddress((void**)&fq1,  g_fq1);
    cudaGetSymbolAddress((void**)&w4q0, g_w4q0);  cudaGetSymbolAddress((void**)&w4q1, g_w4q1);
    cudaGetSymbolAddress((void**)&wlq0, g_wlq0);  cudaGetSymbolAddress((void**)&wlq1, g_wlq1);
    cudaGetSymbolAddress((void**)&l1q0, g_l1q0);  cudaGetSymbolAddress((void**)&l1q1, g_l1q1);

    float *sum1 = st+0,   *sq1 = st+16;
    float *sum2 = st+32,  *sq2 = st+64;
    float *sum3 = st+128, *sq3 = st+192;
    float *sum4 = st+256, *sq4 = st+384;
    float *n1 = st+512, *n2 = st+513;
    float *mxW4 = st+544, *mxWl = st+545, *mxL1 = st+546;
    float *mxH3 = st+547, *mxP2 = st+548, *mxFL = st+549;

    cudaFuncSetAttribute(k_hm2<32,1,0,1,H1_,W1_,16>, cudaFuncAttributeMaxDynamicSharedMemorySize, HM_SMEM32);
    cudaFuncSetAttribute(k_hm2<64,1,0,1,H2_,W2_,32>, cudaFuncAttributeMaxDynamicSharedMemorySize, HM_SMEM64);
    cudaFuncSetAttribute(k_hm2<64,0,1,0,1,1,16>,     cudaFuncAttributeMaxDynamicSharedMemorySize, HM_SMEM64);

    k_zero_stats<<<1, 1024>>>(st);

    // weight maxima, then quantize/transpose (int8); bf16 transposes for the rest
    k_wmax<<<64, 256>>>(W4,  576*128,  mxW4);
    k_wmax<<<64, 256>>>(Wl,  1152*1024, mxWl);   // superset incl. f-gate cols: safe upper bound
    k_wmax<<<128, 256>>>(lw1, 8960*1024, mxL1);
    { dim3 b(32,32);
      k_wq<0><<<dim3(ceil_div(576,32),  4),  b>>>(W4,  w4q0, w4q1, 576,  128,  128,  mxW4);
      k_wq<1><<<dim3(ceil_div(1152,32), 24), b>>>(Wl,  wlq0, wlq1, 1152, 768,  1024, mxWl);
      k_wq<0><<<dim3(ceil_div(8960,32), 32), b>>>(lw1, l1q0, l1q1, 8960, 1024, 1024, mxL1);
      k_wt<0><<<dim3(ceil_div(144,32),  1),  b>>>(W2,  w2h, w2l, 144,  32,   32);
      k_wt<0><<<dim3(ceil_div(288,32),  2),  b>>>(W3,  w3h, w3l, 288,  64,   64);
      k_wt<0><<<dim3(ceil_div(1024,32), 14), b>>>(lw2, l2h, l2l, 1024, 420,  420);
    }

    k_prep<<<ceil_div(S1, 256), 256>>>(x, mask, xm, m1, n1);

    // conv1: 2->16 (K=18) — FFMA2 + fused stats
    { GemmP p = { nullptr, W1, nullptr, h1, S1, 16, 18, 16, xm, m1, sum1, sq1 };
      k_gemm3<32,1,0,1,H1_,W1_,2><<<dim3(1, S1/128), 256>>>(p); }
    k_apply3<4><<<ceil_div(S1*16/4, 256), 256>>>(h1, m1, S1, sum1, sq1, n1, ga1, be1, h1h, h1l);

    // conv2: 16->32 (K=144) — HMMA TN=32 + fused stats
    { GemmB p = { h1h, h1l, w2h, w2l, nullptr, h2, S1, 32, 144, m1, sum2, sq2, nullptr, nullptr };
      k_hm2<32,1,0,1,H1_,W1_,16><<<dim3(1, S1/128), 256, HM_SMEM32>>>(p); }

    // pool1 + BN2 -> bf16, count n2
    k_poolbn<5><<<ceil_div(S2*32, 256), 256>>>(h2, m1, sum2, sq2, n1, ga2, be2,
                                               p1h, p1l, m2, H1_, W1_, H2_, W2_, n2);

    // conv3: 32->64 (K=288) — HMMA TN=64 + fused stats
    { GemmB p = { p1h, p1l, w3h, w3l, nullptr, h3, S2, 64, 288, m2, sum3, sq3, nullptr, nullptr };
      k_hm2<64,1,0,1,H2_,W2_,32><<<dim3(1, S2/128), 256, HM_SMEM64>>>(p); }
    // BN3 in-place fp32 + max, then quantize
    k_apply3Q<6><<<ceil_div(S2*64/4, 256), 256>>>(h3, m2, S2, sum3, sq3, n2, ga3, be3, mxH3);
    k_actq<<<ceil_div(S2*64/4, 256), 256>>>(h3, mxH3, h3q0, h3q1, S2*64);

    // conv4: 64->128 (K=576) — IMMA + fused stats
    { GemmQ p = { h3q0, h3q1, w4q0, w4q1, nullptr, h4, S2, 128, 576, m2, sum4, sq4,
                  nullptr, nullptr, mxH3, mxW4 };
      k_im<1,0,1,H2_,W2_,64><<<dim3(2, S2/128), 256, IM_SMEM>>>(p); }

    // pool2 + BN4 -> fp32 + max, then quantize
    k_poolbnQ<7><<<ceil_div(S3*128, 256), 256>>>(h4, m2, sum4, sq4, n2, ga4, be4,
                                                 p2f, m3, H2_, W2_, H3_, W3_, mxP2);
    k_actq<<<ceil_div(S3*128/4, 256), 256>>>(p2f, mxP2, p2q0, p2q1, S3*128);

    // gate conv: 128->768 (f skipped; remap in k_wq) + bias (K=1152) — IMMA
    { GemmQ p = { p2q0, p2q1, wlq0, wlq1, bl, gates, S3, 768, 1152, nullptr, nullptr, nullptr,
                  nullptr, nullptr, mxP2, mxWl };
      k_im<1,3,0,H3_,W3_,128><<<dim3(12, S3/128), 256, IM_SMEM>>>(p); }

    // LSTM -> fp32 flat + max, then quantize
    k_lstmQ<<<ceil_div(S3*256, 256), 256>>>(gates, m3, flatf, mxFL);
    k_actq<<<ceil_div(B_*8960/4, 256), 256>>>(flatf, mxFL, fq0, fq1, B_*8960);

    // FC1: [2048,8960]x[8960,1024] + bias, relu -> bf16 hi/lo — IMMA
    { GemmQ p = { fq0, fq1, l1q0, l1q1, lb1, nullptr, B_, 1024, 8960, nullptr, nullptr, nullptr,
                  y1h, y1l, mxFL, mxL1 };
      k_im<0,4,0,1,1,32><<<dim3(16, B_/128), 256, IM_SMEM>>>(p); }

    // FC2: [2048,1024]x[1024,420] + bias -> out — HMMA TN=64
    { GemmB p = { y1h, y1l, l2h, l2l, lb2, out, B_, 420, 1024, nullptr, nullptr, nullptr, nullptr, nullptr };
      k_hm2<64,0,1,0,1,1,16><<<dim3(7, B_/128), 256, HM_SMEM64>>>(p); }
}

// round 14
// speedup vs baseline: 1.4422x; 1.4422x over previous
#include <cuda_runtime.h>
#include <cuda_bf16.h>
#include <math.h>
#include <stdint.h>

#define EPS 1e-4f

#define B_  2048
#define H1_ 23
#define W1_ 31
#define H2_ 11
#define W2_ 15
#define H3_ 5
#define W3_ 7

#define S1 (B_*H1_*W1_)
#define S2 (B_*H2_*W2_)
#define S3 (B_*H3_*W3_)

// ---------------- scratch ----------------
__device__ __align__(16) float g_xm[S1*2];
__device__ __align__(16) float g_m1[S1];
__device__ __align__(16) float g_h1[S1*16];
__device__ __align__(16) __nv_bfloat16 g_h1h[S1*16];
__device__ __align__(16) __nv_bfloat16 g_h1l[S1*16];
__device__ __align__(16) float g_h2[S1*32];
__device__ __align__(16) __nv_bfloat16 g_p1h[S2*32];
__device__ __align__(16) __nv_bfloat16 g_p1l[S2*32];
__device__ __align__(16) float g_m2[S2];
__device__ __align__(16) float g_h3[S2*64];
__device__ __align__(16) __nv_bfloat16 g_h3h[S2*64];
__device__ __align__(16) __nv_bfloat16 g_h3l[S2*64];
__device__ __align__(16) float g_h4[S2*128];
__device__ __align__(16) __nv_bfloat16 g_p2h[S3*128];
__device__ __align__(16) __nv_bfloat16 g_p2l[S3*128];
__device__ __align__(16) float g_m3[S3];
__device__ __align__(16) float g_gates[S3*768];
__device__ __align__(16) __nv_bfloat16 g_flath[B_*8960];
__device__ __align__(16) __nv_bfloat16 g_flatl[B_*8960];
__device__ __align__(16) float g_y1f[2*B_*1024];
__device__ __align__(16) __nv_bfloat16 g_y1h[B_*1024];
__device__ __align__(16) __nv_bfloat16 g_y1l[B_*1024];
__device__ __align__(16) float g_stats[544];
// transposed bf16 weights [n][k]
__device__ __align__(16) __nv_bfloat16 g_w2h[32*144],   g_w2l[32*144];
__device__ __align__(16) __nv_bfloat16 g_w3h[64*288],   g_w3l[64*288];
__device__ __align__(16) __nv_bfloat16 g_w4h[128*576],  g_w4l[128*576];
__device__ __align__(16) __nv_bfloat16 g_wlh[768*1152], g_wll[768*1152];
__device__ __align__(16) __nv_bfloat16 g_l1h[1024*8960],g_l1l[1024*8960];
__device__ __align__(16) __nv_bfloat16 g_l2h[448*1024], g_l2l[448*1024];

__host__ __device__ constexpr int ilog2c(int x) { return x <= 1 ? 0 : 1 + ilog2c(x >> 1); }

#define FMA2(d, a, b) asm("fma.rn.f32x2 %0, %1, %2, %0;" : "+l"(d) : "l"(a), "l"(b))
#define SWZ128(x) ((x) ^ (((x) >> 3) & 0x70))

__device__ __forceinline__ uint32_t smem_u32(const void* p) {
    uint32_t a;
    asm("{ .reg .u64 t; cvta.to.shared.u64 t, %1; cvt.u32.u64 %0, t; }" : "=r"(a) : "l"(p));
    return a;
}

#define LDSM_X4(r0, r1, r2, r3, addr) \
    asm volatile("ldmatrix.sync.aligned.m8n8.x4.shared.b16 {%0,%1,%2,%3}, [%4];" \
        : "=r"(r0), "=r"(r1), "=r"(r2), "=r"(r3) : "r"(addr))

#define MMA_BF16(d, a0, a1, a2, a3, b0, b1) \
    asm volatile("mma.sync.aligned.m16n8k16.row.col.f32.bf16.bf16.f32 " \
        "{%0,%1,%2,%3}, {%4,%5,%6,%7}, {%8,%9}, {%0,%1,%2,%3};" \
        : "+f"((d)[0]), "+f"((d)[1]), "+f"((d)[2]), "+f"((d)[3]) \
        : "r"(a0), "r"(a1), "r"(a2), "r"(a3), "r"(b0), "r"(b1))

__device__ __forceinline__ uint32_t bpack(float a, float b) {
    __nv_bfloat162 t;
    t.x = __float2bfloat16(a);
    t.y = __float2bfloat16(b);
    return *reinterpret_cast<uint32_t*>(&t);
}
__device__ __forceinline__ float bres(float x) {
    return x - __bfloat162float(__float2bfloat16(x));
}

// ---------------- small kernels ----------------
__global__ void k_zero_stats(float* st) {
    if (threadIdx.x < 544) st[threadIdx.x] = 0.f;
}

__global__ void k_prep(const float* __restrict__ x, const int* __restrict__ mask,
                       float* __restrict__ xm, float* __restrict__ m1, float* nP) {
    int s = blockIdx.x * blockDim.x + threadIdx.x;
    int act = 0;
    if (s < S1) {
        float m = (float)mask[s];
        m1[s] = m;
        xm[2*s]   = x[2*s]   * m;
        xm[2*s+1] = x[2*s+1] * m;
        act = (m > 0.f);
    }
    __shared__ int sh[256];
    sh[threadIdx.x] = act; __syncthreads();
    for (int o = 128; o > 0; o >>= 1) { if (threadIdx.x < o) sh[threadIdx.x] += sh[threadIdx.x+o]; __syncthreads(); }
    if (threadIdx.x == 0 && sh[0]) atomicAdd(nP, (float)sh[0]);
}

template<int REMAP>
__global__ void k_wt(const float* __restrict__ W, __nv_bfloat16* __restrict__ Wh,
                     __nv_bfloat16* __restrict__ Wl, int K, int N, int ldb) {
    __shared__ float t[32][33];
    int k = blockIdx.x*32 + threadIdx.y;
    int n = blockIdx.y*32 + threadIdx.x;
    int nn = (REMAP && n >= 256) ? n + 256 : n;
    t[threadIdx.y][threadIdx.x] = (k < K && n < N) ? W[(size_t)k*ldb + nn] : 0.f;
    __syncthreads();
    int ko = blockIdx.x*32 + threadIdx.x;
    int no = blockIdx.y*32 + threadIdx.y;
    if (ko < K) {
        float v = t[threadIdx.x][threadIdx.y];
        __nv_bfloat16 h = __float2bfloat16(v);
        Wh[(size_t)no*K + ko] = h;
        Wl[(size_t)no*K + ko] = __float2bfloat16(v - __bfloat162float(h));
    }
}

template<int CSH>
__global__ void k_apply3(const float* __restrict__ v, const float* __restrict__ mf,
                         int sites,
                         const float* __restrict__ sumP, const float* __restrict__ sqP,
                         const float* __restrict__ nP,
                         const float* __restrict__ gamma, const float* __restrict__ beta,
                         __nv_bfloat16* __restrict__ oh, __nv_bfloat16* __restrict__ ol) {
    constexpr int C = 1 << CSH;
    __shared__ float sc[C], so[C];
    if (threadIdx.x < C) {
        float n = fmaxf(nP[0], 1.f);
        float mean = sumP[threadIdx.x] / n;
        float var  = sqP[threadIdx.x] / n - mean*mean;
        float rs   = rsqrtf(var + EPS) * gamma[threadIdx.x];
        sc[threadIdx.x] = rs;
        so[threadIdx.x] = beta[threadIdx.x] - mean * rs;
    }
    __syncthreads();
    int i = blockIdx.x * blockDim.x + threadIdx.x;
    int total4 = (sites << CSH) >> 2;
    if (i < total4) {
        int e = i * 4;
        int c0 = e & (C-1);
        float m = mf[e >> CSH];
        float4 t = *reinterpret_cast<const float4*>(&v[e]);
        t.x = fmaxf(t.x*sc[c0+0] + so[c0+0], 0.f) * m;
        t.y = fmaxf(t.y*sc[c0+1] + so[c0+1], 0.f) * m;
        t.z = fmaxf(t.z*sc[c0+2] + so[c0+2], 0.f) * m;
        t.w = fmaxf(t.w*sc[c0+3] + so[c0+3], 0.f) * m;
        *reinterpret_cast<uint2*>(&oh[e]) = make_uint2(bpack(t.x, t.y), bpack(t.z, t.w));
        *reinterpret_cast<uint2*>(&ol[e]) =
            make_uint2(bpack(bres(t.x), bres(t.y)), bpack(bres(t.z), bres(t.w)));
    }
}

template<int CSH>
__global__ void k_poolbn(const float* __restrict__ in, const float* __restrict__ mfin,
                         const float* __restrict__ sumP, const float* __restrict__ sqP,
                         const float* __restrict__ nP,
                         const float* __restrict__ gamma, const float* __restrict__ beta,
                         __nv_bfloat16* __restrict__ oh, __nv_bfloat16* __restrict__ ol,
                         float* __restrict__ mfout,
                         int Hi, int Wi, int Ho, int Wo, float* cntP) {
    constexpr int C = 1 << CSH;
    __shared__ float sc[C], so[C];
    if (threadIdx.x < C) {
        float n = fmaxf(nP[0], 1.f);
        float mean = sumP[threadIdx.x] / n;
        float var  = sqP[threadIdx.x] / n - mean*mean;
        float rs   = rsqrtf(var + EPS) * gamma[threadIdx.x];
        sc[threadIdx.x] = rs;
        so[threadIdx.x] = beta[threadIdx.x] - mean * rs;
    }
    __syncthreads();
    int e = blockIdx.x * blockDim.x + threadIdx.x;
    int total = B_ * Ho * Wo * C;
    int newact = 0;
    if (e < total) {
        int c = e & (C-1);
        int s = e >> CSH;
        int b = s / (Ho*Wo); int r = s - b*(Ho*Wo);
        int y = r / Wo;      int xo = r - y*Wo;
        float best = -1e30f, mm = 0.f;
        float fc = sc[c], fo = so[c];
        #pragma unroll
        for (int dy = 0; dy < 3; dy++)
            #pragma unroll
            for (int dx = 0; dx < 3; dx++) {
                int si = (b*Hi + 2*y + dy) * Wi + 2*xo + dx;
                float m = mfin[si];
                mm = fmaxf(mm, m);
                float vv = -1e30f;
                if (m > 0.f) vv = fmaxf(in[(size_t)si * C + c] * fc + fo, 0.f);
                best = fmaxf(best, vv);
            }
        float v = (mm > 0.f) ? best : 0.f;
        __nv_bfloat16 h = __float2bfloat16(v);
        oh[e] = h;
        ol[e] = __float2bfloat16(v - __bfloat162float(h));
        if (c == 0) { mfout[s] = mm; newact = (mm > 0.f); }
    }
    if (cntP) {
        __shared__ int sh[256];
        sh[threadIdx.x] = newact; __syncthreads();
        for (int o = 128; o > 0; o >>= 1) { if (threadIdx.x < o) sh[threadIdx.x] += sh[threadIdx.x+o]; __syncthreads(); }
        if (threadIdx.x == 0 && sh[0]) atomicAdd(cntP, (float)sh[0]);
    }
}

__global__ void k_lstm(const float* __restrict__ gates, const float* __restrict__ m3,
                       __nv_bfloat16* __restrict__ fh, __nv_bfloat16* __restrict__ fl) {
    int e = blockIdx.x * blockDim.x + threadIdx.x;
    if (e >= S3 * 256) return;
    int c = e & 255;
    int s = e >> 8;
    const float* g = gates + (size_t)s * 768;
    float gi = g[c], go = g[256 + c], gg = g[512 + c];
    float si = 1.f / (1.f + __expf(-gi));
    float so = 1.f / (1.f + __expf(-go));
    float cc = si * tanhf(gg);
    float hh = so * tanhf(cc) * m3[s];
    int b = s / (H3_*W3_); int r = s - b*(H3_*W3_);
    __nv_bfloat16 h = __float2bfloat16(hh);
    fh[b*8960 + c*35 + r] = h;
    fl[b*8960 + c*35 + r] = __float2bfloat16(hh - __bfloat162float(h));
}

// FC1 split-K finalize: y1 = relu(partial0 + partial1 + bias) -> bf16 hi/lo
__global__ void k_fin(const float* __restrict__ y1f, const float* __restrict__ bias,
                      __nv_bfloat16* __restrict__ oh, __nv_bfloat16* __restrict__ ol) {
    int i = (blockIdx.x * blockDim.x + threadIdx.x) * 4;
    if (i >= B_*1024) return;
    float4 a = *reinterpret_cast<const float4*>(&y1f[i]);
    float4 b = *reinterpret_cast<const float4*>(&y1f[B_*1024 + i]);
    int n = i & 1023;
    float4 t;
    t.x = fmaxf(a.x + b.x + bias[n],   0.f);
    t.y = fmaxf(a.y + b.y + bias[n+1], 0.f);
    t.z = fmaxf(a.z + b.z + bias[n+2], 0.f);
    t.w = fmaxf(a.w + b.w + bias[n+3], 0.f);
    *reinterpret_cast<uint2*>(&oh[i]) = make_uint2(bpack(t.x, t.y), bpack(t.z, t.w));
    *reinterpret_cast<uint2*>(&ol[i]) =
        make_uint2(bpack(bres(t.x), bres(t.y)), bpack(bres(t.z), bres(t.w)));
}

// ---------------- param blocks ----------------
struct GemmP {
    const float* A; const float* Bw; const float* bias; float* C;
    int M, N, K, ldb;
    const float* img;
    const float* mf; float* sumP; float* sqP;
};
struct GemmB {
    const __nv_bfloat16 *Ah, *Al;
    const __nv_bfloat16 *Bh, *Bl;
    const float* bias; float* C;
    int M, N, K;
    const float* mf; float* sumP; float* sqP;
    __nv_bfloat16 *oh, *ol;
};

// ---------------- HMMA bf16x3 GEMM, TN in {32,64} (conv2, conv3, FC2) ----------------
template<int TN, int MODE, int EPI, int STAT, int IH, int IW, int IC>
__global__ void __launch_bounds__(256) k_hm2(GemmB p) {
    constexpr int TM = 128, BK = 64;
    constexpr int IM = (TN == 64) ? 2 : 1;
    constexpr int LIC = ilog2c(IC);
    constexpr int LTN = ilog2c(TN);
    constexpr int A_BYTES = TM * 128;
    constexpr int B_BYTES = TN * 128;
    constexpr int BUF = 2*A_BYTES + 2*B_BYTES;
    constexpr int BCH = TN * 8 / 256;
    constexpr int CST = TN + 1;

    extern __shared__ char sm[];
    const int tid = threadIdx.x;
    const int wid = tid >> 5, lid = tid & 31;
    const int wm = (TN == 64) ? (wid >> 1) : wid;
    const int wn = (TN == 64) ? (wid & 1) : 0;
    const int m0 = blockIdx.y * TM;
    const int n0 = blockIdx.x * TN;
    const uint32_t sbuf = smem_u32(sm);

    float acc[IM][4][4];
    #pragma unroll
    for (int i = 0; i < IM; i++)
        #pragma unroll
        for (int j = 0; j < 4; j++)
            #pragma unroll
            for (int q = 0; q < 4; q++) acc[i][j][q] = 0.f;

    const int row = tid >> 1;
    const int kt  = (tid & 1) * 32;
    int sbm = 0, sy = 0, sx = 0;
    if (MODE == 1) {
        int m = m0 + row;
        int b = m / (IH*IW);
        int r = m - b*(IH*IW);
        sy = r / IW;
        sx = r - sy*IW;
        sbm = b*IH*IW;
    }

    uint2 ahr[8], alr[8];
    uint4 bhr[BCH], blr[BCH];

    auto load_tile = [&](int k0) {
        #pragma unroll
        for (int j = 0; j < 8; j++) {
            int k = k0 + kt + j*4;
            uint2 vh = make_uint2(0u, 0u), vl = vh;
            if (k < p.K) {
                size_t idx;
                bool ok = true;
                if (MODE == 0) {
                    idx = (size_t)(m0 + row) * p.K + k;
                } else {
                    int t9 = k >> LIC;
                    int c0 = k & (IC-1);
                    int ky = t9 / 3, kx = t9 - 3*ky;
                    int yy = sy + ky - 1, xx = sx + kx - 1;
                    ok = (yy >= 0 && yy < IH && xx >= 0 && xx < IW);
                    idx = (size_t)(sbm + yy*IW + xx) * IC + c0;
                }
                if (ok) {
                    vh = *reinterpret_cast<const uint2*>(&p.Ah[idx]);
                    vl = *reinterpret_cast<const uint2*>(&p.Al[idx]);
                }
            }
            ahr[j] = vh; alr[j] = vl;
        }
        #pragma unroll
        for (int e = 0; e < BCH; e++) {
            int ge = tid + e*256;
            int n  = ge >> 3;
            int kc = ge & 7;
            int k  = k0 + kc*8;
            uint4 vh = make_uint4(0u,0u,0u,0u), vl = vh;
            if (k < p.K) {
                size_t idx = (size_t)(n0 + n) * p.K + k;
                vh = *reinterpret_cast<const uint4*>(&p.Bh[idx]);
                vl = *reinterpret_cast<const uint4*>(&p.Bl[idx]);
            }
            bhr[e] = vh; blr[e] = vl;
        }
    };

    auto store_tile = [&](int bb) {
        char* Ah = sm + bb;
        char* Al = Ah + A_BYTES;
        char* Bh = Ah + 2*A_BYTES;
        char* Bl = Bh + B_BYTES;
        #pragma unroll
        for (int j = 0; j < 8; j++) {
            uint32_t so = SWZ128((uint32_t)(row*128 + (kt + j*4)*2));
            *reinterpret_cast<uint2*>(Ah + so) = ahr[j];
            *reinterpret_cast<uint2*>(Al + so) = alr[j];
        }
        #pragma unroll
        for (int e = 0; e < BCH; e++) {
            int ge = tid + e*256;
            int n  = ge >> 3;
            int kc = ge & 7;
            uint32_t so = SWZ128((uint32_t)(n*128 + kc*16));
            *reinterpret_cast<uint4*>(Bh + so) = bhr[e];
            *reinterpret_cast<uint4*>(Bl + so) = blr[e];
        }
    };

    auto consume = [&](int bb) {
        uint32_t AH = sbuf + bb;
        uint32_t AL = AH + A_BYTES;
        uint32_t BH = AH + 2*A_BYTES;
        uint32_t BL = BH + B_BYTES;
        #pragma unroll
        for (int ks = 0; ks < 4; ks++) {
            uint32_t bh[2][4], bl[2][4];
            #pragma unroll
            for (int jp = 0; jp < 2; jp++) {
                int n_r = wn*32 + jp*16 + (lid & 7) + ((lid >> 4) << 3);
                int kb  = ks*32 + (((lid >> 3) & 1) << 4);
                uint32_t off = SWZ128((uint32_t)(n_r*128 + kb));
                LDSM_X4(bh[jp][0], bh[jp][1], bh[jp][2], bh[jp][3], BH + off);
                LDSM_X4(bl[jp][0], bl[jp][1], bl[jp][2], bl[jp][3], BL + off);
            }
            #pragma unroll
            for (int im = 0; im < IM; im++) {
                int row_a = wm*(16*IM) + im*16 + (lid & 15);
                int kb    = ks*32 + (lid >> 4) * 16;
                uint32_t off = SWZ128((uint32_t)(row_a*128 + kb));
                uint32_t ah[4], al[4];
                LDSM_X4(ah[0], ah[1], ah[2], ah[3], AH + off);
                LDSM_X4(al[0], al[1], al[2], al[3], AL + off);
                #pragma unroll
                for (int jn = 0; jn < 4; jn++) {
                    int jp = jn >> 1, s = (jn & 1) * 2;
                    MMA_BF16(acc[im][jn], ah[0], ah[1], ah[2], ah[3], bh[jp][s], bh[jp][s+1]);
                    MMA_BF16(acc[im][jn], ah[0], ah[1], ah[2], ah[3], bl[jp][s], bl[jp][s+1]);
                    MMA_BF16(acc[im][jn], al[0], al[1], al[2], al[3], bh[jp][s], bh[jp][s+1]);
                }
            }
        }
    };

    const int T = (p.K + BK - 1) / BK;
    load_tile(0);
    store_tile(0);
    __syncthreads();

    for (int t = 0; t < T; t++) {
        if (t + 1 < T) load_tile((t + 1) * BK);
        consume((t & 1) * BUF);
        if (t + 1 < T) store_tile(((t + 1) & 1) * BUF);
        __syncthreads();
    }

    float* cs   = reinterpret_cast<float*>(sm);
    float* mrow = cs + TM*CST;
    float* rs   = mrow + TM;
    float* rq   = rs + 256;
    #pragma unroll
    for (int im = 0; im < IM; im++) {
        int r0 = wm*(16*IM) + im*16 + (lid >> 2);
        #pragma unroll
        for (int jn = 0; jn < 4; jn++) {
            int c = wn*32 + jn*8 + (lid & 3)*2;
            cs[r0*CST + c]       = acc[im][jn][0];
            cs[r0*CST + c + 1]   = acc[im][jn][1];
            cs[(r0+8)*CST + c]   = acc[im][jn][2];
            cs[(r0+8)*CST + c+1] = acc[im][jn][3];
        }
    }
    if (STAT && tid < TM) mrow[tid] = p.mf[m0 + tid];
    __syncthreads();

    float lsum = 0.f, lsq = 0.f;
    for (int e = tid; e < TM*TN; e += 256) {
        int rr = e >> LTN;
        int cc = e & (TN-1);
        int n  = n0 + cc;
        float v = cs[rr*CST + cc];
        if (STAT) {
            float mk = mrow[rr];
            float xv = (mk > 0.f) ? v : 0.f;
            lsum += xv; lsq += xv*xv;
        }
        if (n < p.N) {
            if (EPI == 1 || EPI == 2 || EPI == 3) {
                int nnb = (EPI == 3 && n >= 256) ? n + 256 : n;
                v += p.bias[nnb];
                if (EPI == 2) v = fmaxf(v, 0.f);
                p.C[(size_t)(m0 + rr) * p.N + n] = v;
            } else if (EPI == 4) {
                v = fmaxf(v + p.bias[n], 0.f);
                __nv_bfloat16 h = __float2bfloat16(v);
                p.oh[(size_t)(m0 + rr) * p.N + n] = h;
                p.ol[(size_t)(m0 + rr) * p.N + n] = __float2bfloat16(v - __bfloat162float(h));
            } else {
                p.C[(size_t)(m0 + rr) * p.N + n] = v;
            }
        }
    }
    if (STAT) {
        rs[tid] = lsum; rq[tid] = lsq;
        __syncthreads();
        if (tid < TN) {
            float s = 0.f, q = 0.f;
            #pragma unroll
            for (int g = 0; g < 256/TN; g++) { s += rs[tid + g*TN]; q += rq[tid + g*TN]; }
            if (n0 + tid < p.N) {
                atomicAdd(&p.sumP[n0 + tid], s);
                atomicAdd(&p.sqP[n0 + tid], q);
            }
        }
    }
}

// ---------------- HMMA bf16x3 GEMM, TM=128 x TN=128, BK=32 (conv4, gate, FC1) ----------
// SPLIT=1: blockIdx.z selects K half; raw fp32 partials to C + z*M*N.
template<int MODE, int EPI, int STAT, int SPLIT, int IH, int IW, int IC>
__global__ void __launch_bounds__(256, 2) k_hm3(GemmB p) {
    constexpr int TM = 128, TN = 128, BK = 32;
    constexpr int LIC = ilog2c(IC);
    constexpr int A_BYTES = TM * 128;
    constexpr int B_BYTES = TN * 128;
    constexpr int STAGE = A_BYTES + B_BYTES;

    extern __shared__ char sm[];
    const int tid = threadIdx.x;
    const int wid = tid >> 5, lid = tid & 31;
    const int wm = wid >> 2;
    const int wn = wid & 3;
    const int m0 = blockIdx.y * TM;
    const int n0 = blockIdx.x * TN;
    const int koff = SPLIT ? (int)blockIdx.z * (p.K >> 1) : 0;
    const int KT   = SPLIT ? (p.K >> 1) : p.K;
    float* Cw = SPLIT ? p.C + (size_t)blockIdx.z * ((size_t)p.M * p.N) : p.C;
    const uint32_t sbuf = smem_u32(sm);

    float acc[4][4][4];
    #pragma unroll
    for (int i = 0; i < 4; i++)
        #pragma unroll
        for (int j = 0; j < 4; j++)
            #pragma unroll
            for (int q = 0; q < 4; q++) acc[i][j][q] = 0.f;

    const int row  = tid >> 1;
    const int half = tid & 1;
    int sbm = 0, sy = 0, sx = 0;
    if (MODE == 1) {
        int m = m0 + row;
        int b = m / (IH*IW);
        int r = m - b*(IH*IW);
        sy = r / IW;
        sx = r - sy*IW;
        sbm = b*IH*IW;
    }

    uint4 ar[4], br[4];

    auto load_tile = [&](int k0) {
        {
            const __nv_bfloat16* src = half ? p.Al : p.Ah;
            bool ok = true;
            size_t idx = 0;
            if (MODE == 0) {
                idx = (size_t)(m0 + row) * p.K + koff + k0;
            } else {
                int t9 = k0 >> LIC;
                int c0 = k0 & (IC-1);
                int ky = t9 / 3, kx = t9 - 3*ky;
                int yy = sy + ky - 1, xx = sx + kx - 1;
                ok = (yy >= 0 && yy < IH && xx >= 0 && xx < IW);
                idx = (size_t)(sbm + yy*IW + xx) * IC + c0;
            }
            if (ok) {
                const uint4* s4 = reinterpret_cast<const uint4*>(&src[idx]);
                #pragma unroll
                for (int j = 0; j < 4; j++) ar[j] = s4[j];
            } else {
                #pragma unroll
                for (int j = 0; j < 4; j++) ar[j] = make_uint4(0u,0u,0u,0u);
            }
        }
        {
            const __nv_bfloat16* src = half ? p.Bl : p.Bh;
            const uint4* s4 = reinterpret_cast<const uint4*>(&src[(size_t)(n0 + row) * p.K + koff + k0]);
            #pragma unroll
            for (int j = 0; j < 4; j++) br[j] = s4[j];
        }
    };

    auto store_tile = [&](int bb) {
        char* Ab = sm + bb;
        char* Bb = Ab + A_BYTES;
        #pragma unroll
        for (int j = 0; j < 4; j++) {
            uint32_t so = SWZ128((uint32_t)(row*128 + half*64 + j*16));
            *reinterpret_cast<uint4*>(Ab + so) = ar[j];
            *reinterpret_cast<uint4*>(Bb + so) = br[j];
        }
    };

    auto consume = [&](int bb) {
        uint32_t Abase = sbuf + bb;
        uint32_t Bbase = Abase + A_BYTES;
        #pragma unroll
        for (int ks = 0; ks < 2; ks++) {
            uint32_t bh[2][4], bl[2][4];
            #pragma unroll
            for (int jp = 0; jp < 2; jp++) {
                int n_r = wn*32 + jp*16 + (lid & 7) + ((lid >> 4) << 3);
                int kb  = ks*32 + (((lid >> 3) & 1) << 4);
                LDSM_X4(bh[jp][0], bh[jp][1], bh[jp][2], bh[jp][3],
                        Bbase + SWZ128((uint32_t)(n_r*128 + kb)));
                LDSM_X4(bl[jp][0], bl[jp][1], bl[jp][2], bl[jp][3],
                        Bbase + SWZ128((uint32_t)(n_r*128 + 64 + kb)));
            }
            #pragma unroll
            for (int im = 0; im < 4; im++) {
                int row_a = wm*64 + im*16 + (lid & 15);
                int kb    = ks*32 + ((lid >> 4) << 4);
                uint32_t ah[4], al[4];
                LDSM_X4(ah[0], ah[1], ah[2], ah[3],
                        Abase + SWZ128((uint32_t)(row_a*128 + kb)));
                LDSM_X4(al[0], al[1], al[2], al[3],
                        Abase + SWZ128((uint32_t)(row_a*128 + 64 + kb)));
                #pragma unroll
                for (int jn = 0; jn < 4; jn++) {
                    int jp = jn >> 1, s = (jn & 1) * 2;
                    MMA_BF16(acc[im][jn], ah[0], ah[1], ah[2], ah[3], bh[jp][s], bh[jp][s+1]);
                    MMA_BF16(acc[im][jn], ah[0], ah[1], ah[2], ah[3], bl[jp][s], bl[jp][s+1]);
                    MMA_BF16(acc[im][jn], al[0], al[1], al[2], al[3], bh[jp][s], bh[jp][s+1]);
                }
            }
        }
    };

    const int T = KT / BK;
    load_tile(0);
    store_tile(0);
    __syncthreads();

    for (int t = 0; t < T; t++) {
        if (t + 1 < T) load_tile((t + 1) * BK);
        consume((t & 1) * STAGE);
        if (t + 1 < T) store_tile(((t + 1) & 1) * STAGE);
        __syncthreads();
    }

    constexpr int CST = 130;
    float* cs   = reinterpret_cast<float*>(sm);
    float* mrow = cs + 64*CST;
    float* rs   = mrow + 128;
    float* rq   = rs + 256;
    if (STAT && tid < 128) mrow[tid] = p.mf[m0 + tid];
    float lsum = 0.f, lsq = 0.f;

    #pragma unroll
    for (int h = 0; h < 2; h++) {
        if (wm == h) {
            #pragma unroll
            for (int im = 0; im < 4; im++) {
                int r0 = im*16 + (lid >> 2);
                #pragma unroll
                for (int jn = 0; jn < 4; jn++) {
                    int c = wn*32 + jn*8 + (lid & 3)*2;
                    cs[r0*CST + c]       = acc[im][jn][0];
                    cs[r0*CST + c + 1]   = acc[im][jn][1];
                    cs[(r0+8)*CST + c]   = acc[im][jn][2];
                    cs[(r0+8)*CST + c+1] = acc[im][jn][3];
                }
            }
        }
        __syncthreads();
        for (int e = tid; e < 64*128; e += 256) {
            int rr = e >> 7;
            int cc = e & 127;
            int n  = n0 + cc;
            float v = cs[rr*CST + cc];
            if (STAT) {
                float mk = mrow[h*64 + rr];
                float xv = (mk > 0.f) ? v : 0.f;
                lsum += xv; lsq += xv*xv;
            }
            if (n < p.N) {
                if (SPLIT) {
                    Cw[(size_t)(m0 + h*64 + rr) * p.N + n] = v;
                } else if (EPI == 1 || EPI == 2 || EPI == 3) {
                    int nnb = (EPI == 3 && n >= 256) ? n + 256 : n;
                    v += p.bias[nnb];
                    if (EPI == 2) v = fmaxf(v, 0.f);
                    Cw[(size_t)(m0 + h*64 + rr) * p.N + n] = v;
                } else if (EPI == 4) {
                    v = fmaxf(v + p.bias[n], 0.f);
                    __nv_bfloat16 hb = __float2bfloat16(v);
                    p.oh[(size_t)(m0 + h*64 + rr) * p.N + n] = hb;
                    p.ol[(size_t)(m0 + h*64 + rr) * p.N + n] = __float2bfloat16(v - __bfloat162float(hb));
                } else {
                    Cw[(size_t)(m0 + h*64 + rr) * p.N + n] = v;
                }
            }
        }
        __syncthreads();
    }
    if (STAT) {
        rs[tid] = lsum; rq[tid] = lsq;
        __syncthreads();
        if (tid < 128) {
            float s = rs[tid] + rs[tid + 128];
            float q = rq[tid] + rq[tid + 128];
            if (n0 + tid < p.N) {
                atomicAdd(&p.sumP[n0 + tid], s);
                atomicAdd(&p.sqP[n0 + tid], q);
            }
        }
    }
}

// ---------------- packed-f32x2 GEMM (conv1 only), fused stats ----------------
template<int TN, int MODE, int EPI, int STAT, int IH, int IW, int IC>
__global__ void __launch_bounds__(256) k_gemm3(GemmP p) {
    constexpr int TM = 128, BK = 16;
    constexpr int TX = (TN == 32) ? 8 : 16;
    constexpr int NR = TN / TX;
    constexpr int TY = 256 / TX;
    constexpr int MR = TM / TY;
    constexpr int MP = MR / 2;
    constexpr int LIC = ilog2c(IC);
    constexpr int LTN = ilog2c(TN);
    constexpr int B_EPT = (BK * TN) / 256;

    __shared__ float  As[2][BK][TM];
    __shared__ float2 Bs[2][BK][TN];
    __shared__ float mrow[TM];
    __shared__ float sred[TN], qred[TN];

    const int tid = threadIdx.x;
    const int tx = tid % TX, ty = tid / TX;
    const int m0 = blockIdx.y * TM;
    const int n0 = blockIdx.x * TN;

    unsigned long long acc[MP][NR];
    #pragma unroll
    for (int i = 0; i < MP; i++)
        #pragma unroll
        for (int j = 0; j < NR; j++) acc[i][j] = 0ULL;

    int pm_b[2], pm_y[2], pm_x[2];
    if (MODE == 1) {
        #pragma unroll
        for (int i = 0; i < 2; i++) {
            int m = m0 + ((tid + i*256) >> 2);
            int b = m / (IH*IW);
            int r = m - b*(IH*IW);
            int y = r / IW;
            pm_b[i] = b*IH*IW;
            pm_y[i] = y;
            pm_x[i] = r - y*IW;
        }
    }

    float a_reg[8];
    float b_reg[B_EPT];

    auto load_tile = [&](int k0) {
        if (MODE == 1) {
            #pragma unroll
            for (int i = 0; i < 2; i++) {
                int gq = tid + i*256;
                int kbase = k0 + (gq & 3)*4;
                #pragma unroll
                for (int j = 0; j < 4; j++) {
                    int k = kbase + j;
                    float v = 0.f;
                    if (k < p.K) {
                        int c  = k & (IC-1);
                        int t9 = k >> LIC;
                        int ky = t9 / 3, kx = t9 - 3*ky;
                        int yy = pm_y[i] + ky - 1, xx = pm_x[i] + kx - 1;
                        if (yy >= 0 && yy < IH && xx >= 0 && xx < IW)
                            v = p.img[(size_t)(pm_b[i] + yy*IW + xx) * IC + c];
                    }
                    a_reg[i*4+j] = v;
                }
            }
        } else {
            #pragma unroll
            for (int i = 0; i < 2; i++) {
                int gq = tid + i*256;
                int m = m0 + (gq >> 2);
                int k = k0 + (gq & 3) * 4;
                float4 t = *reinterpret_cast<const float4*>(&p.A[(size_t)m * p.K + k]);
                a_reg[i*4+0] = t.x; a_reg[i*4+1] = t.y;
                a_reg[i*4+2] = t.z; a_reg[i*4+3] = t.w;
            }
        }
        #pragma unroll
        for (int e = 0; e < B_EPT; e++) {
            int ge = tid + e*256;
            int kl = ge >> LTN;
            int n  = ge & (TN-1);
            int k  = k0 + kl;
            int nn = n0 + n;
            float v = 0.f;
            if (k < p.K && nn < p.N) v = p.Bw[(size_t)k * p.ldb + nn];
            b_reg[e] = v;
        }
    };

    auto store_tile = [&](int buf) {
        #pragma unroll
        for (int i = 0; i < 2; i++) {
            int gq = tid + i*256;
            int ml = gq >> 2;
            int kq = (gq & 3) * 4;
            #pragma unroll
            for (int j = 0; j < 4; j++) As[buf][kq+j][ml] = a_reg[i*4+j];
        }
        #pragma unroll
        for (int e = 0; e < B_EPT; e++) {
            int ge = tid + e*256;
            int kl = ge >> LTN;
            int n  = ge & (TN-1);
            Bs[buf][kl][n] = make_float2(b_reg[e], b_reg[e]);
        }
    };

    const int nTiles = (p.K + BK - 1) / BK;
    load_tile(0);
    store_tile(0);
    __syncthreads();

    for (int t = 0; t < nTiles; t++) {
        int cur = t & 1;
        if (t + 1 < nTiles) load_tile((t + 1) * BK);
        #pragma unroll
        for (int kk = 0; kk < BK; kk++) {
            unsigned long long af[MP], bf[NR];
            const ulonglong2* ap = reinterpret_cast<const ulonglong2*>(&As[cur][kk][ty*MR]);
            #pragma unroll
            for (int i = 0; i < MP/2; i++) { ulonglong2 v = ap[i]; af[2*i] = v.x; af[2*i+1] = v.y; }
            const unsigned long long* bp = reinterpret_cast<const unsigned long long*>(&Bs[cur][kk][0]);
            #pragma unroll
            for (int nr = 0; nr < NR; nr++) bf[nr] = bp[tx + nr*TX];
            #pragma unroll
            for (int mp = 0; mp < MP; mp++)
                #pragma unroll
                for (int nr = 0; nr < NR; nr++)
                    FMA2(acc[mp][nr], af[mp], bf[nr]);
        }
        if (t + 1 < nTiles) store_tile(cur ^ 1);
        __syncthreads();
    }

    if (STAT) {
        if (tid < TN) { sred[tid] = 0.f; qred[tid] = 0.f; }
        if (tid < TM) mrow[tid] = p.mf[m0 + tid];
        __syncthreads();
    }

    #pragma unroll
    for (int mp = 0; mp < MP; mp++) {
        int m = m0 + ty*MR + 2*mp;
        #pragma unroll
        for (int nr = 0; nr < NR; nr++) {
            int n = n0 + tx + nr*TX;
            if (n >= p.N) continue;
            float lo = __uint_as_float((unsigned)(acc[mp][nr] & 0xFFFFFFFFULL));
            float hi = __uint_as_float((unsigned)(acc[mp][nr] >> 32));
            if (STAT) {
                float mk0 = mrow[ty*MR + 2*mp], mk1 = mrow[ty*MR + 2*mp + 1];
                float x0 = (mk0 > 0.f) ? lo : 0.f;
                float x1 = (mk1 > 0.f) ? hi : 0.f;
                atomicAdd(&sred[n - n0], x0 + x1);
                atomicAdd(&qred[n - n0], x0*x0 + x1*x1);
            }
            if (EPI >= 1) { float bb = p.bias[n]; lo += bb; hi += bb; }
            if (EPI == 2) { lo = fmaxf(lo, 0.f); hi = fmaxf(hi, 0.f); }
            p.C[(size_t)m       * p.N + n] = lo;
            p.C[(size_t)(m + 1) * p.N + n] = hi;
        }
    }
    if (STAT) {
        __syncthreads();
        if (tid < TN && n0 + tid < p.N) {
            atomicAdd(&p.sumP[n0 + tid], sred[tid]);
            atomicAdd(&p.sqP[n0 + tid], qred[tid]);
        }
    }
}

// ---------------- launcher ----------------
static inline int ceil_div(int a, int b) { return (a + b - 1) / b; }
#define HM_SMEM64 (2 * (2*128*128 + 2*64*128))   // 96 KB
#define HM_SMEM32 (2 * (2*128*128 + 2*32*128))   // 80 KB
#define HM3_SMEM  (2 * (128*128 + 128*128))      // 64 KB

extern "C" void kernel_launch(void* const* d_in, const int* in_sizes, int n_in,
                              void* d_out, int out_size) {
    const float* x    = (const float*)d_in[0];
    const int*   mask = (const int*)  d_in[1];
    const float* W1 = (const float*)d_in[2];  const float* ga1 = (const float*)d_in[3];  const float* be1 = (const float*)d_in[4];
    const float* W2 = (const float*)d_in[5];  const float* ga2 = (const float*)d_in[6];  const float* be2 = (const float*)d_in[7];
    const float* W3 = (const float*)d_in[8];  const float* ga3 = (const float*)d_in[9];  const float* be3 = (const float*)d_in[10];
    const float* W4 = (const float*)d_in[11]; const float* ga4 = (const float*)d_in[12]; const float* be4 = (const float*)d_in[13];
    const float* Wl = (const float*)d_in[14]; const float* bl  = (const float*)d_in[15];
    const float* lw1 = (const float*)d_in[16]; const float* lb1 = (const float*)d_in[17];
    const float* lw2 = (const float*)d_in[18]; const float* lb2 = (const float*)d_in[19];
    float* out = (float*)d_out;

    float *xm, *m1, *h1, *h2, *m2, *h3, *h4, *m3, *gates, *y1f, *st;
    __nv_bfloat16 *h1h, *h1l, *p1h, *p1l, *h3h, *h3l, *p2h, *p2l, *fh, *fl, *y1h, *y1l;
    __nv_bfloat16 *w2h, *w2l, *w3h, *w3l, *w4h, *w4l, *wlh, *wll, *l1h, *l1l, *l2h, *l2l;
    cudaGetSymbolAddress((void**)&xm,  g_xm);   cudaGetSymbolAddress((void**)&m1,  g_m1);
    cudaGetSymbolAddress((void**)&h1,  g_h1);   cudaGetSymbolAddress((void**)&h2,  g_h2);
    cudaGetSymbolAddress((void**)&m2,  g_m2);   cudaGetSymbolAddress((void**)&h3,  g_h3);
    cudaGetSymbolAddress((void**)&h4,  g_h4);   cudaGetSymbolAddress((void**)&m3,  g_m3);
    cudaGetSymbolAddress((void**)&gates, g_gates);
    cudaGetSymbolAddress((void**)&y1f, g_y1f);  cudaGetSymbolAddress((void**)&st,  g_stats);
    cudaGetSymbolAddress((void**)&h1h, g_h1h);  cudaGetSymbolAddress((void**)&h1l, g_h1l);
    cudaGetSymbolAddress((void**)&p1h, g_p1h);  cudaGetSymbolAddress((void**)&p1l, g_p1l);
    cudaGetSymbolAddress((void**)&h3h, g_h3h);  cudaGetSymbolAddress((void**)&h3l, g_h3l);
    cudaGetSymbolAddress((void**)&p2h, g_p2h);  cudaGetSymbolAddress((void**)&p2l, g_p2l);
    cudaGetSymbolAddress((void**)&fh,  g_flath);cudaGetSymbolAddress((void**)&fl,  g_flatl);
    cudaGetSymbolAddress((void**)&y1h, g_y1h);  cudaGetSymbolAddress((void**)&y1l, g_y1l);
    cudaGetSymbolAddress((void**)&w2h, g_w2h);  cudaGetSymbolAddress((void**)&w2l, g_w2l);
    cudaGetSymbolAddress((void**)&w3h, g_w3h);  cudaGetSymbolAddress((void**)&w3l, g_w3l);
    cudaGetSymbolAddress((void**)&w4h, g_w4h);  cudaGetSymbolAddress((void**)&w4l, g_w4l);
    cudaGetSymbolAddress((void**)&wlh, g_wlh);  cudaGetSymbolAddress((void**)&wll, g_wll);
    cudaGetSymbolAddress((void**)&l1h, g_l1h);  cudaGetSymbolAddress((void**)&l1l, g_l1l);
    cudaGetSymbolAddress((void**)&l2h, g_l2h);  cudaGetSymbolAddress((void**)&l2l, g_l2l);

    float *sum1 = st+0,   *sq1 = st+16;
    float *sum2 = st+32,  *sq2 = st+64;
    float *sum3 = st+128, *sq3 = st+192;
    float *sum4 = st+256, *sq4 = st+384;
    float *n1 = st+512, *n2 = st+513;

    cudaFuncSetAttribute(k_hm2<32,1,0,1,H1_,W1_,16>,  cudaFuncAttributeMaxDynamicSharedMemorySize, HM_SMEM32);
    cudaFuncSetAttribute(k_hm2<64,1,0,1,H2_,W2_,32>,  cudaFuncAttributeMaxDynamicSharedMemorySize, HM_SMEM64);
    cudaFuncSetAttribute(k_hm2<64,0,1,0,1,1,16>,      cudaFuncAttributeMaxDynamicSharedMemorySize, HM_SMEM64);
    cudaFuncSetAttribute(k_hm3<1,0,1,0,H2_,W2_,64>,   cudaFuncAttributeMaxDynamicSharedMemorySize, HM3_SMEM);
    cudaFuncSetAttribute(k_hm3<1,3,0,0,H3_,W3_,128>,  cudaFuncAttributeMaxDynamicSharedMemorySize, HM3_SMEM);
    cudaFuncSetAttribute(k_hm3<0,0,0,1,1,1,32>,       cudaFuncAttributeMaxDynamicSharedMemorySize, HM3_SMEM);

    // weight transpose+split
    { dim3 b(32,32);
      k_wt<0><<<dim3(ceil_div(144,32),  1),  b>>>(W2,  w2h, w2l, 144,  32,   32);
      k_wt<0><<<dim3(ceil_div(288,32),  2),  b>>>(W3,  w3h, w3l, 288,  64,   64);
      k_wt<0><<<dim3(ceil_div(576,32),  4),  b>>>(W4,  w4h, w4l, 576,  128,  128);
      k_wt<1><<<dim3(ceil_div(1152,32), 24), b>>>(Wl,  wlh, wll, 1152, 768,  1024);
      k_wt<0><<<dim3(ceil_div(8960,32), 32), b>>>(lw1, l1h, l1l, 8960, 1024, 1024);
      k_wt<0><<<dim3(ceil_div(1024,32), 14), b>>>(lw2, l2h, l2l, 1024, 420,  420);
    }

    k_zero_stats<<<1, 1024>>>(st);
    k_prep<<<ceil_div(S1, 256), 256>>>(x, mask, xm, m1, n1);

    // conv1: 2->16 (K=18) — FFMA2 + fused stats
    { GemmP p = { nullptr, W1, nullptr, h1, S1, 16, 18, 16, xm, m1, sum1, sq1 };
      k_gemm3<32,1,0,1,H1_,W1_,2><<<dim3(1, S1/128), 256>>>(p); }
    k_apply3<4><<<ceil_div(S1*16/4, 256), 256>>>(h1, m1, S1, sum1, sq1, n1, ga1, be1, h1h, h1l);

    // conv2: 16->32 (K=144) — HMMA TN=32 + fused stats
    { GemmB p = { h1h, h1l, w2h, w2l, nullptr, h2, S1, 32, 144, m1, sum2, sq2, nullptr, nullptr };
      k_hm2<32,1,0,1,H1_,W1_,16><<<dim3(1, S1/128), 256, HM_SMEM32>>>(p); }

    // pool1 + BN2 fused -> bf16, count n2
    k_poolbn<5><<<ceil_div(S2*32, 256), 256>>>(h2, m1, sum2, sq2, n1, ga2, be2,
                                               p1h, p1l, m2, H1_, W1_, H2_, W2_, n2);

    // conv3: 32->64 (K=288) — HMMA TN=64 + fused stats
    { GemmB p = { p1h, p1l, w3h, w3l, nullptr, h3, S2, 64, 288, m2, sum3, sq3, nullptr, nullptr };
      k_hm2<64,1,0,1,H2_,W2_,32><<<dim3(1, S2/128), 256, HM_SMEM64>>>(p); }
    k_apply3<6><<<ceil_div(S2*64/4, 256), 256>>>(h3, m2, S2, sum3, sq3, n2, ga3, be3, h3h, h3l);

    // conv4: 64->128 (K=576) — HMMA TN=128 + fused stats
    { GemmB p = { h3h, h3l, w4h, w4l, nullptr, h4, S2, 128, 576, m2, sum4, sq4, nullptr, nullptr };
      k_hm3<1,0,1,0,H2_,W2_,64><<<dim3(1, S2/128), 256, HM3_SMEM>>>(p); }

    // pool2 + BN4 fused -> bf16
    k_poolbn<7><<<ceil_div(S3*128, 256), 256>>>(h4, m2, sum4, sq4, n2, ga4, be4,
                                                p2h, p2l, m3, H2_, W2_, H3_, W3_, nullptr);

    // gate conv: 128->768 (f skipped; remap in k_wt) + bias (K=1152) — HMMA TN=128
    { GemmB p = { p2h, p2l, wlh, wll, bl, gates, S3, 768, 1152, nullptr, nullptr, nullptr, nullptr, nullptr };
      k_hm3<1,3,0,0,H3_,W3_,128><<<dim3(6, S3/128), 256, HM3_SMEM>>>(p); }

    // LSTM nonlinearity -> flat bf16 hi/lo in (C,H,W) order
    k_lstm<<<ceil_div(S3*256, 256), 256>>>(gates, m3, fh, fl);

    // FC1: [2048,8960]x[8960,1024] — HMMA TN=128, split-K=2 -> fp32 partials
    { GemmB p = { fh, fl, l1h, l1l, nullptr, y1f, B_, 1024, 8960, nullptr, nullptr, nullptr, nullptr, nullptr };
      k_hm3<0,0,0,1,1,1,32><<<dim3(8, B_/128, 2), 256, HM3_SMEM>>>(p); }
    // finalize: sum partials + bias + relu -> bf16 hi/lo
    k_fin<<<ceil_div(B_*1024/4, 256), 256>>>(y1f, lb1, y1h, y1l);

    // FC2: [2048,1024]x[1024,420] + bias -> out — HMMA TN=64
    { GemmB p = { y1h, y1l, l2h, l2l, lb2, out, B_, 420, 1024, nullptr, nullptr, nullptr, nullptr, nullptr };
      k_hm2<64,0,1,0,1,1,16><<<dim3(7, B_/128), 256, HM_SMEM64>>>(p); }
}

// round 15
// speedup vs baseline: 1.5684x; 1.0875x over previous
#include <cuda_runtime.h>
#include <cuda_bf16.h>
#include <math.h>
#include <stdint.h>

#define EPS 1e-4f

#define B_  2048
#define H1_ 23
#define W1_ 31
#define H2_ 11
#define W2_ 15
#define H3_ 5
#define W3_ 7

#define S1 (B_*H1_*W1_)
#define S2 (B_*H2_*W2_)
#define S3 (B_*H3_*W3_)

// ---------------- scratch ----------------
__device__ __align__(16) float g_xm[S1*2];
__device__ __align__(16) float g_m1[S1];
__device__ __align__(16) float g_h1[S1*16];
__device__ __align__(16) __nv_bfloat16 g_h1h[S1*16];
__device__ __align__(16) __nv_bfloat16 g_h1l[S1*16];
__device__ __align__(16) float g_h2[S1*32];
__device__ __align__(16) __nv_bfloat16 g_p1h[S2*32];
__device__ __align__(16) __nv_bfloat16 g_p1l[S2*32];
__device__ __align__(16) float g_m2[S2];
__device__ __align__(16) float g_h3[S2*64];
__device__ __align__(16) __nv_bfloat16 g_h3h[S2*64];
__device__ __align__(16) __nv_bfloat16 g_h3l[S2*64];
__device__ __align__(16) float g_h4[S2*128];
__device__ __align__(16) __nv_bfloat16 g_p2h[S3*128];
__device__ __align__(16) __nv_bfloat16 g_p2l[S3*128];
__device__ __align__(16) float g_m3[S3];
__device__ __align__(16) float g_gates[S3*768];   // rows ordered m = r*2048 + b
__device__ __align__(16) __nv_bfloat16 g_flath[B_*8960];
__device__ __align__(16) __nv_bfloat16 g_flatl[B_*8960];
__device__ __align__(16) float g_y1f[2*B_*1024];
__device__ __align__(16) __nv_bfloat16 g_y1h[B_*1024];
__device__ __align__(16) __nv_bfloat16 g_y1l[B_*1024];
__device__ __align__(16) float g_stats[544];
// transposed bf16 weights [n][k]
__device__ __align__(16) __nv_bfloat16 g_w2h[32*144],   g_w2l[32*144];
__device__ __align__(16) __nv_bfloat16 g_w3h[64*288],   g_w3l[64*288];
__device__ __align__(16) __nv_bfloat16 g_w4h[128*576],  g_w4l[128*576];
__device__ __align__(16) __nv_bfloat16 g_wlh[768*1152], g_wll[768*1152];
__device__ __align__(16) __nv_bfloat16 g_l1h[1024*8960],g_l1l[1024*8960];
__device__ __align__(16) __nv_bfloat16 g_l2h[448*1024], g_l2l[448*1024];

__host__ __device__ constexpr int ilog2c(int x) { return x <= 1 ? 0 : 1 + ilog2c(x >> 1); }

#define FMA2(d, a, b) asm("fma.rn.f32x2 %0, %1, %2, %0;" : "+l"(d) : "l"(a), "l"(b))
#define SWZ128(x) ((x) ^ (((x) >> 3) & 0x70))

__device__ __forceinline__ uint32_t smem_u32(const void* p) {
    uint32_t a;
    asm("{ .reg .u64 t; cvta.to.shared.u64 t, %1; cvt.u32.u64 %0, t; }" : "=r"(a) : "l"(p));
    return a;
}

#define LDSM_X4(r0, r1, r2, r3, addr) \
    asm volatile("ldmatrix.sync.aligned.m8n8.x4.shared.b16 {%0,%1,%2,%3}, [%4];" \
        : "=r"(r0), "=r"(r1), "=r"(r2), "=r"(r3) : "r"(addr))

#define MMA_BF16(d, a0, a1, a2, a3, b0, b1) \
    asm volatile("mma.sync.aligned.m16n8k16.row.col.f32.bf16.bf16.f32 " \
        "{%0,%1,%2,%3}, {%4,%5,%6,%7}, {%8,%9}, {%0,%1,%2,%3};" \
        : "+f"((d)[0]), "+f"((d)[1]), "+f"((d)[2]), "+f"((d)[3]) \
        : "r"(a0), "r"(a1), "r"(a2), "r"(a3), "r"(b0), "r"(b1))

__device__ __forceinline__ uint32_t bpack(float a, float b) {
    __nv_bfloat162 t;
    t.x = __float2bfloat16(a);
    t.y = __float2bfloat16(b);
    return *reinterpret_cast<uint32_t*>(&t);
}
__device__ __forceinline__ float bres(float x) {
    return x - __bfloat162float(__float2bfloat16(x));
}

// ---------------- small kernels ----------------
__global__ void k_zero_stats(float* st) {
    if (threadIdx.x < 544) st[threadIdx.x] = 0.f;
}

__global__ void k_prep(const float* __restrict__ x, const int* __restrict__ mask,
                       float* __restrict__ xm, float* __restrict__ m1, float* nP) {
    int s = blockIdx.x * blockDim.x + threadIdx.x;
    int act = 0;
    if (s < S1) {
        float m = (float)mask[s];
        m1[s] = m;
        xm[2*s]   = x[2*s]   * m;
        xm[2*s+1] = x[2*s+1] * m;
        act = (m > 0.f);
    }
    __shared__ int sh[256];
    sh[threadIdx.x] = act; __syncthreads();
    for (int o = 128; o > 0; o >>= 1) { if (threadIdx.x < o) sh[threadIdx.x] += sh[threadIdx.x+o]; __syncthreads(); }
    if (threadIdx.x == 0 && sh[0]) atomicAdd(nP, (float)sh[0]);
}

template<int REMAP>
__global__ void k_wt(const float* __restrict__ W, __nv_bfloat16* __restrict__ Wh,
                     __nv_bfloat16* __restrict__ Wl, int K, int N, int ldb) {
    __shared__ float t[32][33];
    int k = blockIdx.x*32 + threadIdx.y;
    int n = blockIdx.y*32 + threadIdx.x;
    int nn = (REMAP && n >= 256) ? n + 256 : n;
    t[threadIdx.y][threadIdx.x] = (k < K && n < N) ? W[(size_t)k*ldb + nn] : 0.f;
    __syncthreads();
    int ko = blockIdx.x*32 + threadIdx.x;
    int no = blockIdx.y*32 + threadIdx.y;
    if (ko < K) {
        float v = t[threadIdx.x][threadIdx.y];
        __nv_bfloat16 h = __float2bfloat16(v);
        Wh[(size_t)no*K + ko] = h;
        Wl[(size_t)no*K + ko] = __float2bfloat16(v - __bfloat162float(h));
    }
}

template<int CSH>
__global__ void k_apply3(const float* __restrict__ v, const float* __restrict__ mf,
                         int sites,
                         const float* __restrict__ sumP, const float* __restrict__ sqP,
                         const float* __restrict__ nP,
                         const float* __restrict__ gamma, const float* __restrict__ beta,
                         __nv_bfloat16* __restrict__ oh, __nv_bfloat16* __restrict__ ol) {
    constexpr int C = 1 << CSH;
    __shared__ float sc[C], so[C];
    if (threadIdx.x < C) {
        float n = fmaxf(nP[0], 1.f);
        float mean = sumP[threadIdx.x] / n;
        float var  = sqP[threadIdx.x] / n - mean*mean;
        float rs   = rsqrtf(var + EPS) * gamma[threadIdx.x];
        sc[threadIdx.x] = rs;
        so[threadIdx.x] = beta[threadIdx.x] - mean * rs;
    }
    __syncthreads();
    int i = blockIdx.x * blockDim.x + threadIdx.x;
    int total4 = (sites << CSH) >> 2;
    if (i < total4) {
        int e = i * 4;
        int c0 = e & (C-1);
        float m = mf[e >> CSH];
        float4 t = *reinterpret_cast<const float4*>(&v[e]);
        t.x = fmaxf(t.x*sc[c0+0] + so[c0+0], 0.f) * m;
        t.y = fmaxf(t.y*sc[c0+1] + so[c0+1], 0.f) * m;
        t.z = fmaxf(t.z*sc[c0+2] + so[c0+2], 0.f) * m;
        t.w = fmaxf(t.w*sc[c0+3] + so[c0+3], 0.f) * m;
        *reinterpret_cast<uint2*>(&oh[e]) = make_uint2(bpack(t.x, t.y), bpack(t.z, t.w));
        *reinterpret_cast<uint2*>(&ol[e]) =
            make_uint2(bpack(bres(t.x), bres(t.y)), bpack(bres(t.z), bres(t.w)));
    }
}

template<int CSH>
__global__ void k_poolbn(const float* __restrict__ in, const float* __restrict__ mfin,
                         const float* __restrict__ sumP, const float* __restrict__ sqP,
                         const float* __restrict__ nP,
                         const float* __restrict__ gamma, const float* __restrict__ beta,
                         __nv_bfloat16* __restrict__ oh, __nv_bfloat16* __restrict__ ol,
                         float* __restrict__ mfout,
                         int Hi, int Wi, int Ho, int Wo, float* cntP) {
    constexpr int C = 1 << CSH;
    __shared__ float sc[C], so[C];
    if (threadIdx.x < C) {
        float n = fmaxf(nP[0], 1.f);
        float mean = sumP[threadIdx.x] / n;
        float var  = sqP[threadIdx.x] / n - mean*mean;
        float rs   = rsqrtf(var + EPS) * gamma[threadIdx.x];
        sc[threadIdx.x] = rs;
        so[threadIdx.x] = beta[threadIdx.x] - mean * rs;
    }
    __syncthreads();
    int e = blockIdx.x * blockDim.x + threadIdx.x;
    int total = B_ * Ho * Wo * C;
    int newact = 0;
    if (e < total) {
        int c = e & (C-1);
        int s = e >> CSH;
        int b = s / (Ho*Wo); int r = s - b*(Ho*Wo);
        int y = r / Wo;      int xo = r - y*Wo;
        float best = -1e30f, mm = 0.f;
        float fc = sc[c], fo = so[c];
        #pragma unroll
        for (int dy = 0; dy < 3; dy++)
            #pragma unroll
            for (int dx = 0; dx < 3; dx++) {
                int si = (b*Hi + 2*y + dy) * Wi + 2*xo + dx;
                float m = mfin[si];
                mm = fmaxf(mm, m);
                float vv = -1e30f;
                if (m > 0.f) vv = fmaxf(in[(size_t)si * C + c] * fc + fo, 0.f);
                best = fmaxf(best, vv);
            }
        float v = (mm > 0.f) ? best : 0.f;
        __nv_bfloat16 h = __float2bfloat16(v);
        oh[e] = h;
        ol[e] = __float2bfloat16(v - __bfloat162float(h));
        if (c == 0) { mfout[s] = mm; newact = (mm > 0.f); }
    }
    if (cntP) {
        __shared__ int sh[256];
        sh[threadIdx.x] = newact; __syncthreads();
        for (int o = 128; o > 0; o >>= 1) { if (threadIdx.x < o) sh[threadIdx.x] += sh[threadIdx.x+o]; __syncthreads(); }
        if (threadIdx.x == 0 && sh[0]) atomicAdd(cntP, (float)sh[0]);
    }
}

// LSTM; gates rows ordered m = r*2048 + b
__global__ void k_lstm(const float* __restrict__ gates, const float* __restrict__ m3,
                       __nv_bfloat16* __restrict__ fh, __nv_bfloat16* __restrict__ fl) {
    int e = blockIdx.x * blockDim.x + threadIdx.x;
    if (e >= S3 * 256) return;
    int c = e & 255;
    int s = e >> 8;              // gate row = r*2048 + b
    int b = s & 2047, r = s >> 11;
    const float* g = gates + (size_t)s * 768;
    float gi = g[c], go = g[256 + c], gg = g[512 + c];
    float si = 1.f / (1.f + __expf(-gi));
    float so = 1.f / (1.f + __expf(-go));
    float cc = si * tanhf(gg);
    float hh = so * tanhf(cc) * m3[b*35 + r];
    __nv_bfloat16 h = __float2bfloat16(hh);
    fh[b*8960 + c*35 + r] = h;
    fl[b*8960 + c*35 + r] = __float2bfloat16(hh - __bfloat162float(h));
}

// FC1 split-K finalize
__global__ void k_fin(const float* __restrict__ y1f, const float* __restrict__ bias,
                      __nv_bfloat16* __restrict__ oh, __nv_bfloat16* __restrict__ ol) {
    int i = (blockIdx.x * blockDim.x + threadIdx.x) * 4;
    if (i >= B_*1024) return;
    float4 a = *reinterpret_cast<const float4*>(&y1f[i]);
    float4 b = *reinterpret_cast<const float4*>(&y1f[B_*1024 + i]);
    int n = i & 1023;
    float4 t;
    t.x = fmaxf(a.x + b.x + bias[n],   0.f);
    t.y = fmaxf(a.y + b.y + bias[n+1], 0.f);
    t.z = fmaxf(a.z + b.z + bias[n+2], 0.f);
    t.w = fmaxf(a.w + b.w + bias[n+3], 0.f);
    *reinterpret_cast<uint2*>(&oh[i]) = make_uint2(bpack(t.x, t.y), bpack(t.z, t.w));
    *reinterpret_cast<uint2*>(&ol[i]) =
        make_uint2(bpack(bres(t.x), bres(t.y)), bpack(bres(t.z), bres(t.w)));
}

// ---------------- param blocks ----------------
struct GemmP {
    const float* A; const float* Bw; const float* bias; float* C;
    int M, N, K, ldb;
    const float* img;
    const float* mf; float* sumP; float* sqP;
};
struct GemmB {
    const __nv_bfloat16 *Ah, *Al;
    const __nv_bfloat16 *Bh, *Bl;
    const float* bias; float* C;
    int M, N, K;
    const float* mf; float* sumP; float* sqP;
    __nv_bfloat16 *oh, *ol;
};

// ---------------- HMMA bf16x3 GEMM, TN in {32,64} (conv2, conv3, FC2) ----------------
template<int TN, int MODE, int EPI, int STAT, int IH, int IW, int IC>
__global__ void __launch_bounds__(256) k_hm2(GemmB p) {
    constexpr int TM = 128, BK = 64;
    constexpr int IM = (TN == 64) ? 2 : 1;
    constexpr int LIC = ilog2c(IC);
    constexpr int LTN = ilog2c(TN);
    constexpr int A_BYTES = TM * 128;
    constexpr int B_BYTES = TN * 128;
    constexpr int BUF = 2*A_BYTES + 2*B_BYTES;
    constexpr int BCH = TN * 8 / 256;
    constexpr int CST = TN + 1;

    extern __shared__ char sm[];
    const int tid = threadIdx.x;
    const int wid = tid >> 5, lid = tid & 31;
    const int wm = (TN == 64) ? (wid >> 1) : wid;
    const int wn = (TN == 64) ? (wid & 1) : 0;
    const int m0 = blockIdx.y * TM;
    const int n0 = blockIdx.x * TN;
    const uint32_t sbuf = smem_u32(sm);

    float acc[IM][4][4];
    #pragma unroll
    for (int i = 0; i < IM; i++)
        #pragma unroll
        for (int j = 0; j < 4; j++)
            #pragma unroll
            for (int q = 0; q < 4; q++) acc[i][j][q] = 0.f;

    const int row = tid >> 1;
    const int kt  = (tid & 1) * 32;
    int sbm = 0, sy = 0, sx = 0;
    if (MODE == 1) {
        int m = m0 + row;
        int b = m / (IH*IW);
        int r = m - b*(IH*IW);
        sy = r / IW;
        sx = r - sy*IW;
        sbm = b*IH*IW;
    }

    uint2 ahr[8], alr[8];
    uint4 bhr[BCH], blr[BCH];

    auto load_tile = [&](int k0) {
        #pragma unroll
        for (int j = 0; j < 8; j++) {
            int k = k0 + kt + j*4;
            uint2 vh = make_uint2(0u, 0u), vl = vh;
            if (k < p.K) {
                size_t idx;
                bool ok = true;
                if (MODE == 0) {
                    idx = (size_t)(m0 + row) * p.K + k;
                } else {
                    int t9 = k >> LIC;
                    int c0 = k & (IC-1);
                    int ky = t9 / 3, kx = t9 - 3*ky;
                    int yy = sy + ky - 1, xx = sx + kx - 1;
                    ok = (yy >= 0 && yy < IH && xx >= 0 && xx < IW);
                    idx = (size_t)(sbm + yy*IW + xx) * IC + c0;
                }
                if (ok) {
                    vh = *reinterpret_cast<const uint2*>(&p.Ah[idx]);
                    vl = *reinterpret_cast<const uint2*>(&p.Al[idx]);
                }
            }
            ahr[j] = vh; alr[j] = vl;
        }
        #pragma unroll
        for (int e = 0; e < BCH; e++) {
            int ge = tid + e*256;
            int n  = ge >> 3;
            int kc = ge & 7;
            int k  = k0 + kc*8;
            uint4 vh = make_uint4(0u,0u,0u,0u), vl = vh;
            if (k < p.K) {
                size_t idx = (size_t)(n0 + n) * p.K + k;
                vh = *reinterpret_cast<const uint4*>(&p.Bh[idx]);
                vl = *reinterpret_cast<const uint4*>(&p.Bl[idx]);
            }
            bhr[e] = vh; blr[e] = vl;
        }
    };

    auto store_tile = [&](int bb) {
        char* Ah = sm + bb;
        char* Al = Ah + A_BYTES;
        char* Bh = Ah + 2*A_BYTES;
        char* Bl = Bh + B_BYTES;
        #pragma unroll
        for (int j = 0; j < 8; j++) {
            uint32_t so = SWZ128((uint32_t)(row*128 + (kt + j*4)*2));
            *reinterpret_cast<uint2*>(Ah + so) = ahr[j];
            *reinterpret_cast<uint2*>(Al + so) = alr[j];
        }
        #pragma unroll
        for (int e = 0; e < BCH; e++) {
            int ge = tid + e*256;
            int n  = ge >> 3;
            int kc = ge & 7;
            uint32_t so = SWZ128((uint32_t)(n*128 + kc*16));
            *reinterpret_cast<uint4*>(Bh + so) = bhr[e];
            *reinterpret_cast<uint4*>(Bl + so) = blr[e];
        }
    };

    auto consume = [&](int bb) {
        uint32_t AH = sbuf + bb;
        uint32_t AL = AH + A_BYTES;
        uint32_t BH = AH + 2*A_BYTES;
        uint32_t BL = BH + B_BYTES;
        #pragma unroll
        for (int ks = 0; ks < 4; ks++) {
            uint32_t bh[2][4], bl[2][4];
            #pragma unroll
            for (int jp = 0; jp < 2; jp++) {
                int n_r = wn*32 + jp*16 + (lid & 7) + ((lid >> 4) << 3);
                int kb  = ks*32 + (((lid >> 3) & 1) << 4);
                uint32_t off = SWZ128((uint32_t)(n_r*128 + kb));
                LDSM_X4(bh[jp][0], bh[jp][1], bh[jp][2], bh[jp][3], BH + off);
                LDSM_X4(bl[jp][0], bl[jp][1], bl[jp][2], bl[jp][3], BL + off);
            }
            #pragma unroll
            for (int im = 0; im < IM; im++) {
                int row_a = wm*(16*IM) + im*16 + (lid & 15);
                int kb    = ks*32 + (lid >> 4) * 16;
                uint32_t off = SWZ128((uint32_t)(row_a*128 + kb));
                uint32_t ah[4], al[4];
                LDSM_X4(ah[0], ah[1], ah[2], ah[3], AH + off);
                LDSM_X4(al[0], al[1], al[2], al[3], AL + off);
                #pragma unroll
                for (int jn = 0; jn < 4; jn++) {
                    int jp = jn >> 1, s = (jn & 1) * 2;
                    MMA_BF16(acc[im][jn], ah[0], ah[1], ah[2], ah[3], bh[jp][s], bh[jp][s+1]);
                    MMA_BF16(acc[im][jn], ah[0], ah[1], ah[2], ah[3], bl[jp][s], bl[jp][s+1]);
                    MMA_BF16(acc[im][jn], al[0], al[1], al[2], al[3], bh[jp][s], bh[jp][s+1]);
                }
            }
        }
    };

    const int T = (p.K + BK - 1) / BK;
    load_tile(0);
    store_tile(0);
    __syncthreads();

    for (int t = 0; t < T; t++) {
        if (t + 1 < T) load_tile((t + 1) * BK);
        consume((t & 1) * BUF);
        if (t + 1 < T) store_tile(((t + 1) & 1) * BUF);
        __syncthreads();
    }

    float* cs   = reinterpret_cast<float*>(sm);
    float* mrow = cs + TM*CST;
    float* rs   = mrow + TM;
    float* rq   = rs + 256;
    #pragma unroll
    for (int im = 0; im < IM; im++) {
        int r0 = wm*(16*IM) + im*16 + (lid >> 2);
        #pragma unroll
        for (int jn = 0; jn < 4; jn++) {
            int c = wn*32 + jn*8 + (lid & 3)*2;
            cs[r0*CST + c]       = acc[im][jn][0];
            cs[r0*CST + c + 1]   = acc[im][jn][1];
            cs[(r0+8)*CST + c]   = acc[im][jn][2];
            cs[(r0+8)*CST + c+1] = acc[im][jn][3];
        }
    }
    if (STAT && tid < TM) mrow[tid] = p.mf[m0 + tid];
    __syncthreads();

    float lsum = 0.f, lsq = 0.f;
    for (int e = tid; e < TM*TN; e += 256) {
        int rr = e >> LTN;
        int cc = e & (TN-1);
        int n  = n0 + cc;
        float v = cs[rr*CST + cc];
        if (STAT) {
            float mk = mrow[rr];
            float xv = (mk > 0.f) ? v : 0.f;
            lsum += xv; lsq += xv*xv;
        }
        if (n < p.N) {
            if (EPI == 1 || EPI == 2 || EPI == 3) {
                int nnb = (EPI == 3 && n >= 256) ? n + 256 : n;
                v += p.bias[nnb];
                if (EPI == 2) v = fmaxf(v, 0.f);
                p.C[(size_t)(m0 + rr) * p.N + n] = v;
            } else if (EPI == 4) {
                v = fmaxf(v + p.bias[n], 0.f);
                __nv_bfloat16 h = __float2bfloat16(v);
                p.oh[(size_t)(m0 + rr) * p.N + n] = h;
                p.ol[(size_t)(m0 + rr) * p.N + n] = __float2bfloat16(v - __bfloat162float(h));
            } else {
                p.C[(size_t)(m0 + rr) * p.N + n] = v;
            }
        }
    }
    if (STAT) {
        rs[tid] = lsum; rq[tid] = lsq;
        __syncthreads();
        if (tid < TN) {
            float s = 0.f, q = 0.f;
            #pragma unroll
            for (int g = 0; g < 256/TN; g++) { s += rs[tid + g*TN]; q += rq[tid + g*TN]; }
            if (n0 + tid < p.N) {
                atomicAdd(&p.sumP[n0 + tid], s);
                atomicAdd(&p.sqP[n0 + tid], q);
            }
        }
    }
}

// ---------------- HMMA bf16x3 GEMM, TM=128 x TN=128, BK=32 (conv4, gate, FC1) ----------
// MODE 0: dense. MODE 1: im2col. MODE 2: gate mode — rows m = r*2048 + b (tile-uniform
// spatial position), invalid taps skipped entirely.  SPLIT=1: blockIdx.z K-half partials.
template<int MODE, int EPI, int STAT, int SPLIT, int IH, int IW, int IC>
__global__ void __launch_bounds__(256, 2) k_hm3(GemmB p) {
    constexpr int TM = 128, TN = 128, BK = 32;
    constexpr int LIC = ilog2c(IC);
    constexpr int A_BYTES = TM * 128;
    constexpr int B_BYTES = TN * 128;
    constexpr int STAGE = A_BYTES + B_BYTES;

    extern __shared__ char sm[];
    const int tid = threadIdx.x;
    const int wid = tid >> 5, lid = tid & 31;
    const int wm = wid >> 2;
    const int wn = wid & 3;
    const int m0 = blockIdx.y * TM;
    const int n0 = blockIdx.x * TN;
    const int koff = SPLIT ? (int)blockIdx.z * (p.K >> 1) : 0;
    const int KT   = SPLIT ? (p.K >> 1) : p.K;
    float* Cw = SPLIT ? p.C + (size_t)blockIdx.z * ((size_t)p.M * p.N) : p.C;
    const uint32_t sbuf = smem_u32(sm);

    float acc[4][4][4];
    #pragma unroll
    for (int i = 0; i < 4; i++)
        #pragma unroll
        for (int j = 0; j < 4; j++)
            #pragma unroll
            for (int q = 0; q < 4; q++) acc[i][j][q] = 0.f;

    const int row  = tid >> 1;
    const int half = tid & 1;
    int sbm = 0, sy = 0, sx = 0, vmask = 0;
    if (MODE == 1) {
        int m = m0 + row;
        int b = m / (IH*IW);
        int r = m - b*(IH*IW);
        sy = r / IW;
        sx = r - sy*IW;
        sbm = b*IH*IW;
    } else if (MODE == 2) {
        int rt = m0 >> 11;            // tile-uniform spatial position
        sy = rt / IW;
        sx = rt - sy*IW;
        sbm = ((m0 & 2047) + row) * (IH*IW);
        #pragma unroll
        for (int t = 0; t < 9; t++) {
            int dy = t/3, dx = t - 3*(t/3);
            int yy = sy + dy - 1, xx = sx + dx - 1;
            if (yy >= 0 && yy < IH && xx >= 0 && xx < IW) vmask |= 1 << t;
        }
    }

    uint4 ar[4], br[4];

    auto load_tile = [&](int k0) {
        {
            const __nv_bfloat16* src = half ? p.Al : p.Ah;
            bool ok = true;
            size_t idx = 0;
            if (MODE == 0) {
                idx = (size_t)(m0 + row) * p.K + koff + k0;
            } else if (MODE == 1) {
                int t9 = k0 >> LIC;
                int c0 = k0 & (IC-1);
                int ky = t9 / 3, kx = t9 - 3*ky;
                int yy = sy + ky - 1, xx = sx + kx - 1;
                ok = (yy >= 0 && yy < IH && xx >= 0 && xx < IW);
                idx = (size_t)(sbm + yy*IW + xx) * IC + c0;
            } else {
                int t9 = k0 >> LIC;               // valid by construction
                int ky = t9 / 3, kx = t9 - 3*ky;
                idx = (size_t)(sbm + (sy + ky - 1)*IW + (sx + kx - 1)) * IC + (k0 & (IC-1));
            }
            if (ok) {
                const uint4* s4 = reinterpret_cast<const uint4*>(&src[idx]);
                #pragma unroll
                for (int j = 0; j < 4; j++) ar[j] = s4[j];
            } else {
                #pragma unroll
                for (int j = 0; j < 4; j++) ar[j] = make_uint4(0u,0u,0u,0u);
            }
        }
        {
            const __nv_bfloat16* src = half ? p.Bl : p.Bh;
            const uint4* s4 = reinterpret_cast<const uint4*>(&src[(size_t)(n0 + row) * p.K + koff + k0]);
            #pragma unroll
            for (int j = 0; j < 4; j++) br[j] = s4[j];
        }
    };

    auto store_tile = [&](int bb) {
        char* Ab = sm + bb;
        char* Bb = Ab + A_BYTES;
        #pragma unroll
        for (int j = 0; j < 4; j++) {
            uint32_t so = SWZ128((uint32_t)(row*128 + half*64 + j*16));
            *reinterpret_cast<uint4*>(Ab + so) = ar[j];
            *reinterpret_cast<uint4*>(Bb + so) = br[j];
        }
    };

    auto consume = [&](int bb) {
        uint32_t Abase = sbuf + bb;
        uint32_t Bbase = Abase + A_BYTES;
        #pragma unroll
        for (int ks = 0; ks < 2; ks++) {
            uint32_t bh[2][4], bl[2][4];
            #pragma unroll
            for (int jp = 0; jp < 2; jp++) {
                int n_r = wn*32 + jp*16 + (lid & 7) + ((lid >> 4) << 3);
                int kb  = ks*32 + (((lid >> 3) & 1) << 4);
                LDSM_X4(bh[jp][0], bh[jp][1], bh[jp][2], bh[jp][3],
                        Bbase + SWZ128((uint32_t)(n_r*128 + kb)));
                LDSM_X4(bl[jp][0], bl[jp][1], bl[jp][2], bl[jp][3],
                        Bbase + SWZ128((uint32_t)(n_r*128 + 64 + kb)));
            }
            #pragma unroll
            for (int im = 0; im < 4; im++) {
                int row_a = wm*64 + im*16 + (lid & 15);
                int kb    = ks*32 + ((lid >> 4) << 4);
                uint32_t ah[4], al[4];
                LDSM_X4(ah[0], ah[1], ah[2], ah[3],
                        Abase + SWZ128((uint32_t)(row_a*128 + kb)));
                LDSM_X4(al[0], al[1], al[2], al[3],
                        Abase + SWZ128((uint32_t)(row_a*128 + 64 + kb)));
                #pragma unroll
                for (int jn = 0; jn < 4; jn++) {
                    int jp = jn >> 1, s = (jn & 1) * 2;
                    MMA_BF16(acc[im][jn], ah[0], ah[1], ah[2], ah[3], bh[jp][s], bh[jp][s+1]);
                    MMA_BF16(acc[im][jn], ah[0], ah[1], ah[2], ah[3], bl[jp][s], bl[jp][s+1]);
                    MMA_BF16(acc[im][jn], al[0], al[1], al[2], al[3], bh[jp][s], bh[jp][s+1]);
                }
            }
        }
    };

    if (MODE == 2) {
        // skip-list traversal over valid taps only
        auto next_k0 = [&](int k0) {
            k0 += BK;
            while (k0 < KT && !((vmask >> (k0 >> LIC)) & 1))
                k0 = (((k0 >> LIC) + 1) << LIC);
            return k0;
        };
        int k0 = 0;
        while (!((vmask >> (k0 >> LIC)) & 1)) k0 += (1 << LIC);
        load_tile(k0);
        store_tile(0);
        __syncthreads();
        int buf = 0;
        while (k0 < KT) {
            int kn = next_k0(k0);
            if (kn < KT) load_tile(kn);
            consume(buf * STAGE);
            if (kn < KT) store_tile((buf ^ 1) * STAGE);
            __syncthreads();
            buf ^= 1;
            k0 = kn;
        }
    } else {
        const int T = KT / BK;
        load_tile(0);
        store_tile(0);
        __syncthreads();
        for (int t = 0; t < T; t++) {
            if (t + 1 < T) load_tile((t + 1) * BK);
            consume((t & 1) * STAGE);
            if (t + 1 < T) store_tile(((t + 1) & 1) * STAGE);
            __syncthreads();
        }
    }

    constexpr int CST = 130;
    float* cs   = reinterpret_cast<float*>(sm);
    float* mrow = cs + 64*CST;
    float* rs   = mrow + 128;
    float* rq   = rs + 256;
    if (STAT && tid < 128) mrow[tid] = p.mf[m0 + tid];
    float lsum = 0.f, lsq = 0.f;

    #pragma unroll
    for (int h = 0; h < 2; h++) {
        if (wm == h) {
            #pragma unroll
            for (int im = 0; im < 4; im++) {
                int r0 = im*16 + (lid >> 2);
                #pragma unroll
                for (int jn = 0; jn < 4; jn++) {
                    int c = wn*32 + jn*8 + (lid & 3)*2;
                    cs[r0*CST + c]       = acc[im][jn][0];
                    cs[r0*CST + c + 1]   = acc[im][jn][1];
                    cs[(r0+8)*CST + c]   = acc[im][jn][2];
                    cs[(r0+8)*CST + c+1] = acc[im][jn][3];
                }
            }
        }
        __syncthreads();
        for (int e = tid; e < 64*128; e += 256) {
            int rr = e >> 7;
            int cc = e & 127;
            int n  = n0 + cc;
            float v = cs[rr*CST + cc];
            if (STAT) {
                float mk = mrow[h*64 + rr];
                float xv = (mk > 0.f) ? v : 0.f;
                lsum += xv; lsq += xv*xv;
            }
            if (n < p.N) {
                if (SPLIT) {
                    Cw[(size_t)(m0 + h*64 + rr) * p.N + n] = v;
                } else if (EPI == 1 || EPI == 2 || EPI == 3) {
                    int nnb = (EPI == 3 && n >= 256) ? n + 256 : n;
                    v += p.bias[nnb];
                    if (EPI == 2) v = fmaxf(v, 0.f);
                    Cw[(size_t)(m0 + h*64 + rr) * p.N + n] = v;
                } else if (EPI == 4) {
                    v = fmaxf(v + p.bias[n], 0.f);
                    __nv_bfloat16 hb = __float2bfloat16(v);
                    p.oh[(size_t)(m0 + h*64 + rr) * p.N + n] = hb;
                    p.ol[(size_t)(m0 + h*64 + rr) * p.N + n] = __float2bfloat16(v - __bfloat162float(hb));
                } else {
                    Cw[(size_t)(m0 + h*64 + rr) * p.N + n] = v;
                }
            }
        }
        __syncthreads();
    }
    if (STAT) {
        rs[tid] = lsum; rq[tid] = lsq;
        __syncthreads();
        if (tid < 128) {
            float s = rs[tid] + rs[tid + 128];
            float q = rq[tid] + rq[tid + 128];
            if (n0 + tid < p.N) {
                atomicAdd(&p.sumP[n0 + tid], s);
                atomicAdd(&p.sqP[n0 + tid], q);
            }
        }
    }
}

// ---------------- packed-f32x2 GEMM (conv1 only), fused stats ----------------
template<int TN, int MODE, int EPI, int STAT, int IH, int IW, int IC>
__global__ void __launch_bounds__(256) k_gemm3(GemmP p) {
    constexpr int TM = 128, BK = 16;
    constexpr int TX = (TN == 32) ? 8 : 16;
    constexpr int NR = TN / TX;
    constexpr int TY = 256 / TX;
    constexpr int MR = TM / TY;
    constexpr int MP = MR / 2;
    constexpr int LIC = ilog2c(IC);
    constexpr int LTN = ilog2c(TN);
    constexpr int B_EPT = (BK * TN) / 256;

    __shared__ float  As[2][BK][TM];
    __shared__ float2 Bs[2][BK][TN];
    __shared__ float mrow[TM];
    __shared__ float sred[TN], qred[TN];

    const int tid = threadIdx.x;
    const int tx = tid % TX, ty = tid / TX;
    const int m0 = blockIdx.y * TM;
    const int n0 = blockIdx.x * TN;

    unsigned long long acc[MP][NR];
    #pragma unroll
    for (int i = 0; i < MP; i++)
        #pragma unroll
        for (int j = 0; j < NR; j++) acc[i][j] = 0ULL;

    int pm_b[2], pm_y[2], pm_x[2];
    if (MODE == 1) {
        #pragma unroll
        for (int i = 0; i < 2; i++) {
            int m = m0 + ((tid + i*256) >> 2);
            int b = m / (IH*IW);
            int r = m - b*(IH*IW);
            int y = r / IW;
            pm_b[i] = b*IH*IW;
            pm_y[i] = y;
            pm_x[i] = r - y*IW;
        }
    }

    float a_reg[8];
    float b_reg[B_EPT];

    auto load_tile = [&](int k0) {
        if (MODE == 1) {
            #pragma unroll
            for (int i = 0; i < 2; i++) {
                int gq = tid + i*256;
                int kbase = k0 + (gq & 3)*4;
                #pragma unroll
                for (int j = 0; j < 4; j++) {
                    int k = kbase + j;
                    float v = 0.f;
                    if (k < p.K) {
                        int c  = k & (IC-1);
                        int t9 = k >> LIC;
                        int ky = t9 / 3, kx = t9 - 3*ky;
                        int yy = pm_y[i] + ky - 1, xx = pm_x[i] + kx - 1;
                        if (yy >= 0 && yy < IH && xx >= 0 && xx < IW)
                            v = p.img[(size_t)(pm_b[i] + yy*IW + xx) * IC + c];
                    }
                    a_reg[i*4+j] = v;
                }
            }
        } else {
            #pragma unroll
            for (int i = 0; i < 2; i++) {
                int gq = tid + i*256;
                int m = m0 + (gq >> 2);
                int k = k0 + (gq & 3) * 4;
                float4 t = *reinterpret_cast<const float4*>(&p.A[(size_t)m * p.K + k]);
                a_reg[i*4+0] = t.x; a_reg[i*4+1] = t.y;
                a_reg[i*4+2] = t.z; a_reg[i*4+3] = t.w;
            }
        }
        #pragma unroll
        for (int e = 0; e < B_EPT; e++) {
            int ge = tid + e*256;
            int kl = ge >> LTN;
            int n  = ge & (TN-1);
            int k  = k0 + kl;
            int nn = n0 + n;
            float v = 0.f;
            if (k < p.K && nn < p.N) v = p.Bw[(size_t)k * p.ldb + nn];
            b_reg[e] = v;
        }
    };

    auto store_tile = [&](int buf) {
        #pragma unroll
        for (int i = 0; i < 2; i++) {
            int gq = tid + i*256;
            int ml = gq >> 2;
            int kq = (gq & 3) * 4;
            #pragma unroll
            for (int j = 0; j < 4; j++) As[buf][kq+j][ml] = a_reg[i*4+j];
        }
        #pragma unroll
        for (int e = 0; e < B_EPT; e++) {
            int ge = tid + e*256;
            int kl = ge >> LTN;
            int n  = ge & (TN-1);
            Bs[buf][kl][n] = make_float2(b_reg[e], b_reg[e]);
        }
    };

    const int nTiles = (p.K + BK - 1) / BK;
    load_tile(0);
    store_tile(0);
    __syncthreads();

    for (int t = 0; t < nTiles; t++) {
        int cur = t & 1;
        if (t + 1 < nTiles) load_tile((t + 1) * BK);
        #pragma unroll
        for (int kk = 0; kk < BK; kk++) {
            unsigned long long af[MP], bf[NR];
            const ulonglong2* ap = reinterpret_cast<const ulonglong2*>(&As[cur][kk][ty*MR]);
            #pragma unroll
            for (int i = 0; i < MP/2; i++) { ulonglong2 v = ap[i]; af[2*i] = v.x; af[2*i+1] = v.y; }
            const unsigned long long* bp = reinterpret_cast<const unsigned long long*>(&Bs[cur][kk][0]);
            #pragma unroll
            for (int nr = 0; nr < NR; nr++) bf[nr] = bp[tx + nr*TX];
            #pragma unroll
            for (int mp = 0; mp < MP; mp++)
                #pragma unroll
                for (int nr = 0; nr < NR; nr++)
                    FMA2(acc[mp][nr], af[mp], bf[nr]);
        }
        if (t + 1 < nTiles) store_tile(cur ^ 1);
        __syncthreads();
    }

    if (STAT) {
        if (tid < TN) { sred[tid] = 0.f; qred[tid] = 0.f; }
        if (tid < TM) mrow[tid] = p.mf[m0 + tid];
        __syncthreads();
    }

    #pragma unroll
    for (int mp = 0; mp < MP; mp++) {
        int m = m0 + ty*MR + 2*mp;
        #pragma unroll
        for (int nr = 0; nr < NR; nr++) {
            int n = n0 + tx + nr*TX;
            if (n >= p.N) continue;
            float lo = __uint_as_float((unsigned)(acc[mp][nr] & 0xFFFFFFFFULL));
            float hi = __uint_as_float((unsigned)(acc[mp][nr] >> 32));
            if (STAT) {
                float mk0 = mrow[ty*MR + 2*mp], mk1 = mrow[ty*MR + 2*mp + 1];
                float x0 = (mk0 > 0.f) ? lo : 0.f;
                float x1 = (mk1 > 0.f) ? hi : 0.f;
                atomicAdd(&sred[n - n0], x0 + x1);
                atomicAdd(&qred[n - n0], x0*x0 + x1*x1);
            }
            if (EPI >= 1) { float bb = p.bias[n]; lo += bb; hi += bb; }
            if (EPI == 2) { lo = fmaxf(lo, 0.f); hi = fmaxf(hi, 0.f); }
            p.C[(size_t)m       * p.N + n] = lo;
            p.C[(size_t)(m + 1) * p.N + n] = hi;
        }
    }
    if (STAT) {
        __syncthreads();
        if (tid < TN && n0 + tid < p.N) {
            atomicAdd(&p.sumP[n0 + tid], sred[tid]);
            atomicAdd(&p.sqP[n0 + tid], qred[tid]);
        }
    }
}

// ---------------- launcher ----------------
static inline int ceil_div(int a, int b) { return (a + b - 1) / b; }
#define HM_SMEM64 (2 * (2*128*128 + 2*64*128))   // 96 KB
#define HM_SMEM32 (2 * (2*128*128 + 2*32*128))   // 80 KB
#define HM3_SMEM  (2 * (128*128 + 128*128))      // 64 KB

extern "C" void kernel_launch(void* const* d_in, const int* in_sizes, int n_in,
                              void* d_out, int out_size) {
    const float* x    = (const float*)d_in[0];
    const int*   mask = (const int*)  d_in[1];
    const float* W1 = (const float*)d_in[2];  const float* ga1 = (const float*)d_in[3];  const float* be1 = (const float*)d_in[4];
    const float* W2 = (const float*)d_in[5];  const float* ga2 = (const float*)d_in[6];  const float* be2 = (const float*)d_in[7];
    const float* W3 = (const float*)d_in[8];  const float* ga3 = (const float*)d_in[9];  const float* be3 = (const float*)d_in[10];
    const float* W4 = (const float*)d_in[11]; const float* ga4 = (const float*)d_in[12]; const float* be4 = (const float*)d_in[13];
    const float* Wl = (const float*)d_in[14]; const float* bl  = (const float*)d_in[15];
    const float* lw1 = (const float*)d_in[16]; const float* lb1 = (const float*)d_in[17];
    const float* lw2 = (const float*)d_in[18]; const float* lb2 = (const float*)d_in[19];
    float* out = (float*)d_out;

    float *xm, *m1, *h1, *h2, *m2, *h3, *h4, *m3, *gates, *y1f, *st;
    __nv_bfloat16 *h1h, *h1l, *p1h, *p1l, *h3h, *h3l, *p2h, *p2l, *fh, *fl, *y1h, *y1l;
    __nv_bfloat16 *w2h, *w2l, *w3h, *w3l, *w4h, *w4l, *wlh, *wll, *l1h, *l1l, *l2h, *l2l;
    cudaGetSymbolAddress((void**)&xm,  g_xm);   cudaGetSymbolAddress((void**)&m1,  g_m1);
    cudaGetSymbolAddress((void**)&h1,  g_h1);   cudaGetSymbolAddress((void**)&h2,  g_h2);
    cudaGetSymbolAddress((void**)&m2,  g_m2);   cudaGetSymbolAddress((void**)&h3,  g_h3);
    cudaGetSymbolAddress((void**)&h4,  g_h4);   cudaGetSymbolAddress((void**)&m3,  g_m3);
    cudaGetSymbolAddress((void**)&gates, g_gates);
    cudaGetSymbolAddress((void**)&y1f, g_y1f);  cudaGetSymbolAddress((void**)&st,  g_stats);
    cudaGetSymbolAddress((void**)&h1h, g_h1h);  cudaGetSymbolAddress((void**)&h1l, g_h1l);
    cudaGetSymbolAddress((void**)&p1h, g_p1h);  cudaGetSymbolAddress((void**)&p1l, g_p1l);
    cudaGetSymbolAddress((void**)&h3h, g_h3h);  cudaGetSymbolAddress((void**)&h3l, g_h3l);
    cudaGetSymbolAddress((void**)&p2h, g_p2h);  cudaGetSymbolAddress((void**)&p2l, g_p2l);
    cudaGetSymbolAddress((void**)&fh,  g_flath);cudaGetSymbolAddress((void**)&fl,  g_flatl);
    cudaGetSymbolAddress((void**)&y1h, g_y1h);  cudaGetSymbolAddress((void**)&y1l, g_y1l);
    cudaGetSymbolAddress((void**)&w2h, g_w2h);  cudaGetSymbolAddress((void**)&w2l, g_w2l);
    cudaGetSymbolAddress((void**)&w3h, g_w3h);  cudaGetSymbolAddress((void**)&w3l, g_w3l);
    cudaGetSymbolAddress((void**)&w4h, g_w4h);  cudaGetSymbolAddress((void**)&w4l, g_w4l);
    cudaGetSymbolAddress((void**)&wlh, g_wlh);  cudaGetSymbolAddress((void**)&wll, g_wll);
    cudaGetSymbolAddress((void**)&l1h, g_l1h);  cudaGetSymbolAddress((void**)&l1l, g_l1l);
    cudaGetSymbolAddress((void**)&l2h, g_l2h);  cudaGetSymbolAddress((void**)&l2l, g_l2l);

    float *sum1 = st+0,   *sq1 = st+16;
    float *sum2 = st+32,  *sq2 = st+64;
    float *sum3 = st+128, *sq3 = st+192;
    float *sum4 = st+256, *sq4 = st+384;
    float *n1 = st+512, *n2 = st+513;

    cudaFuncSetAttribute(k_hm2<32,1,0,1,H1_,W1_,16>,  cudaFuncAttributeMaxDynamicSharedMemorySize, HM_SMEM32);
    cudaFuncSetAttribute(k_hm2<64,1,0,1,H2_,W2_,32>,  cudaFuncAttributeMaxDynamicSharedMemorySize, HM_SMEM64);
    cudaFuncSetAttribute(k_hm2<64,0,1,0,1,1,16>,      cudaFuncAttributeMaxDynamicSharedMemorySize, HM_SMEM64);
    cudaFuncSetAttribute(k_hm3<1,0,1,0,H2_,W2_,64>,   cudaFuncAttributeMaxDynamicSharedMemorySize, HM3_SMEM);
    cudaFuncSetAttribute(k_hm3<2,3,0,0,H3_,W3_,128>,  cudaFuncAttributeMaxDynamicSharedMemorySize, HM3_SMEM);
    cudaFuncSetAttribute(k_hm3<0,0,0,1,1,1,32>,       cudaFuncAttributeMaxDynamicSharedMemorySize, HM3_SMEM);

    // weight transpose+split
    { dim3 b(32,32);
      k_wt<0><<<dim3(ceil_div(144,32),  1),  b>>>(W2,  w2h, w2l, 144,  32,   32);
      k_wt<0><<<dim3(ceil_div(288,32),  2),  b>>>(W3,  w3h, w3l, 288,  64,   64);
      k_wt<0><<<dim3(ceil_div(576,32),  4),  b>>>(W4,  w4h, w4l, 576,  128,  128);
      k_wt<1><<<dim3(ceil_div(1152,32), 24), b>>>(Wl,  wlh, wll, 1152, 768,  1024);
      k_wt<0><<<dim3(ceil_div(8960,32), 32), b>>>(lw1, l1h, l1l, 8960, 1024, 1024);
      k_wt<0><<<dim3(ceil_div(1024,32), 14), b>>>(lw2, l2h, l2l, 1024, 420,  420);
    }

    k_zero_stats<<<1, 1024>>>(st);
    k_prep<<<ceil_div(S1, 256), 256>>>(x, mask, xm, m1, n1);

    // conv1: 2->16 (K=18) — FFMA2 + fused stats
    { GemmP p = { nullptr, W1, nullptr, h1, S1, 16, 18, 16, xm, m1, sum1, sq1 };
      k_gemm3<32,1,0,1,H1_,W1_,2><<<dim3(1, S1/128), 256>>>(p); }
    k_apply3<4><<<ceil_div(S1*16/4, 256), 256>>>(h1, m1, S1, sum1, sq1, n1, ga1, be1, h1h, h1l);

    // conv2: 16->32 (K=144) — HMMA TN=32 + fused stats
    { GemmB p = { h1h, h1l, w2h, w2l, nullptr, h2, S1, 32, 144, m1, sum2, sq2, nullptr, nullptr };
      k_hm2<32,1,0,1,H1_,W1_,16><<<dim3(1, S1/128), 256, HM_SMEM32>>>(p); }

    // pool1 + BN2 fused -> bf16, count n2
    k_poolbn<5><<<ceil_div(S2*32, 256), 256>>>(h2, m1, sum2, sq2, n1, ga2, be2,
                                               p1h, p1l, m2, H1_, W1_, H2_, W2_, n2);

    // conv3: 32->64 (K=288) — HMMA TN=64 + fused stats
    { GemmB p = { p1h, p1l, w3h, w3l, nullptr, h3, S2, 64, 288, m2, sum3, sq3, nullptr, nullptr };
      k_hm2<64,1,0,1,H2_,W2_,32><<<dim3(1, S2/128), 256, HM_SMEM64>>>(p); }
    k_apply3<6><<<ceil_div(S2*64/4, 256), 256>>>(h3, m2, S2, sum3, sq3, n2, ga3, be3, h3h, h3l);

    // conv4: 64->128 (K=576) — HMMA TN=128 + fused stats
    { GemmB p = { h3h, h3l, w4h, w4l, nullptr, h4, S2, 128, 576, m2, sum4, sq4, nullptr, nullptr };
      k_hm3<1,0,1,0,H2_,W2_,64><<<dim3(1, S2/128), 256, HM3_SMEM>>>(p); }

    // pool2 + BN4 fused -> bf16
    k_poolbn<7><<<ceil_div(S3*128, 256), 256>>>(h4, m2, sum4, sq4, n2, ga4, be4,
                                                p2h, p2l, m3, H2_, W2_, H3_, W3_, nullptr);

    // gate conv: 128->768 (f skipped; remap in k_wt) + bias (K=1152) — HMMA TN=128
    // gate mode: rows m = r*2048 + b, tile-uniform taps, invalid taps skipped
    { GemmB p = { p2h, p2l, wlh, wll, bl, gates, S3, 768, 1152, nullptr, nullptr, nullptr, nullptr, nullptr };
      k_hm3<2,3,0,0,H3_,W3_,128><<<dim3(6, S3/128), 256, HM3_SMEM>>>(p); }

    // LSTM nonlinearity (gate rows r*2048+b) -> flat bf16 hi/lo in (C,H,W) order
    k_lstm<<<ceil_div(S3*256, 256), 256>>>(gates, m3, fh, fl);

    // FC1: [2048,8960]x[8960,1024] — HMMA TN=128, split-K=2 -> fp32 partials
    { GemmB p = { fh, fl, l1h, l1l, nullptr, y1f, B_, 1024, 8960, nullptr, nullptr, nullptr, nullptr, nullptr };
      k_hm3<0,0,0,1,1,1,32><<<dim3(8, B_/128, 2), 256, HM3_SMEM>>>(p); }
    k_fin<<<ceil_div(B_*1024/4, 256), 256>>>(y1f, lb1, y1h, y1l);

    // FC2: [2048,1024]x[1024,420] + bias -> out — HMMA TN=64
    { GemmB p = { y1h, y1l, l2h, l2l, lb2, out, B_, 420, 1024, nullptr, nullptr, nullptr, nullptr, nullptr };
      k_hm2<64,0,1,0,1,1,16><<<dim3(7, B_/128), 256, HM_SMEM64>>>(p); }
}

// round 16
// speedup vs baseline: 1.6131x; 1.0285x over previous
#include <cuda_runtime.h>
#include <cuda_bf16.h>
#include <math.h>
#include <stdint.h>

#define EPS 1e-4f

#define B_  2048
#define H1_ 23
#define W1_ 31
#define H2_ 11
#define W2_ 15
#define H3_ 5
#define W3_ 7

#define S1 (B_*H1_*W1_)
#define S2 (B_*H2_*W2_)
#define S3 (B_*H3_*W3_)

// ---------------- scratch ----------------
__device__ __align__(16) float g_xm[S1*2];
__device__ __align__(16) float g_m1[S1];
__device__ __align__(16) float g_h1[S1*16];
__device__ __align__(16) __nv_bfloat16 g_h1h[S1*16];
__device__ __align__(16) __nv_bfloat16 g_h1l[S1*16];
__device__ __align__(16) float g_h2[S1*32];
__device__ __align__(16) __nv_bfloat16 g_p1h[S2*32];
__device__ __align__(16) __nv_bfloat16 g_p1l[S2*32];
__device__ __align__(16) float g_m2[S2];
__device__ __align__(16) float g_h3[S2*64];
__device__ __align__(16) __nv_bfloat16 g_h3h[S2*64];
__device__ __align__(16) __nv_bfloat16 g_h3l[S2*64];
__device__ __align__(16) float g_h4[S2*128];
__device__ __align__(16) __nv_bfloat16 g_p2h[S3*128];
__device__ __align__(16) __nv_bfloat16 g_p2l[S3*128];
__device__ __align__(16) float g_m3[S3];
__device__ __align__(16) float g_gates[S3*768];   // rows ordered m = r*2048 + b
__device__ __align__(16) __nv_bfloat16 g_flath[B_*8960];
__device__ __align__(16) __nv_bfloat16 g_flatl[B_*8960];
__device__ __align__(16) float g_y1f[2*B_*1024];
__device__ __align__(16) __nv_bfloat16 g_y1h[B_*1024];
__device__ __align__(16) __nv_bfloat16 g_y1l[B_*1024];
__device__ __align__(16) float g_stats[544];
// transposed bf16 weights [n][k]
__device__ __align__(16) __nv_bfloat16 g_w2h[32*144],   g_w2l[32*144];
__device__ __align__(16) __nv_bfloat16 g_w3h[64*288],   g_w3l[64*288];
__device__ __align__(16) __nv_bfloat16 g_w4h[128*576],  g_w4l[128*576];
__device__ __align__(16) __nv_bfloat16 g_wlh[768*1152], g_wll[768*1152];
__device__ __align__(16) __nv_bfloat16 g_l1h[1024*8960],g_l1l[1024*8960];
__device__ __align__(16) __nv_bfloat16 g_l2h[448*1024], g_l2l[448*1024];

__host__ __device__ constexpr int ilog2c(int x) { return x <= 1 ? 0 : 1 + ilog2c(x >> 1); }

#define FMA2(d, a, b) asm("fma.rn.f32x2 %0, %1, %2, %0;" : "+l"(d) : "l"(a), "l"(b))
#define SWZ128(x) ((x) ^ (((x) >> 3) & 0x70))

__device__ __forceinline__ uint32_t smem_u32(const void* p) {
    uint32_t a;
    asm("{ .reg .u64 t; cvta.to.shared.u64 t, %1; cvt.u32.u64 %0, t; }" : "=r"(a) : "l"(p));
    return a;
}

#define LDSM_X4(r0, r1, r2, r3, addr) \
    asm volatile("ldmatrix.sync.aligned.m8n8.x4.shared.b16 {%0,%1,%2,%3}, [%4];" \
        : "=r"(r0), "=r"(r1), "=r"(r2), "=r"(r3) : "r"(addr))

#define MMA_BF16(d, a0, a1, a2, a3, b0, b1) \
    asm volatile("mma.sync.aligned.m16n8k16.row.col.f32.bf16.bf16.f32 " \
        "{%0,%1,%2,%3}, {%4,%5,%6,%7}, {%8,%9}, {%0,%1,%2,%3};" \
        : "+f"((d)[0]), "+f"((d)[1]), "+f"((d)[2]), "+f"((d)[3]) \
        : "r"(a0), "r"(a1), "r"(a2), "r"(a3), "r"(b0), "r"(b1))

#define CP16(dst, src, bytes) \
    asm volatile("cp.async.cg.shared.global [%0], [%1], 16, %2;" \
        :: "r"(dst), "l"(src), "r"(bytes) : "memory")
#define CP_COMMIT() asm volatile("cp.async.commit_group;" ::: "memory")
#define CP_WAIT1()  asm volatile("cp.async.wait_group 1;" ::: "memory")
#define CP_WAIT0()  asm volatile("cp.async.wait_group 0;" ::: "memory")

__device__ __forceinline__ uint32_t bpack(float a, float b) {
    __nv_bfloat162 t;
    t.x = __float2bfloat16(a);
    t.y = __float2bfloat16(b);
    return *reinterpret_cast<uint32_t*>(&t);
}
__device__ __forceinline__ float bres(float x) {
    return x - __bfloat162float(__float2bfloat16(x));
}

// ---------------- small kernels ----------------
__global__ void k_zero_stats(float* st) {
    if (threadIdx.x < 544) st[threadIdx.x] = 0.f;
}

__global__ void k_prep(const float* __restrict__ x, const int* __restrict__ mask,
                       float* __restrict__ xm, float* __restrict__ m1, float* nP) {
    int s = blockIdx.x * blockDim.x + threadIdx.x;
    int act = 0;
    if (s < S1) {
        float m = (float)mask[s];
        m1[s] = m;
        xm[2*s]   = x[2*s]   * m;
        xm[2*s+1] = x[2*s+1] * m;
        act = (m > 0.f);
    }
    __shared__ int sh[256];
    sh[threadIdx.x] = act; __syncthreads();
    for (int o = 128; o > 0; o >>= 1) { if (threadIdx.x < o) sh[threadIdx.x] += sh[threadIdx.x+o]; __syncthreads(); }
    if (threadIdx.x == 0 && sh[0]) atomicAdd(nP, (float)sh[0]);
}

template<int REMAP>
__global__ void k_wt(const float* __restrict__ W, __nv_bfloat16* __restrict__ Wh,
                     __nv_bfloat16* __restrict__ Wl, int K, int N, int ldb) {
    __shared__ float t[32][33];
    int k = blockIdx.x*32 + threadIdx.y;
    int n = blockIdx.y*32 + threadIdx.x;
    int nn = (REMAP && n >= 256) ? n + 256 : n;
    t[threadIdx.y][threadIdx.x] = (k < K && n < N) ? W[(size_t)k*ldb + nn] : 0.f;
    __syncthreads();
    int ko = blockIdx.x*32 + threadIdx.x;
    int no = blockIdx.y*32 + threadIdx.y;
    if (ko < K) {
        float v = t[threadIdx.x][threadIdx.y];
        __nv_bfloat16 h = __float2bfloat16(v);
        Wh[(size_t)no*K + ko] = h;
        Wl[(size_t)no*K + ko] = __float2bfloat16(v - __bfloat162float(h));
    }
}

template<int CSH>
__global__ void k_apply3(const float* __restrict__ v, const float* __restrict__ mf,
                         int sites,
                         const float* __restrict__ sumP, const float* __restrict__ sqP,
                         const float* __restrict__ nP,
                         const float* __restrict__ gamma, const float* __restrict__ beta,
                         __nv_bfloat16* __restrict__ oh, __nv_bfloat16* __restrict__ ol) {
    constexpr int C = 1 << CSH;
    __shared__ float sc[C], so[C];
    if (threadIdx.x < C) {
        float n = fmaxf(nP[0], 1.f);
        float mean = sumP[threadIdx.x] / n;
        float var  = sqP[threadIdx.x] / n - mean*mean;
        float rs   = rsqrtf(var + EPS) * gamma[threadIdx.x];
        sc[threadIdx.x] = rs;
        so[threadIdx.x] = beta[threadIdx.x] - mean * rs;
    }
    __syncthreads();
    int i = blockIdx.x * blockDim.x + threadIdx.x;
    int total4 = (sites << CSH) >> 2;
    if (i < total4) {
        int e = i * 4;
        int c0 = e & (C-1);
        float m = mf[e >> CSH];
        float4 t = *reinterpret_cast<const float4*>(&v[e]);
        t.x = fmaxf(t.x*sc[c0+0] + so[c0+0], 0.f) * m;
        t.y = fmaxf(t.y*sc[c0+1] + so[c0+1], 0.f) * m;
        t.z = fmaxf(t.z*sc[c0+2] + so[c0+2], 0.f) * m;
        t.w = fmaxf(t.w*sc[c0+3] + so[c0+3], 0.f) * m;
        *reinterpret_cast<uint2*>(&oh[e]) = make_uint2(bpack(t.x, t.y), bpack(t.z, t.w));
        *reinterpret_cast<uint2*>(&ol[e]) =
            make_uint2(bpack(bres(t.x), bres(t.y)), bpack(bres(t.z), bres(t.w)));
    }
}

template<int CSH>
__global__ void k_poolbn(const float* __restrict__ in, const float* __restrict__ mfin,
                         const float* __restrict__ sumP, const float* __restrict__ sqP,
                         const float* __restrict__ nP,
                         const float* __restrict__ gamma, const float* __restrict__ beta,
                         __nv_bfloat16* __restrict__ oh, __nv_bfloat16* __restrict__ ol,
                         float* __restrict__ mfout,
                         int Hi, int Wi, int Ho, int Wo, float* cntP) {
    constexpr int C = 1 << CSH;
    __shared__ float sc[C], so[C];
    if (threadIdx.x < C) {
        float n = fmaxf(nP[0], 1.f);
        float mean = sumP[threadIdx.x] / n;
        float var  = sqP[threadIdx.x] / n - mean*mean;
        float rs   = rsqrtf(var + EPS) * gamma[threadIdx.x];
        sc[threadIdx.x] = rs;
        so[threadIdx.x] = beta[threadIdx.x] - mean * rs;
    }
    __syncthreads();
    int e = blockIdx.x * blockDim.x + threadIdx.x;
    int total = B_ * Ho * Wo * C;
    int newact = 0;
    if (e < total) {
        int c = e & (C-1);
        int s = e >> CSH;
        int b = s / (Ho*Wo); int r = s - b*(Ho*Wo);
        int y = r / Wo;      int xo = r - y*Wo;
        float best = -1e30f, mm = 0.f;
        float fc = sc[c], fo = so[c];
        #pragma unroll
        for (int dy = 0; dy < 3; dy++)
            #pragma unroll
            for (int dx = 0; dx < 3; dx++) {
                int si = (b*Hi + 2*y + dy) * Wi + 2*xo + dx;
                float m = mfin[si];
                mm = fmaxf(mm, m);
                float vv = -1e30f;
                if (m > 0.f) vv = fmaxf(in[(size_t)si * C + c] * fc + fo, 0.f);
                best = fmaxf(best, vv);
            }
        float v = (mm > 0.f) ? best : 0.f;
        __nv_bfloat16 h = __float2bfloat16(v);
        oh[e] = h;
        ol[e] = __float2bfloat16(v - __bfloat162float(h));
        if (c == 0) { mfout[s] = mm; newact = (mm > 0.f); }
    }
    if (cntP) {
        __shared__ int sh[256];
        sh[threadIdx.x] = newact; __syncthreads();
        for (int o = 128; o > 0; o >>= 1) { if (threadIdx.x < o) sh[threadIdx.x] += sh[threadIdx.x+o]; __syncthreads(); }
        if (threadIdx.x == 0 && sh[0]) atomicAdd(cntP, (float)sh[0]);
    }
}

// LSTM; gates rows ordered m = r*2048 + b
__global__ void k_lstm(const float* __restrict__ gates, const float* __restrict__ m3,
                       __nv_bfloat16* __restrict__ fh, __nv_bfloat16* __restrict__ fl) {
    int e = blockIdx.x * blockDim.x + threadIdx.x;
    if (e >= S3 * 256) return;
    int c = e & 255;
    int s = e >> 8;              // gate row = r*2048 + b
    int b = s & 2047, r = s >> 11;
    const float* g = gates + (size_t)s * 768;
    float gi = g[c], go = g[256 + c], gg = g[512 + c];
    float si = 1.f / (1.f + __expf(-gi));
    float so = 1.f / (1.f + __expf(-go));
    float cc = si * tanhf(gg);
    float hh = so * tanhf(cc) * m3[b*35 + r];
    __nv_bfloat16 h = __float2bfloat16(hh);
    fh[b*8960 + c*35 + r] = h;
    fl[b*8960 + c*35 + r] = __float2bfloat16(hh - __bfloat162float(h));
}

// FC1 split-K finalize
__global__ void k_fin(const float* __restrict__ y1f, const float* __restrict__ bias,
                      __nv_bfloat16* __restrict__ oh, __nv_bfloat16* __restrict__ ol) {
    int i = (blockIdx.x * blockDim.x + threadIdx.x) * 4;
    if (i >= B_*1024) return;
    float4 a = *reinterpret_cast<const float4*>(&y1f[i]);
    float4 b = *reinterpret_cast<const float4*>(&y1f[B_*1024 + i]);
    int n = i & 1023;
    float4 t;
    t.x = fmaxf(a.x + b.x + bias[n],   0.f);
    t.y = fmaxf(a.y + b.y + bias[n+1], 0.f);
    t.z = fmaxf(a.z + b.z + bias[n+2], 0.f);
    t.w = fmaxf(a.w + b.w + bias[n+3], 0.f);
    *reinterpret_cast<uint2*>(&oh[i]) = make_uint2(bpack(t.x, t.y), bpack(t.z, t.w));
    *reinterpret_cast<uint2*>(&ol[i]) =
        make_uint2(bpack(bres(t.x), bres(t.y)), bpack(bres(t.z), bres(t.w)));
}

// ---------------- param blocks ----------------
struct GemmP {
    const float* A; const float* Bw; const float* bias; float* C;
    int M, N, K, ldb;
    const float* img;
    const float* mf; float* sumP; float* sqP;
};
struct GemmB {
    const __nv_bfloat16 *Ah, *Al;
    const __nv_bfloat16 *Bh, *Bl;
    const float* bias; float* C;
    int M, N, K;
    const float* mf; float* sumP; float* sqP;
    __nv_bfloat16 *oh, *ol;
};

// ---------------- HMMA bf16x3 GEMM, TN in {32,64} (conv2, conv3, FC2) ----------------
template<int TN, int MODE, int EPI, int STAT, int IH, int IW, int IC>
__global__ void __launch_bounds__(256) k_hm2(GemmB p) {
    constexpr int TM = 128, BK = 64;
    constexpr int IM = (TN == 64) ? 2 : 1;
    constexpr int LIC = ilog2c(IC);
    constexpr int LTN = ilog2c(TN);
    constexpr int A_BYTES = TM * 128;
    constexpr int B_BYTES = TN * 128;
    constexpr int BUF = 2*A_BYTES + 2*B_BYTES;
    constexpr int BCH = TN * 8 / 256;
    constexpr int CST = TN + 1;

    extern __shared__ char sm[];
    const int tid = threadIdx.x;
    const int wid = tid >> 5, lid = tid & 31;
    const int wm = (TN == 64) ? (wid >> 1) : wid;
    const int wn = (TN == 64) ? (wid & 1) : 0;
    const int m0 = blockIdx.y * TM;
    const int n0 = blockIdx.x * TN;
    const uint32_t sbuf = smem_u32(sm);

    float acc[IM][4][4];
    #pragma unroll
    for (int i = 0; i < IM; i++)
        #pragma unroll
        for (int j = 0; j < 4; j++)
            #pragma unroll
            for (int q = 0; q < 4; q++) acc[i][j][q] = 0.f;

    const int row = tid >> 1;
    const int kt  = (tid & 1) * 32;
    int sbm = 0, sy = 0, sx = 0;
    if (MODE == 1) {
        int m = m0 + row;
        int b = m / (IH*IW);
        int r = m - b*(IH*IW);
        sy = r / IW;
        sx = r - sy*IW;
        sbm = b*IH*IW;
    }

    uint2 ahr[8], alr[8];
    uint4 bhr[BCH], blr[BCH];

    auto load_tile = [&](int k0) {
        #pragma unroll
        for (int j = 0; j < 8; j++) {
            int k = k0 + kt + j*4;
            uint2 vh = make_uint2(0u, 0u), vl = vh;
            if (k < p.K) {
                size_t idx;
                bool ok = true;
                if (MODE == 0) {
                    idx = (size_t)(m0 + row) * p.K + k;
                } else {
                    int t9 = k >> LIC;
                    int c0 = k & (IC-1);
                    int ky = t9 / 3, kx = t9 - 3*ky;
                    int yy = sy + ky - 1, xx = sx + kx - 1;
                    ok = (yy >= 0 && yy < IH && xx >= 0 && xx < IW);
                    idx = (size_t)(sbm + yy*IW + xx) * IC + c0;
                }
                if (ok) {
                    vh = *reinterpret_cast<const uint2*>(&p.Ah[idx]);
                    vl = *reinterpret_cast<const uint2*>(&p.Al[idx]);
                }
            }
            ahr[j] = vh; alr[j] = vl;
        }
        #pragma unroll
        for (int e = 0; e < BCH; e++) {
            int ge = tid + e*256;
            int n  = ge >> 3;
            int kc = ge & 7;
            int k  = k0 + kc*8;
            uint4 vh = make_uint4(0u,0u,0u,0u), vl = vh;
            if (k < p.K) {
                size_t idx = (size_t)(n0 + n) * p.K + k;
                vh = *reinterpret_cast<const uint4*>(&p.Bh[idx]);
                vl = *reinterpret_cast<const uint4*>(&p.Bl[idx]);
            }
            bhr[e] = vh; blr[e] = vl;
        }
    };

    auto store_tile = [&](int bb) {
        char* Ah = sm + bb;
        char* Al = Ah + A_BYTES;
        char* Bh = Ah + 2*A_BYTES;
        char* Bl = Bh + B_BYTES;
        #pragma unroll
        for (int j = 0; j < 8; j++) {
            uint32_t so = SWZ128((uint32_t)(row*128 + (kt + j*4)*2));
            *reinterpret_cast<uint2*>(Ah + so) = ahr[j];
            *reinterpret_cast<uint2*>(Al + so) = alr[j];
        }
        #pragma unroll
        for (int e = 0; e < BCH; e++) {
            int ge = tid + e*256;
            int n  = ge >> 3;
            int kc = ge & 7;
            uint32_t so = SWZ128((uint32_t)(n*128 + kc*16));
            *reinterpret_cast<uint4*>(Bh + so) = bhr[e];
            *reinterpret_cast<uint4*>(Bl + so) = blr[e];
        }
    };

    auto consume = [&](int bb) {
        uint32_t AH = sbuf + bb;
        uint32_t AL = AH + A_BYTES;
        uint32_t BH = AH + 2*A_BYTES;
        uint32_t BL = BH + B_BYTES;
        #pragma unroll
        for (int ks = 0; ks < 4; ks++) {
            uint32_t bh[2][4], bl[2][4];
            #pragma unroll
            for (int jp = 0; jp < 2; jp++) {
                int n_r = wn*32 + jp*16 + (lid & 7) + ((lid >> 4) << 3);
                int kb  = ks*32 + (((lid >> 3) & 1) << 4);
                uint32_t off = SWZ128((uint32_t)(n_r*128 + kb));
                LDSM_X4(bh[jp][0], bh[jp][1], bh[jp][2], bh[jp][3], BH + off);
                LDSM_X4(bl[jp][0], bl[jp][1], bl[jp][2], bl[jp][3], BL + off);
            }
            #pragma unroll
            for (int im = 0; im < IM; im++) {
                int row_a = wm*(16*IM) + im*16 + (lid & 15);
                int kb    = ks*32 + (lid >> 4) * 16;
                uint32_t off = SWZ128((uint32_t)(row_a*128 + kb));
                uint32_t ah[4], al[4];
                LDSM_X4(ah[0], ah[1], ah[2], ah[3], AH + off);
                LDSM_X4(al[0], al[1], al[2], al[3], AL + off);
                #pragma unroll
                for (int jn = 0; jn < 4; jn++) {
                    int jp = jn >> 1, s = (jn & 1) * 2;
                    MMA_BF16(acc[im][jn], ah[0], ah[1], ah[2], ah[3], bh[jp][s], bh[jp][s+1]);
                    MMA_BF16(acc[im][jn], ah[0], ah[1], ah[2], ah[3], bl[jp][s], bl[jp][s+1]);
                    MMA_BF16(acc[im][jn], al[0], al[1], al[2], al[3], bh[jp][s], bh[jp][s+1]);
                }
            }
        }
    };

    const int T = (p.K + BK - 1) / BK;
    load_tile(0);
    store_tile(0);
    __syncthreads();

    for (int t = 0; t < T; t++) {
        if (t + 1 < T) load_tile((t + 1) * BK);
        consume((t & 1) * BUF);
        if (t + 1 < T) store_tile(((t + 1) & 1) * BUF);
        __syncthreads();
    }

    float* cs   = reinterpret_cast<float*>(sm);
    float* mrow = cs + TM*CST;
    float* rs   = mrow + TM;
    float* rq   = rs + 256;
    #pragma unroll
    for (int im = 0; im < IM; im++) {
        int r0 = wm*(16*IM) + im*16 + (lid >> 2);
        #pragma unroll
        for (int jn = 0; jn < 4; jn++) {
            int c = wn*32 + jn*8 + (lid & 3)*2;
            cs[r0*CST + c]       = acc[im][jn][0];
            cs[r0*CST + c + 1]   = acc[im][jn][1];
            cs[(r0+8)*CST + c]   = acc[im][jn][2];
            cs[(r0+8)*CST + c+1] = acc[im][jn][3];
        }
    }
    if (STAT && tid < TM) mrow[tid] = p.mf[m0 + tid];
    __syncthreads();

    float lsum = 0.f, lsq = 0.f;
    for (int e = tid; e < TM*TN; e += 256) {
        int rr = e >> LTN;
        int cc = e & (TN-1);
        int n  = n0 + cc;
        float v = cs[rr*CST + cc];
        if (STAT) {
            float mk = mrow[rr];
            float xv = (mk > 0.f) ? v : 0.f;
            lsum += xv; lsq += xv*xv;
        }
        if (n < p.N) {
            if (EPI == 1 || EPI == 2 || EPI == 3) {
                int nnb = (EPI == 3 && n >= 256) ? n + 256 : n;
                v += p.bias[nnb];
                if (EPI == 2) v = fmaxf(v, 0.f);
                p.C[(size_t)(m0 + rr) * p.N + n] = v;
            } else if (EPI == 4) {
                v = fmaxf(v + p.bias[n], 0.f);
                __nv_bfloat16 h = __float2bfloat16(v);
                p.oh[(size_t)(m0 + rr) * p.N + n] = h;
                p.ol[(size_t)(m0 + rr) * p.N + n] = __float2bfloat16(v - __bfloat162float(h));
            } else {
                p.C[(size_t)(m0 + rr) * p.N + n] = v;
            }
        }
    }
    if (STAT) {
        rs[tid] = lsum; rq[tid] = lsq;
        __syncthreads();
        if (tid < TN) {
            float s = 0.f, q = 0.f;
            #pragma unroll
            for (int g = 0; g < 256/TN; g++) { s += rs[tid + g*TN]; q += rq[tid + g*TN]; }
            if (n0 + tid < p.N) {
                atomicAdd(&p.sumP[n0 + tid], s);
                atomicAdd(&p.sqP[n0 + tid], q);
            }
        }
    }
}

// ---------------- HMMA bf16x3 GEMM, TM=128 x TN=128, BK=32, 3-stage cp.async ----------
// MODE 0: dense. MODE 1: im2col. MODE 2: gate mode (rows m = r*2048 + b, tile-uniform
// taps, invalid taps skipped).  SPLIT=1: blockIdx.z K-half partials.
template<int MODE, int EPI, int STAT, int SPLIT, int IH, int IW, int IC>
__global__ void __launch_bounds__(256, 2) k_hm3(GemmB p) {
    constexpr int TM = 128, TN = 128, BK = 32;
    constexpr int LIC = ilog2c(IC);
    constexpr int A_BYTES = TM * 128;
    constexpr int B_BYTES = TN * 128;
    constexpr int STAGE = A_BYTES + B_BYTES;   // 32 KB; 3 stages = 96 KB

    extern __shared__ char sm[];
    const int tid = threadIdx.x;
    const int wid = tid >> 5, lid = tid & 31;
    const int wm = wid >> 2;
    const int wn = wid & 3;
    const int m0 = blockIdx.y * TM;
    const int n0 = blockIdx.x * TN;
    const int koff = SPLIT ? (int)blockIdx.z * (p.K >> 1) : 0;
    const int KT   = SPLIT ? (p.K >> 1) : p.K;
    float* Cw = SPLIT ? p.C + (size_t)blockIdx.z * ((size_t)p.M * p.N) : p.C;
    const uint32_t sbuf = smem_u32(sm);

    float acc[4][4][4];
    #pragma unroll
    for (int i = 0; i < 4; i++)
        #pragma unroll
        for (int j = 0; j < 4; j++)
            #pragma unroll
            for (int q = 0; q < 4; q++) acc[i][j][q] = 0.f;

    const int row  = tid >> 1;
    const int half = tid & 1;
    int sbm = 0, sy = 0, sx = 0, vmask = 0;
    if (MODE == 1) {
        int m = m0 + row;
        int b = m / (IH*IW);
        int r = m - b*(IH*IW);
        sy = r / IW;
        sx = r - sy*IW;
        sbm = b*IH*IW;
    } else if (MODE == 2) {
        int rt = m0 >> 11;            // tile-uniform spatial position
        sy = rt / IW;
        sx = rt - sy*IW;
        sbm = ((m0 & 2047) + row) * (IH*IW);
        #pragma unroll
        for (int t = 0; t < 9; t++) {
            int dy = t/3, dx = t - 3*(t/3);
            int yy = sy + dy - 1, xx = sx + dx - 1;
            if (yy >= 0 && yy < IH && xx >= 0 && xx < IW) vmask |= 1 << t;
        }
    }

    // issue one stage of cp.async (8 x 16B per thread)
    auto issue_stage = [&](int k0, int bb) {
        {
            const __nv_bfloat16* src = half ? p.Al : p.Ah;
            bool ok = true;
            size_t idx = 0;
            if (MODE == 0) {
                idx = (size_t)(m0 + row) * p.K + koff + k0;
            } else if (MODE == 1) {
                int t9 = k0 >> LIC;
                int c0 = k0 & (IC-1);
                int ky = t9 / 3, kx = t9 - 3*ky;
                int yy = sy + ky - 1, xx = sx + kx - 1;
                ok = (yy >= 0 && yy < IH && xx >= 0 && xx < IW);
                idx = ok ? (size_t)(sbm + yy*IW + xx) * IC + c0 : 0;
            } else {
                int t9 = k0 >> LIC;               // valid by construction
                int ky = t9 / 3, kx = t9 - 3*ky;
                idx = (size_t)(sbm + (sy + ky - 1)*IW + (sx + kx - 1)) * IC + (k0 & (IC-1));
            }
            const char* g = reinterpret_cast<const char*>(src + idx);
            uint32_t okb = ok ? 16u : 0u;
            #pragma unroll
            for (int j = 0; j < 4; j++) {
                uint32_t dst = sbuf + bb + SWZ128((uint32_t)(row*128 + half*64 + j*16));
                CP16(dst, g + j*16, okb);
            }
        }
        {
            const __nv_bfloat16* src = half ? p.Bl : p.Bh;
            const char* g = reinterpret_cast<const char*>(src + (size_t)(n0 + row) * p.K + koff + k0);
            #pragma unroll
            for (int j = 0; j < 4; j++) {
                uint32_t dst = sbuf + bb + A_BYTES + SWZ128((uint32_t)(row*128 + half*64 + j*16));
                CP16(dst, g + j*16, 16u);
            }
        }
    };

    auto consume = [&](int bb) {
        uint32_t Abase = sbuf + bb;
        uint32_t Bbase = Abase + A_BYTES;
        #pragma unroll
        for (int ks = 0; ks < 2; ks++) {
            uint32_t bh[2][4], bl[2][4];
            #pragma unroll
            for (int jp = 0; jp < 2; jp++) {
                int n_r = wn*32 + jp*16 + (lid & 7) + ((lid >> 4) << 3);
                int kb  = ks*32 + (((lid >> 3) & 1) << 4);
                LDSM_X4(bh[jp][0], bh[jp][1], bh[jp][2], bh[jp][3],
                        Bbase + SWZ128((uint32_t)(n_r*128 + kb)));
                LDSM_X4(bl[jp][0], bl[jp][1], bl[jp][2], bl[jp][3],
                        Bbase + SWZ128((uint32_t)(n_r*128 + 64 + kb)));
            }
            #pragma unroll
            for (int im = 0; im < 4; im++) {
                int row_a = wm*64 + im*16 + (lid & 15);
                int kb    = ks*32 + ((lid >> 4) << 4);
                uint32_t ah[4], al[4];
                LDSM_X4(ah[0], ah[1], ah[2], ah[3],
                        Abase + SWZ128((uint32_t)(row_a*128 + kb)));
                LDSM_X4(al[0], al[1], al[2], al[3],
                        Abase + SWZ128((uint32_t)(row_a*128 + 64 + kb)));
                #pragma unroll
                for (int jn = 0; jn < 4; jn++) {
                    int jp = jn >> 1, s = (jn & 1) * 2;
                    MMA_BF16(acc[im][jn], ah[0], ah[1], ah[2], ah[3], bh[jp][s], bh[jp][s+1]);
                    MMA_BF16(acc[im][jn], ah[0], ah[1], ah[2], ah[3], bl[jp][s], bl[jp][s+1]);
                    MMA_BF16(acc[im][jn], al[0], al[1], al[2], al[3], bh[jp][s], bh[jp][s+1]);
                }
            }
        }
    };

    // tile cursor (linear for MODE 0/1, skip-list for MODE 2)
    auto advance = [&](int k0) {
        if (MODE == 2) {
            k0 += BK;
            while (k0 < KT && !((vmask >> (k0 >> LIC)) & 1))
                k0 = (((k0 >> LIC) + 1) << LIC);
            return k0;
        }
        return k0 + BK;
    };
    int kis, T;
    if (MODE == 2) {
        kis = 0;
        while (!((vmask >> (kis >> LIC)) & 1)) kis += (1 << LIC);
        T = __popc(vmask) * (IC / BK);
    } else {
        kis = 0;
        T = KT / BK;
    }

    // 3-stage pipeline: 2 stages in flight, one commit-group per iteration
    issue_stage(kis, 0);
    CP_COMMIT();
    kis = advance(kis);
    if (T > 1) issue_stage(kis, STAGE);
    CP_COMMIT();
    kis = advance(kis);

    for (int t = 0; t < T; t++) {
        CP_WAIT1();
        __syncthreads();
        if (t + 2 < T) { issue_stage(kis, ((t + 2) % 3) * STAGE); kis = advance(kis); }
        CP_COMMIT();
        consume((t % 3) * STAGE);
    }
    CP_WAIT0();
    __syncthreads();

    constexpr int CST = 130;
    float* cs   = reinterpret_cast<float*>(sm);
    float* mrow = cs + 64*CST;
    float* rs   = mrow + 128;
    float* rq   = rs + 256;
    if (STAT && tid < 128) mrow[tid] = p.mf[m0 + tid];
    float lsum = 0.f, lsq = 0.f;

    #pragma unroll
    for (int h = 0; h < 2; h++) {
        if (wm == h) {
            #pragma unroll
            for (int im = 0; im < 4; im++) {
                int r0 = im*16 + (lid >> 2);
                #pragma unroll
                for (int jn = 0; jn < 4; jn++) {
                    int c = wn*32 + jn*8 + (lid & 3)*2;
                    cs[r0*CST + c]       = acc[im][jn][0];
                    cs[r0*CST + c + 1]   = acc[im][jn][1];
                    cs[(r0+8)*CST + c]   = acc[im][jn][2];
                    cs[(r0+8)*CST + c+1] = acc[im][jn][3];
                }
            }
        }
        __syncthreads();
        for (int e = tid; e < 64*128; e += 256) {
            int rr = e >> 7;
            int cc = e & 127;
            int n  = n0 + cc;
            float v = cs[rr*CST + cc];
            if (STAT) {
                float mk = mrow[h*64 + rr];
                float xv = (mk > 0.f) ? v : 0.f;
                lsum += xv; lsq += xv*xv;
            }
            if (n < p.N) {
                if (SPLIT) {
                    Cw[(size_t)(m0 + h*64 + rr) * p.N + n] = v;
                } else if (EPI == 1 || EPI == 2 || EPI == 3) {
                    int nnb = (EPI == 3 && n >= 256) ? n + 256 : n;
                    v += p.bias[nnb];
                    if (EPI == 2) v = fmaxf(v, 0.f);
                    Cw[(size_t)(m0 + h*64 + rr) * p.N + n] = v;
                } else if (EPI == 4) {
                    v = fmaxf(v + p.bias[n], 0.f);
                    __nv_bfloat16 hb = __float2bfloat16(v);
                    p.oh[(size_t)(m0 + h*64 + rr) * p.N + n] = hb;
                    p.ol[(size_t)(m0 + h*64 + rr) * p.N + n] = __float2bfloat16(v - __bfloat162float(hb));
                } else {
                    Cw[(size_t)(m0 + h*64 + rr) * p.N + n] = v;
                }
            }
        }
        __syncthreads();
    }
    if (STAT) {
        rs[tid] = lsum; rq[tid] = lsq;
        __syncthreads();
        if (tid < 128) {
            float s = rs[tid] + rs[tid + 128];
            float q = rq[tid] + rq[tid + 128];
            if (n0 + tid < p.N) {
                atomicAdd(&p.sumP[n0 + tid], s);
                atomicAdd(&p.sqP[n0 + tid], q);
            }
        }
    }
}

// ---------------- packed-f32x2 GEMM (conv1 only), fused stats ----------------
template<int TN, int MODE, int EPI, int STAT, int IH, int IW, int IC>
__global__ void __launch_bounds__(256) k_gemm3(GemmP p) {
    constexpr int TM = 128, BK = 16;
    constexpr int TX = (TN == 32) ? 8 : 16;
    constexpr int NR = TN / TX;
    constexpr int TY = 256 / TX;
    constexpr int MR = TM / TY;
    constexpr int MP = MR / 2;
    constexpr int LIC = ilog2c(IC);
    constexpr int LTN = ilog2c(TN);
    constexpr int B_EPT = (BK * TN) / 256;

    __shared__ float  As[2][BK][TM];
    __shared__ float2 Bs[2][BK][TN];
    __shared__ float mrow[TM];
    __shared__ float sred[TN], qred[TN];

    const int tid = threadIdx.x;
    const int tx = tid % TX, ty = tid / TX;
    const int m0 = blockIdx.y * TM;
    const int n0 = blockIdx.x * TN;

    unsigned long long acc[MP][NR];
    #pragma unroll
    for (int i = 0; i < MP; i++)
        #pragma unroll
        for (int j = 0; j < NR; j++) acc[i][j] = 0ULL;

    int pm_b[2], pm_y[2], pm_x[2];
    if (MODE == 1) {
        #pragma unroll
        for (int i = 0; i < 2; i++) {
            int m = m0 + ((tid + i*256) >> 2);
            int b = m / (IH*IW);
            int r = m - b*(IH*IW);
            int y = r / IW;
            pm_b[i] = b*IH*IW;
            pm_y[i] = y;
            pm_x[i] = r - y*IW;
        }
    }

    float a_reg[8];
    float b_reg[B_EPT];

    auto load_tile = [&](int k0) {
        if (MODE == 1) {
            #pragma unroll
            for (int i = 0; i < 2; i++) {
                int gq = tid + i*256;
                int kbase = k0 + (gq & 3)*4;
                #pragma unroll
                for (int j = 0; j < 4; j++) {
                    int k = kbase + j;
                    float v = 0.f;
                    if (k < p.K) {
                        int c  = k & (IC-1);
                        int t9 = k >> LIC;
                        int ky = t9 / 3, kx = t9 - 3*ky;
                        int yy = pm_y[i] + ky - 1, xx = pm_x[i] + kx - 1;
                        if (yy >= 0 && yy < IH && xx >= 0 && xx < IW)
                            v = p.img[(size_t)(pm_b[i] + yy*IW + xx) * IC + c];
                    }
                    a_reg[i*4+j] = v;
                }
            }
        } else {
            #pragma unroll
            for (int i = 0; i < 2; i++) {
                int gq = tid + i*256;
                int m = m0 + (gq >> 2);
                int k = k0 + (gq & 3) * 4;
                float4 t = *reinterpret_cast<const float4*>(&p.A[(size_t)m * p.K + k]);
                a_reg[i*4+0] = t.x; a_reg[i*4+1] = t.y;
                a_reg[i*4+2] = t.z; a_reg[i*4+3] = t.w;
            }
        }
        #pragma unroll
        for (int e = 0; e < B_EPT; e++) {
            int ge = tid + e*256;
            int kl = ge >> LTN;
            int n  = ge & (TN-1);
            int k  = k0 + kl;
            int nn = n0 + n;
            float v = 0.f;
            if (k < p.K && nn < p.N) v = p.Bw[(size_t)k * p.ldb + nn];
            b_reg[e] = v;
        }
    };

    auto store_tile = [&](int buf) {
        #pragma unroll
        for (int i = 0; i < 2; i++) {
            int gq = tid + i*256;
            int ml = gq >> 2;
            int kq = (gq & 3) * 4;
            #pragma unroll
            for (int j = 0; j < 4; j++) As[buf][kq+j][ml] = a_reg[i*4+j];
        }
        #pragma unroll
        for (int e = 0; e < B_EPT; e++) {
            int ge = tid + e*256;
            int kl = ge >> LTN;
            int n  = ge & (TN-1);
            Bs[buf][kl][n] = make_float2(b_reg[e], b_reg[e]);
        }
    };

    const int nTiles = (p.K + BK - 1) / BK;
    load_tile(0);
    store_tile(0);
    __syncthreads();

    for (int t = 0; t < nTiles; t++) {
        int cur = t & 1;
        if (t + 1 < nTiles) load_tile((t + 1) * BK);
        #pragma unroll
        for (int kk = 0; kk < BK; kk++) {
            unsigned long long af[MP], bf[NR];
            const ulonglong2* ap = reinterpret_cast<const ulonglong2*>(&As[cur][kk][ty*MR]);
            #pragma unroll
            for (int i = 0; i < MP/2; i++) { ulonglong2 v = ap[i]; af[2*i] = v.x; af[2*i+1] = v.y; }
            const unsigned long long* bp = reinterpret_cast<const unsigned long long*>(&Bs[cur][kk][0]);
            #pragma unroll
            for (int nr = 0; nr < NR; nr++) bf[nr] = bp[tx + nr*TX];
            #pragma unroll
            for (int mp = 0; mp < MP; mp++)
                #pragma unroll
                for (int nr = 0; nr < NR; nr++)
                    FMA2(acc[mp][nr], af[mp], bf[nr]);
        }
        if (t + 1 < nTiles) store_tile(cur ^ 1);
        __syncthreads();
    }

    if (STAT) {
        if (tid < TN) { sred[tid] = 0.f; qred[tid] = 0.f; }
        if (tid < TM) mrow[tid] = p.mf[m0 + tid];
        __syncthreads();
    }

    #pragma unroll
    for (int mp = 0; mp < MP; mp++) {
        int m = m0 + ty*MR + 2*mp;
        #pragma unroll
        for (int nr = 0; nr < NR; nr++) {
            int n = n0 + tx + nr*TX;
            if (n >= p.N) continue;
            float lo = __uint_as_float((unsigned)(acc[mp][nr] & 0xFFFFFFFFULL));
            float hi = __uint_as_float((unsigned)(acc[mp][nr] >> 32));
            if (STAT) {
                float mk0 = mrow[ty*MR + 2*mp], mk1 = mrow[ty*MR + 2*mp + 1];
                float x0 = (mk0 > 0.f) ? lo : 0.f;
                float x1 = (mk1 > 0.f) ? hi : 0.f;
                atomicAdd(&sred[n - n0], x0 + x1);
                atomicAdd(&qred[n - n0], x0*x0 + x1*x1);
            }
            if (EPI >= 1) { float bb = p.bias[n]; lo += bb; hi += bb; }
            if (EPI == 2) { lo = fmaxf(lo, 0.f); hi = fmaxf(hi, 0.f); }
            p.C[(size_t)m       * p.N + n] = lo;
            p.C[(size_t)(m + 1) * p.N + n] = hi;
        }
    }
    if (STAT) {
        __syncthreads();
        if (tid < TN && n0 + tid < p.N) {
            atomicAdd(&p.sumP[n0 + tid], sred[tid]);
            atomicAdd(&p.sqP[n0 + tid], qred[tid]);
        }
    }
}

// ---------------- launcher ----------------
static inline int ceil_div(int a, int b) { return (a + b - 1) / b; }
#define HM_SMEM64 (2 * (2*128*128 + 2*64*128))   // 96 KB
#define HM_SMEM32 (2 * (2*128*128 + 2*32*128))   // 80 KB
#define HM3_SMEM  (3 * (128*128 + 128*128))      // 96 KB (3-stage cp.async)

extern "C" void kernel_launch(void* const* d_in, const int* in_sizes, int n_in,
                              void* d_out, int out_size) {
    const float* x    = (const float*)d_in[0];
    const int*   mask = (const int*)  d_in[1];
    const float* W1 = (const float*)d_in[2];  const float* ga1 = (const float*)d_in[3];  const float* be1 = (const float*)d_in[4];
    const float* W2 = (const float*)d_in[5];  const float* ga2 = (const float*)d_in[6];  const float* be2 = (const float*)d_in[7];
    const float* W3 = (const float*)d_in[8];  const float* ga3 = (const float*)d_in[9];  const float* be3 = (const float*)d_in[10];
    const float* W4 = (const float*)d_in[11]; const float* ga4 = (const float*)d_in[12]; const float* be4 = (const float*)d_in[13];
    const float* Wl = (const float*)d_in[14]; const float* bl  = (const float*)d_in[15];
    const float* lw1 = (const float*)d_in[16]; const float* lb1 = (const float*)d_in[17];
    const float* lw2 = (const float*)d_in[18]; const float* lb2 = (const float*)d_in[19];
    float* out = (float*)d_out;

    float *xm, *m1, *h1, *h2, *m2, *h3, *h4, *m3, *gates, *y1f, *st;
    __nv_bfloat16 *h1h, *h1l, *p1h, *p1l, *h3h, *h3l, *p2h, *p2l, *fh, *fl, *y1h, *y1l;
    __nv_bfloat16 *w2h, *w2l, *w3h, *w3l, *w4h, *w4l, *wlh, *wll, *l1h, *l1l, *l2h, *l2l;
    cudaGetSymbolAddress((void**)&xm,  g_xm);   cudaGetSymbolAddress((void**)&m1,  g_m1);
    cudaGetSymbolAddress((void**)&h1,  g_h1);   cudaGetSymbolAddress((void**)&h2,  g_h2);
    cudaGetSymbolAddress((void**)&m2,  g_m2);   cudaGetSymbolAddress((void**)&h3,  g_h3);
    cudaGetSymbolAddress((void**)&h4,  g_h4);   cudaGetSymbolAddress((void**)&m3,  g_m3);
    cudaGetSymbolAddress((void**)&gates, g_gates);
    cudaGetSymbolAddress((void**)&y1f, g_y1f);  cudaGetSymbolAddress((void**)&st,  g_stats);
    cudaGetSymbolAddress((void**)&h1h, g_h1h);  cudaGetSymbolAddress((void**)&h1l, g_h1l);
    cudaGetSymbolAddress((void**)&p1h, g_p1h);  cudaGetSymbolAddress((void**)&p1l, g_p1l);
    cudaGetSymbolAddress((void**)&h3h, g_h3h);  cudaGetSymbolAddress((void**)&h3l, g_h3l);
    cudaGetSymbolAddress((void**)&p2h, g_p2h);  cudaGetSymbolAddress((void**)&p2l, g_p2l);
    cudaGetSymbolAddress((void**)&fh,  g_flath);cudaGetSymbolAddress((void**)&fl,  g_flatl);
    cudaGetSymbolAddress((void**)&y1h, g_y1h);  cudaGetSymbolAddress((void**)&y1l, g_y1l);
    cudaGetSymbolAddress((void**)&w2h, g_w2h);  cudaGetSymbolAddress((void**)&w2l, g_w2l);
    cudaGetSymbolAddress((void**)&w3h, g_w3h);  cudaGetSymbolAddress((void**)&w3l, g_w3l);
    cudaGetSymbolAddress((void**)&w4h, g_w4h);  cudaGetSymbolAddress((void**)&w4l, g_w4l);
    cudaGetSymbolAddress((void**)&wlh, g_wlh);  cudaGetSymbolAddress((void**)&wll, g_wll);
    cudaGetSymbolAddress((void**)&l1h, g_l1h);  cudaGetSymbolAddress((void**)&l1l, g_l1l);
    cudaGetSymbolAddress((void**)&l2h, g_l2h);  cudaGetSymbolAddress((void**)&l2l, g_l2l);

    float *sum1 = st+0,   *sq1 = st+16;
    float *sum2 = st+32,  *sq2 = st+64;
    float *sum3 = st+128, *sq3 = st+192;
    float *sum4 = st+256, *sq4 = st+384;
    float *n1 = st+512, *n2 = st+513;

    cudaFuncSetAttribute(k_hm2<32,1,0,1,H1_,W1_,16>,  cudaFuncAttributeMaxDynamicSharedMemorySize, HM_SMEM32);
    cudaFuncSetAttribute(k_hm2<64,1,0,1,H2_,W2_,32>,  cudaFuncAttributeMaxDynamicSharedMemorySize, HM_SMEM64);
    cudaFuncSetAttribute(k_hm2<64,0,1,0,1,1,16>,      cudaFuncAttributeMaxDynamicSharedMemorySize, HM_SMEM64);
    cudaFuncSetAttribute(k_hm3<1,0,1,0,H2_,W2_,64>,   cudaFuncAttributeMaxDynamicSharedMemorySize, HM3_SMEM);
    cudaFuncSetAttribute(k_hm3<2,3,0,0,H3_,W3_,128>,  cudaFuncAttributeMaxDynamicSharedMemorySize, HM3_SMEM);
    cudaFuncSetAttribute(k_hm3<0,0,0,1,1,1,32>,       cudaFuncAttributeMaxDynamicSharedMemorySize, HM3_SMEM);

    // weight transpose+split
    { dim3 b(32,32);
      k_wt<0><<<dim3(ceil_div(144,32),  1),  b>>>(W2,  w2h, w2l, 144,  32,   32);
      k_wt<0><<<dim3(ceil_div(288,32),  2),  b>>>(W3,  w3h, w3l, 288,  64,   64);
      k_wt<0><<<dim3(ceil_div(576,32),  4),  b>>>(W4,  w4h, w4l, 576,  128,  128);
      k_wt<1><<<dim3(ceil_div(1152,32), 24), b>>>(Wl,  wlh, wll, 1152, 768,  1024);
      k_wt<0><<<dim3(ceil_div(8960,32), 32), b>>>(lw1, l1h, l1l, 8960, 1024, 1024);
      k_wt<0><<<dim3(ceil_div(1024,32), 14), b>>>(lw2, l2h, l2l, 1024, 420,  420);
    }

    k_zero_stats<<<1, 1024>>>(st);
    k_prep<<<ceil_div(S1, 256), 256>>>(x, mask, xm, m1, n1);

    // conv1: 2->16 (K=18) — FFMA2 + fused stats
    { GemmP p = { nullptr, W1, nullptr, h1, S1, 16, 18, 16, xm, m1, sum1, sq1 };
      k_gemm3<32,1,0,1,H1_,W1_,2><<<dim3(1, S1/128), 256>>>(p); }
    k_apply3<4><<<ceil_div(S1*16/4, 256), 256>>>(h1, m1, S1, sum1, sq1, n1, ga1, be1, h1h, h1l);

    // conv2: 16->32 (K=144) — HMMA TN=32 + fused stats
    { GemmB p = { h1h, h1l, w2h, w2l, nullptr, h2, S1, 32, 144, m1, sum2, sq2, nullptr, nullptr };
      k_hm2<32,1,0,1,H1_,W1_,16><<<dim3(1, S1/128), 256, HM_SMEM32>>>(p); }

    // pool1 + BN2 fused -> bf16, count n2
    k_poolbn<5><<<ceil_div(S2*32, 256), 256>>>(h2, m1, sum2, sq2, n1, ga2, be2,
                                               p1h, p1l, m2, H1_, W1_, H2_, W2_, n2);

    // conv3: 32->64 (K=288) — HMMA TN=64 + fused stats
    { GemmB p = { p1h, p1l, w3h, w3l, nullptr, h3, S2, 64, 288, m2, sum3, sq3, nullptr, nullptr };
      k_hm2<64,1,0,1,H2_,W2_,32><<<dim3(1, S2/128), 256, HM_SMEM64>>>(p); }
    k_apply3<6><<<ceil_div(S2*64/4, 256), 256>>>(h3, m2, S2, sum3, sq3, n2, ga3, be3, h3h, h3l);

    // conv4: 64->128 (K=576) — HMMA TN=128 cp.async + fused stats
    { GemmB p = { h3h, h3l, w4h, w4l, nullptr, h4, S2, 128, 576, m2, sum4, sq4, nullptr, nullptr };
      k_hm3<1,0,1,0,H2_,W2_,64><<<dim3(1, S2/128), 256, HM3_SMEM>>>(p); }

    // pool2 + BN4 fused -> bf16
    k_poolbn<7><<<ceil_div(S3*128, 256), 256>>>(h4, m2, sum4, sq4, n2, ga4, be4,
                                                p2h, p2l, m3, H2_, W2_, H3_, W3_, nullptr);

    // gate conv: 128->768 (f skipped; remap in k_wt) + bias (K=1152) — HMMA cp.async,
    // gate mode: rows m = r*2048 + b, tile-uniform taps, invalid taps skipped
    { GemmB p = { p2h, p2l, wlh, wll, bl, gates, S3, 768, 1152, nullptr, nullptr, nullptr, nullptr, nullptr };
      k_hm3<2,3,0,0,H3_,W3_,128><<<dim3(6, S3/128), 256, HM3_SMEM>>>(p); }

    // LSTM nonlinearity (gate rows r*2048+b) -> flat bf16 hi/lo in (C,H,W) order
    k_lstm<<<ceil_div(S3*256, 256), 256>>>(gates, m3, fh, fl);

    // FC1: [2048,8960]x[8960,1024] — HMMA cp.async, split-K=2 -> fp32 partials
    { GemmB p = { fh, fl, l1h, l1l, nullptr, y1f, B_, 1024, 8960, nullptr, nullptr, nullptr, nullptr, nullptr };
      k_hm3<0,0,0,1,1,1,32><<<dim3(8, B_/128, 2), 256, HM3_SMEM>>>(p); }
    k_fin<<<ceil_div(B_*1024/4, 256), 256>>>(y1f, lb1, y1h, y1l);

    // FC2: [2048,1024]x[1024,420] + bias -> out — HMMA TN=64
    { GemmB p = { y1h, y1l, l2h, l2l, lb2, out, B_, 420, 1024, nullptr, nullptr, nullptr, nullptr, nullptr };
      k_hm2<64,0,1,0,1,1,16><<<dim3(7, B_/128), 256, HM_SMEM64>>>(p); }
}

// round 17
// speedup vs baseline: 2.0728x; 1.2849x over previous
#include <cuda_runtime.h>
#include <cuda_fp16.h>
#include <math.h>
#include <stdint.h>

#define EPS 1e-4f

#define B_  2048
#define H1_ 23
#define W1_ 31
#define H2_ 11
#define W2_ 15
#define H3_ 5
#define W3_ 7

#define S1 (B_*H1_*W1_)
#define S2 (B_*H2_*W2_)
#define S3 (B_*H3_*W3_)

// ---------------- scratch ----------------
__device__ __align__(16) float g_xm[S1*2];
__device__ __align__(16) float g_m1[S1];
__device__ __align__(16) float g_h1[S1*16];
__device__ __align__(16) __half g_h1h[S1*16];
__device__ __align__(16) __half g_h1l[S1*16];
__device__ __align__(16) float g_h2[S1*32];
__device__ __align__(16) __half g_p1h[S2*32];
__device__ __align__(16) __half g_p1l[S2*32];
__device__ __align__(16) float g_m2[S2];
__device__ __align__(16) float g_h3[S2*64];
__device__ __align__(16) __half g_h3h[S2*64];
__device__ __align__(16) __half g_h3l[S2*64];
__device__ __align__(16) float g_h4[S2*128];
__device__ __align__(16) __half g_p2h[S3*128];
__device__ __align__(16) __half g_p2l[S3*128];
__device__ __align__(16) float g_m3[S3];
__device__ __align__(16) float g_gates[S3*768];   // rows ordered m = r*2048 + b
__device__ __align__(16) __half g_flath[B_*8960];
__device__ __align__(16) __half g_flatl[B_*8960];
__device__ __align__(16) float g_y1f[2*B_*1024];
__device__ __align__(16) __half g_y1h[B_*1024];
__device__ __align__(16) __half g_y1l[B_*1024];
__device__ __align__(16) float g_stats[544];
// transposed fp16 weights [n][k] (hi only; A carries the split)
__device__ __align__(16) __half g_w2h[32*144];
__device__ __align__(16) __half g_w3h[64*288];
__device__ __align__(16) __half g_w4h[128*576];
__device__ __align__(16) __half g_wlh[768*1152];
__device__ __align__(16) __half g_l1h[1024*8960];
__device__ __align__(16) __half g_l2h[448*1024];

__host__ __device__ constexpr int ilog2c(int x) { return x <= 1 ? 0 : 1 + ilog2c(x >> 1); }

#define FMA2(d, a, b) asm("fma.rn.f32x2 %0, %1, %2, %0;" : "+l"(d) : "l"(a), "l"(b))
#define SWZ128(x) ((x) ^ (((x) >> 3) & 0x70))

__device__ __forceinline__ uint32_t smem_u32(const void* p) {
    uint32_t a;
    asm("{ .reg .u64 t; cvta.to.shared.u64 t, %1; cvt.u32.u64 %0, t; }" : "=r"(a) : "l"(p));
    return a;
}

#define LDSM_X4(r0, r1, r2, r3, addr) \
    asm volatile("ldmatrix.sync.aligned.m8n8.x4.shared.b16 {%0,%1,%2,%3}, [%4];" \
        : "=r"(r0), "=r"(r1), "=r"(r2), "=r"(r3) : "r"(addr))

#define MMA_F16(d, a0, a1, a2, a3, b0, b1) \
    asm volatile("mma.sync.aligned.m16n8k16.row.col.f32.f16.f16.f32 " \
        "{%0,%1,%2,%3}, {%4,%5,%6,%7}, {%8,%9}, {%0,%1,%2,%3};" \
        : "+f"((d)[0]), "+f"((d)[1]), "+f"((d)[2]), "+f"((d)[3]) \
        : "r"(a0), "r"(a1), "r"(a2), "r"(a3), "r"(b0), "r"(b1))

#define CP16(dst, src, bytes) \
    asm volatile("cp.async.cg.shared.global [%0], [%1], 16, %2;" \
        :: "r"(dst), "l"(src), "r"(bytes) : "memory")
#define CP_COMMIT() asm volatile("cp.async.commit_group;" ::: "memory")
#define CP_WAIT1()  asm volatile("cp.async.wait_group 1;" ::: "memory")
#define CP_WAIT0()  asm volatile("cp.async.wait_group 0;" ::: "memory")

__device__ __forceinline__ uint32_t hpack(float a, float b) {
    __half2 t;
    t.x = __float2half_rn(a);
    t.y = __float2half_rn(b);
    return *reinterpret_cast<uint32_t*>(&t);
}
__device__ __forceinline__ float hres(float x) {
    return x - __half2float(__float2half_rn(x));
}

// ---------------- small kernels ----------------
__global__ void k_zero_stats(float* st) {
    if (threadIdx.x < 544) st[threadIdx.x] = 0.f;
}

__global__ void k_prep(const float* __restrict__ x, const int* __restrict__ mask,
                       float* __restrict__ xm, float* __restrict__ m1, float* nP) {
    int s = blockIdx.x * blockDim.x + threadIdx.x;
    int act = 0;
    if (s < S1) {
        float m = (float)mask[s];
        m1[s] = m;
        xm[2*s]   = x[2*s]   * m;
        xm[2*s+1] = x[2*s+1] * m;
        act = (m > 0.f);
    }
    __shared__ int sh[256];
    sh[threadIdx.x] = act; __syncthreads();
    for (int o = 128; o > 0; o >>= 1) { if (threadIdx.x < o) sh[threadIdx.x] += sh[threadIdx.x+o]; __syncthreads(); }
    if (threadIdx.x == 0 && sh[0]) atomicAdd(nP, (float)sh[0]);
}

// weight transpose -> fp16 hi only: W[k][ldb] (fp32) -> Wh[n][K]
template<int REMAP>
__global__ void k_wt(const float* __restrict__ W, __half* __restrict__ Wh,
                     int K, int N, int ldb) {
    __shared__ float t[32][33];
    int k = blockIdx.x*32 + threadIdx.y;
    int n = blockIdx.y*32 + threadIdx.x;
    int nn = (REMAP && n >= 256) ? n + 256 : n;
    t[threadIdx.y][threadIdx.x] = (k < K && n < N) ? W[(size_t)k*ldb + nn] : 0.f;
    __syncthreads();
    int ko = blockIdx.x*32 + threadIdx.x;
    int no = blockIdx.y*32 + threadIdx.y;
    if (ko < K) Wh[(size_t)no*K + ko] = __float2half_rn(t[threadIdx.x][threadIdx.y]);
}

template<int CSH>
__global__ void k_apply3(const float* __restrict__ v, const float* __restrict__ mf,
                         int sites,
                         const float* __restrict__ sumP, const float* __restrict__ sqP,
                         const float* __restrict__ nP,
                         const float* __restrict__ gamma, const float* __restrict__ beta,
                         __half* __restrict__ oh, __half* __restrict__ ol) {
    constexpr int C = 1 << CSH;
    __shared__ float sc[C], so[C];
    if (threadIdx.x < C) {
        float n = fmaxf(nP[0], 1.f);
        float mean = sumP[threadIdx.x] / n;
        float var  = sqP[threadIdx.x] / n - mean*mean;
        float rs   = rsqrtf(var + EPS) * gamma[threadIdx.x];
        sc[threadIdx.x] = rs;
        so[threadIdx.x] = beta[threadIdx.x] - mean * rs;
    }
    __syncthreads();
    int i = blockIdx.x * blockDim.x + threadIdx.x;
    int total4 = (sites << CSH) >> 2;
    if (i < total4) {
        int e = i * 4;
        int c0 = e & (C-1);
        float m = mf[e >> CSH];
        float4 t = *reinterpret_cast<const float4*>(&v[e]);
        t.x = fmaxf(t.x*sc[c0+0] + so[c0+0], 0.f) * m;
        t.y = fmaxf(t.y*sc[c0+1] + so[c0+1], 0.f) * m;
        t.z = fmaxf(t.z*sc[c0+2] + so[c0+2], 0.f) * m;
        t.w = fmaxf(t.w*sc[c0+3] + so[c0+3], 0.f) * m;
        *reinterpret_cast<uint2*>(&oh[e]) = make_uint2(hpack(t.x, t.y), hpack(t.z, t.w));
        *reinterpret_cast<uint2*>(&ol[e]) =
            make_uint2(hpack(hres(t.x), hres(t.y)), hpack(hres(t.z), hres(t.w)));
    }
}

template<int CSH>
__global__ void k_poolbn(const float* __restrict__ in, const float* __restrict__ mfin,
                         const float* __restrict__ sumP, const float* __restrict__ sqP,
                         const float* __restrict__ nP,
                         const float* __restrict__ gamma, const float* __restrict__ beta,
                         __half* __restrict__ oh, __half* __restrict__ ol,
                         float* __restrict__ mfout,
                         int Hi, int Wi, int Ho, int Wo, float* cntP) {
    constexpr int C = 1 << CSH;
    __shared__ float sc[C], so[C];
    if (threadIdx.x < C) {
        float n = fmaxf(nP[0], 1.f);
        float mean = sumP[threadIdx.x] / n;
        float var  = sqP[threadIdx.x] / n - mean*mean;
        float rs   = rsqrtf(var + EPS) * gamma[threadIdx.x];
        sc[threadIdx.x] = rs;
        so[threadIdx.x] = beta[threadIdx.x] - mean * rs;
    }
    __syncthreads();
    int e = blockIdx.x * blockDim.x + threadIdx.x;
    int total = B_ * Ho * Wo * C;
    int newact = 0;
    if (e < total) {
        int c = e & (C-1);
        int s = e >> CSH;
        int b = s / (Ho*Wo); int r = s - b*(Ho*Wo);
        int y = r / Wo;      int xo = r - y*Wo;
        float best = -1e30f, mm = 0.f;
        float fc = sc[c], fo = so[c];
        #pragma unroll
        for (int dy = 0; dy < 3; dy++)
            #pragma unroll
            for (int dx = 0; dx < 3; dx++) {
                int si = (b*Hi + 2*y + dy) * Wi + 2*xo + dx;
                float m = mfin[si];
                mm = fmaxf(mm, m);
                float vv = -1e30f;
                if (m > 0.f) vv = fmaxf(in[(size_t)si * C + c] * fc + fo, 0.f);
                best = fmaxf(best, vv);
            }
        float v = (mm > 0.f) ? best : 0.f;
        oh[e] = __float2half_rn(v);
        ol[e] = __float2half_rn(hres(v));
        if (c == 0) { mfout[s] = mm; newact = (mm > 0.f); }
    }
    if (cntP) {
        __shared__ int sh[256];
        sh[threadIdx.x] = newact; __syncthreads();
        for (int o = 128; o > 0; o >>= 1) { if (threadIdx.x < o) sh[threadIdx.x] += sh[threadIdx.x+o]; __syncthreads(); }
        if (threadIdx.x == 0 && sh[0]) atomicAdd(cntP, (float)sh[0]);
    }
}

// LSTM; gates rows ordered m = r*2048 + b
__global__ void k_lstm(const float* __restrict__ gates, const float* __restrict__ m3,
                       __half* __restrict__ fh, __half* __restrict__ fl) {
    int e = blockIdx.x * blockDim.x + threadIdx.x;
    if (e >= S3 * 256) return;
    int c = e & 255;
    int s = e >> 8;              // gate row = r*2048 + b
    int b = s & 2047, r = s >> 11;
    const float* g = gates + (size_t)s * 768;
    float gi = g[c], go = g[256 + c], gg = g[512 + c];
    float si = 1.f / (1.f + __expf(-gi));
    float so = 1.f / (1.f + __expf(-go));
    float cc = si * tanhf(gg);
    float hh = so * tanhf(cc) * m3[b*35 + r];
    fh[b*8960 + c*35 + r] = __float2half_rn(hh);
    fl[b*8960 + c*35 + r] = __float2half_rn(hres(hh));
}

// FC1 split-K finalize
__global__ void k_fin(const float* __restrict__ y1f, const float* __restrict__ bias,
                      __half* __restrict__ oh, __half* __restrict__ ol) {
    int i = (blockIdx.x * blockDim.x + threadIdx.x) * 4;
    if (i >= B_*1024) return;
    float4 a = *reinterpret_cast<const float4*>(&y1f[i]);
    float4 b = *reinterpret_cast<const float4*>(&y1f[B_*1024 + i]);
    int n = i & 1023;
    float4 t;
    t.x = fmaxf(a.x + b.x + bias[n],   0.f);
    t.y = fmaxf(a.y + b.y + bias[n+1], 0.f);
    t.z = fmaxf(a.z + b.z + bias[n+2], 0.f);
    t.w = fmaxf(a.w + b.w + bias[n+3], 0.f);
    *reinterpret_cast<uint2*>(&oh[i]) = make_uint2(hpack(t.x, t.y), hpack(t.z, t.w));
    *reinterpret_cast<uint2*>(&ol[i]) =
        make_uint2(hpack(hres(t.x), hres(t.y)), hpack(hres(t.z), hres(t.w)));
}

// ---------------- param blocks ----------------
struct GemmP {
    const float* A; const float* Bw; const float* bias; float* C;
    int M, N, K, ldb;
    const float* img;
    const float* mf; float* sumP; float* sqP;
};
struct GemmB {
    const __half *Ah, *Al;
    const __half *Bh;
    const float* bias; float* C;
    int M, N, K;
    const float* mf; float* sumP; float* sqP;
    __half *oh, *ol;
};

// ---------------- HMMA fp16 (A split, B hi) GEMM, TN in {32,64} ----------------
template<int TN, int MODE, int EPI, int STAT, int IH, int IW, int IC>
__global__ void __launch_bounds__(256) k_hm2(GemmB p) {
    constexpr int TM = 128, BK = 64;
    constexpr int IM = (TN == 64) ? 2 : 1;
    constexpr int LIC = ilog2c(IC);
    constexpr int LTN = ilog2c(TN);
    constexpr int A_BYTES = TM * 128;
    constexpr int B_BYTES = TN * 128;
    constexpr int BUF = 2*A_BYTES + B_BYTES;
    constexpr int BCH = TN * 8 / 256;
    constexpr int CST = TN + 1;

    extern __shared__ char sm[];
    const int tid = threadIdx.x;
    const int wid = tid >> 5, lid = tid & 31;
    const int wm = (TN == 64) ? (wid >> 1) : wid;
    const int wn = (TN == 64) ? (wid & 1) : 0;
    const int m0 = blockIdx.y * TM;
    const int n0 = blockIdx.x * TN;
    const uint32_t sbuf = smem_u32(sm);

    float acc[IM][4][4];
    #pragma unroll
    for (int i = 0; i < IM; i++)
        #pragma unroll
        for (int j = 0; j < 4; j++)
            #pragma unroll
            for (int q = 0; q < 4; q++) acc[i][j][q] = 0.f;

    const int row = tid >> 1;
    const int kt  = (tid & 1) * 32;
    int sbm = 0, sy = 0, sx = 0;
    if (MODE == 1) {
        int m = m0 + row;
        int b = m / (IH*IW);
        int r = m - b*(IH*IW);
        sy = r / IW;
        sx = r - sy*IW;
        sbm = b*IH*IW;
    }

    uint2 ahr[8], alr[8];
    uint4 bhr[BCH];

    auto load_tile = [&](int k0) {
        #pragma unroll
        for (int j = 0; j < 8; j++) {
            int k = k0 + kt + j*4;
            uint2 vh = make_uint2(0u, 0u), vl = vh;
            if (k < p.K) {
                size_t idx;
                bool ok = true;
                if (MODE == 0) {
                    idx = (size_t)(m0 + row) * p.K + k;
                } else {
                    int t9 = k >> LIC;
                    int c0 = k & (IC-1);
                    int ky = t9 / 3, kx = t9 - 3*ky;
                    int yy = sy + ky - 1, xx = sx + kx - 1;
                    ok = (yy >= 0 && yy < IH && xx >= 0 && xx < IW);
                    idx = (size_t)(sbm + yy*IW + xx) * IC + c0;
                }
                if (ok) {
                    vh = *reinterpret_cast<const uint2*>(&p.Ah[idx]);
                    vl = *reinterpret_cast<const uint2*>(&p.Al[idx]);
                }
            }
            ahr[j] = vh; alr[j] = vl;
        }
        #pragma unroll
        for (int e = 0; e < BCH; e++) {
            int ge = tid + e*256;
            int n  = ge >> 3;
            int kc = ge & 7;
            int k  = k0 + kc*8;
            uint4 vh = make_uint4(0u,0u,0u,0u);
            if (k < p.K)
                vh = *reinterpret_cast<const uint4*>(&p.Bh[(size_t)(n0 + n) * p.K + k]);
            bhr[e] = vh;
        }
    };

    auto store_tile = [&](int bb) {
        char* Ah = sm + bb;
        char* Al = Ah + A_BYTES;
        char* Bh = Ah + 2*A_BYTES;
        #pragma unroll
        for (int j = 0; j < 8; j++) {
            uint32_t so = SWZ128((uint32_t)(row*128 + (kt + j*4)*2));
            *reinterpret_cast<uint2*>(Ah + so) = ahr[j];
            *reinterpret_cast<uint2*>(Al + so) = alr[j];
        }
        #pragma unroll
        for (int e = 0; e < BCH; e++) {
            int ge = tid + e*256;
            int n  = ge >> 3;
            int kc = ge & 7;
            uint32_t so = SWZ128((uint32_t)(n*128 + kc*16));
            *reinterpret_cast<uint4*>(Bh + so) = bhr[e];
        }
    };

    auto consume = [&](int bb) {
        uint32_t AH = sbuf + bb;
        uint32_t AL = AH + A_BYTES;
        uint32_t BH = AH + 2*A_BYTES;
        #pragma unroll
        for (int ks = 0; ks < 4; ks++) {
            uint32_t bh[2][4];
            #pragma unroll
            for (int jp = 0; jp < 2; jp++) {
                int n_r = wn*32 + jp*16 + (lid & 7) + ((lid >> 4) << 3);
                int kb  = ks*32 + (((lid >> 3) & 1) << 4);
                LDSM_X4(bh[jp][0], bh[jp][1], bh[jp][2], bh[jp][3],
                        BH + SWZ128((uint32_t)(n_r*128 + kb)));
            }
            #pragma unroll
            for (int im = 0; im < IM; im++) {
                int row_a = wm*(16*IM) + im*16 + (lid & 15);
                int kb    = ks*32 + (lid >> 4) * 16;
                uint32_t off = SWZ128((uint32_t)(row_a*128 + kb));
                uint32_t ah[4], al[4];
                LDSM_X4(ah[0], ah[1], ah[2], ah[3], AH + off);
                LDSM_X4(al[0], al[1], al[2], al[3], AL + off);
                #pragma unroll
                for (int jn = 0; jn < 4; jn++) {
                    int jp = jn >> 1, s = (jn & 1) * 2;
                    MMA_F16(acc[im][jn], ah[0], ah[1], ah[2], ah[3], bh[jp][s], bh[jp][s+1]);
                    MMA_F16(acc[im][jn], al[0], al[1], al[2], al[3], bh[jp][s], bh[jp][s+1]);
                }
            }
        }
    };

    const int T = (p.K + BK - 1) / BK;
    load_tile(0);
    store_tile(0);
    __syncthreads();

    for (int t = 0; t < T; t++) {
        if (t + 1 < T) load_tile((t + 1) * BK);
        consume((t & 1) * BUF);
        if (t + 1 < T) store_tile(((t + 1) & 1) * BUF);
        __syncthreads();
    }

    float* cs   = reinterpret_cast<float*>(sm);
    float* mrow = cs + TM*CST;
    float* rs   = mrow + TM;
    float* rq   = rs + 256;
    #pragma unroll
    for (int im = 0; im < IM; im++) {
        int r0 = wm*(16*IM) + im*16 + (lid >> 2);
        #pragma unroll
        for (int jn = 0; jn < 4; jn++) {
            int c = wn*32 + jn*8 + (lid & 3)*2;
            cs[r0*CST + c]       = acc[im][jn][0];
            cs[r0*CST + c + 1]   = acc[im][jn][1];
            cs[(r0+8)*CST + c]   = acc[im][jn][2];
            cs[(r0+8)*CST + c+1] = acc[im][jn][3];
        }
    }
    if (STAT && tid < TM) mrow[tid] = p.mf[m0 + tid];
    __syncthreads();

    float lsum = 0.f, lsq = 0.f;
    for (int e = tid; e < TM*TN; e += 256) {
        int rr = e >> LTN;
        int cc = e & (TN-1);
        int n  = n0 + cc;
        float v = cs[rr*CST + cc];
        if (STAT) {
            float mk = mrow[rr];
            float xv = (mk > 0.f) ? v : 0.f;
            lsum += xv; lsq += xv*xv;
        }
        if (n < p.N) {
            if (EPI == 1 || EPI == 2 || EPI == 3) {
                int nnb = (EPI == 3 && n >= 256) ? n + 256 : n;
                v += p.bias[nnb];
                if (EPI == 2) v = fmaxf(v, 0.f);
                p.C[(size_t)(m0 + rr) * p.N + n] = v;
            } else if (EPI == 4) {
                v = fmaxf(v + p.bias[n], 0.f);
                p.oh[(size_t)(m0 + rr) * p.N + n] = __float2half_rn(v);
                p.ol[(size_t)(m0 + rr) * p.N + n] = __float2half_rn(hres(v));
            } else {
                p.C[(size_t)(m0 + rr) * p.N + n] = v;
            }
        }
    }
    if (STAT) {
        rs[tid] = lsum; rq[tid] = lsq;
        __syncthreads();
        if (tid < TN) {
            float s = 0.f, q = 0.f;
            #pragma unroll
            for (int g = 0; g < 256/TN; g++) { s += rs[tid + g*TN]; q += rq[tid + g*TN]; }
            if (n0 + tid < p.N) {
                atomicAdd(&p.sumP[n0 + tid], s);
                atomicAdd(&p.sqP[n0 + tid], q);
            }
        }
    }
}

// ---------------- HMMA fp16 (A split, B hi) GEMM, TM=128 x TN=128, 3-stage cp.async ----
// MODE 0: dense. MODE 1: im2col. MODE 2: gate mode (rows m = r*2048 + b).
// SPLIT=1: blockIdx.z K-half partials.
template<int MODE, int EPI, int STAT, int SPLIT, int IH, int IW, int IC>
__global__ void __launch_bounds__(256, 2) k_hm3(GemmB p) {
    constexpr int TM = 128, TN = 128, BK = 32;
    constexpr int LIC = ilog2c(IC);
    constexpr int A_BYTES = TM * 128;          // rows [Ah 64B | Al 64B]
    constexpr int B_BYTES = TN * 128;          // rows [Bh 64B | unused]
    constexpr int STAGE = A_BYTES + B_BYTES;

    extern __shared__ char sm[];
    const int tid = threadIdx.x;
    const int wid = tid >> 5, lid = tid & 31;
    const int wm = wid >> 2;
    const int wn = wid & 3;
    const int m0 = blockIdx.y * TM;
    const int n0 = blockIdx.x * TN;
    const int koff = SPLIT ? (int)blockIdx.z * (p.K >> 1) : 0;
    const int KT   = SPLIT ? (p.K >> 1) : p.K;
    float* Cw = SPLIT ? p.C + (size_t)blockIdx.z * ((size_t)p.M * p.N) : p.C;
    const uint32_t sbuf = smem_u32(sm);

    float acc[4][4][4];
    #pragma unroll
    for (int i = 0; i < 4; i++)
        #pragma unroll
        for (int j = 0; j < 4; j++)
            #pragma unroll
            for (int q = 0; q < 4; q++) acc[i][j][q] = 0.f;

    const int row  = tid >> 1;
    const int half = tid & 1;
    int sbm = 0, sy = 0, sx = 0, vmask = 0;
    if (MODE == 1) {
        int m = m0 + row;
        int b = m / (IH*IW);
        int r = m - b*(IH*IW);
        sy = r / IW;
        sx = r - sy*IW;
        sbm = b*IH*IW;
    } else if (MODE == 2) {
        int rt = m0 >> 11;
        sy = rt / IW;
        sx = rt - sy*IW;
        sbm = ((m0 & 2047) + row) * (IH*IW);
        #pragma unroll
        for (int t = 0; t < 9; t++) {
            int dy = t/3, dx = t - 3*(t/3);
            int yy = sy + dy - 1, xx = sx + dx - 1;
            if (yy >= 0 && yy < IH && xx >= 0 && xx < IW) vmask |= 1 << t;
        }
    }

    auto issue_stage = [&](int k0, int bb) {
        {
            const __half* src = half ? p.Al : p.Ah;
            bool ok = true;
            size_t idx = 0;
            if (MODE == 0) {
                idx = (size_t)(m0 + row) * p.K + koff + k0;
            } else if (MODE == 1) {
                int t9 = k0 >> LIC;
                int c0 = k0 & (IC-1);
                int ky = t9 / 3, kx = t9 - 3*ky;
                int yy = sy + ky - 1, xx = sx + kx - 1;
                ok = (yy >= 0 && yy < IH && xx >= 0 && xx < IW);
                idx = ok ? (size_t)(sbm + yy*IW + xx) * IC + c0 : 0;
            } else {
                int t9 = k0 >> LIC;
                int ky = t9 / 3, kx = t9 - 3*ky;
                idx = (size_t)(sbm + (sy + ky - 1)*IW + (sx + kx - 1)) * IC + (k0 & (IC-1));
            }
            const char* g = reinterpret_cast<const char*>(src + idx);
            uint32_t okb = ok ? 16u : 0u;
            #pragma unroll
            for (int j = 0; j < 4; j++) {
                uint32_t dst = sbuf + bb + SWZ128((uint32_t)(row*128 + half*64 + j*16));
                CP16(dst, g + j*16, okb);
            }
        }
        if (half == 0) {   // B hi only
            const char* g = reinterpret_cast<const char*>(p.Bh + (size_t)(n0 + row) * p.K + koff + k0);
            #pragma unroll
            for (int j = 0; j < 4; j++) {
                uint32_t dst = sbuf + bb + A_BYTES + SWZ128((uint32_t)(row*128 + j*16));
                CP16(dst, g + j*16, 16u);
            }
        }
    };

    auto consume = [&](int bb) {
        uint32_t Abase = sbuf + bb;
        uint32_t Bbase = Abase + A_BYTES;
        #pragma unroll
        for (int ks = 0; ks < 2; ks++) {
            uint32_t bh[2][4];
            #pragma unroll
            for (int jp = 0; jp < 2; jp++) {
                int n_r = wn*32 + jp*16 + (lid & 7) + ((lid >> 4) << 3);
                int kb  = ks*32 + (((lid >> 3) & 1) << 4);
                LDSM_X4(bh[jp][0], bh[jp][1], bh[jp][2], bh[jp][3],
                        Bbase + SWZ128((uint32_t)(n_r*128 + kb)));
            }
            #pragma unroll
            for (int im = 0; im < 4; im++) {
                int row_a = wm*64 + im*16 + (lid & 15);
                int kb    = ks*32 + ((lid >> 4) << 4);
                uint32_t ah[4], al[4];
                LDSM_X4(ah[0], ah[1], ah[2], ah[3],
                        Abase + SWZ128((uint32_t)(row_a*128 + kb)));
                LDSM_X4(al[0], al[1], al[2], al[3],
                        Abase + SWZ128((uint32_t)(row_a*128 + 64 + kb)));
                #pragma unroll
                for (int jn = 0; jn < 4; jn++) {
                    int jp = jn >> 1, s = (jn & 1) * 2;
                    MMA_F16(acc[im][jn], ah[0], ah[1], ah[2], ah[3], bh[jp][s], bh[jp][s+1]);
                    MMA_F16(acc[im][jn], al[0], al[1], al[2], al[3], bh[jp][s], bh[jp][s+1]);
                }
            }
        }
    };

    auto advance = [&](int k0) {
        if (MODE == 2) {
            k0 += BK;
            while (k0 < KT && !((vmask >> (k0 >> LIC)) & 1))
                k0 = (((k0 >> LIC) + 1) << LIC);
            return k0;
        }
        return k0 + BK;
    };
    int kis, T;
    if (MODE == 2) {
        kis = 0;
        while (!((vmask >> (kis >> LIC)) & 1)) kis += (1 << LIC);
        T = __popc(vmask) * (IC / BK);
    } else {
        kis = 0;
        T = KT / BK;
    }

    issue_stage(kis, 0);
    CP_COMMIT();
    kis = advance(kis);
    if (T > 1) issue_stage(kis, STAGE);
    CP_COMMIT();
    kis = advance(kis);

    for (int t = 0; t < T; t++) {
        CP_WAIT1();
        __syncthreads();
        if (t + 2 < T) { issue_stage(kis, ((t + 2) % 3) * STAGE); kis = advance(kis); }
        CP_COMMIT();
        consume((t % 3) * STAGE);
    }
    CP_WAIT0();
    __syncthreads();

    constexpr int CST = 130;
    float* cs   = reinterpret_cast<float*>(sm);
    float* mrow = cs + 64*CST;
    float* rs   = mrow + 128;
    float* rq   = rs + 256;
    if (STAT && tid < 128) mrow[tid] = p.mf[m0 + tid];
    float lsum = 0.f, lsq = 0.f;

    #pragma unroll
    for (int h = 0; h < 2; h++) {
        if (wm == h) {
            #pragma unroll
            for (int im = 0; im < 4; im++) {
                int r0 = im*16 + (lid >> 2);
                #pragma unroll
                for (int jn = 0; jn < 4; jn++) {
                    int c = wn*32 + jn*8 + (lid & 3)*2;
                    cs[r0*CST + c]       = acc[im][jn][0];
                    cs[r0*CST + c + 1]   = acc[im][jn][1];
                    cs[(r0+8)*CST + c]   = acc[im][jn][2];
                    cs[(r0+8)*CST + c+1] = acc[im][jn][3];
                }
            }
        }
        __syncthreads();
        for (int e = tid; e < 64*128; e += 256) {
            int rr = e >> 7;
            int cc = e & 127;
            int n  = n0 + cc;
            float v = cs[rr*CST + cc];
            if (STAT) {
                float mk = mrow[h*64 + rr];
                float xv = (mk > 0.f) ? v : 0.f;
                lsum += xv; lsq += xv*xv;
            }
            if (n < p.N) {
                if (SPLIT) {
                    Cw[(size_t)(m0 + h*64 + rr) * p.N + n] = v;
                } else if (EPI == 1 || EPI == 2 || EPI == 3) {
                    int nnb = (EPI == 3 && n >= 256) ? n + 256 : n;
                    v += p.bias[nnb];
                    if (EPI == 2) v = fmaxf(v, 0.f);
                    Cw[(size_t)(m0 + h*64 + rr) * p.N + n] = v;
                } else if (EPI == 4) {
                    v = fmaxf(v + p.bias[n], 0.f);
                    p.oh[(size_t)(m0 + h*64 + rr) * p.N + n] = __float2half_rn(v);
                    p.ol[(size_t)(m0 + h*64 + rr) * p.N + n] = __float2half_rn(hres(v));
                } else {
                    Cw[(size_t)(m0 + h*64 + rr) * p.N + n] = v;
                }
            }
        }
        __syncthreads();
    }
    if (STAT) {
        rs[tid] = lsum; rq[tid] = lsq;
        __syncthreads();
        if (tid < 128) {
            float s = rs[tid] + rs[tid + 128];
            float q = rq[tid] + rq[tid + 128];
            if (n0 + tid < p.N) {
                atomicAdd(&p.sumP[n0 + tid], s);
                atomicAdd(&p.sqP[n0 + tid], q);
            }
        }
    }
}

// ---------------- packed-f32x2 GEMM (conv1 only), fused stats ----------------
template<int TN, int MODE, int EPI, int STAT, int IH, int IW, int IC>
__global__ void __launch_bounds__(256) k_gemm3(GemmP p) {
    constexpr int TM = 128, BK = 16;
    constexpr int TX = (TN == 32) ? 8 : 16;
    constexpr int NR = TN / TX;
    constexpr int TY = 256 / TX;
    constexpr int MR = TM / TY;
    constexpr int MP = MR / 2;
    constexpr int LIC = ilog2c(IC);
    constexpr int LTN = ilog2c(TN);
    constexpr int B_EPT = (BK * TN) / 256;

    __shared__ float  As[2][BK][TM];
    __shared__ float2 Bs[2][BK][TN];
    __shared__ float mrow[TM];
    __shared__ float sred[TN], qred[TN];

    const int tid = threadIdx.x;
    const int tx = tid % TX, ty = tid / TX;
    const int m0 = blockIdx.y * TM;
    const int n0 = blockIdx.x * TN;

    unsigned long long acc[MP][NR];
    #pragma unroll
    for (int i = 0; i < MP; i++)
        #pragma unroll
        for (int j = 0; j < NR; j++) acc[i][j] = 0ULL;

    int pm_b[2], pm_y[2], pm_x[2];
    if (MODE == 1) {
        #pragma unroll
        for (int i = 0; i < 2; i++) {
            int m = m0 + ((tid + i*256) >> 2);
            int b = m / (IH*IW);
            int r = m - b*(IH*IW);
            int y = r / IW;
            pm_b[i] = b*IH*IW;
            pm_y[i] = y;
            pm_x[i] = r - y*IW;
        }
    }

    float a_reg[8];
    float b_reg[B_EPT];

    auto load_tile = [&](int k0) {
        if (MODE == 1) {
            #pragma unroll
            for (int i = 0; i < 2; i++) {
                int gq = tid + i*256;
                int kbase = k0 + (gq & 3)*4;
                #pragma unroll
                for (int j = 0; j < 4; j++) {
                    int k = kbase + j;
                    float v = 0.f;
                    if (k < p.K) {
                        int c  = k & (IC-1);
                        int t9 = k >> LIC;
                        int ky = t9 / 3, kx = t9 - 3*ky;
                        int yy = pm_y[i] + ky - 1, xx = pm_x[i] + kx - 1;
                        if (yy >= 0 && yy < IH && xx >= 0 && xx < IW)
                            v = p.img[(size_t)(pm_b[i] + yy*IW + xx) * IC + c];
                    }
                    a_reg[i*4+j] = v;
                }
            }
        } else {
            #pragma unroll
            for (int i = 0; i < 2; i++) {
                int gq = tid + i*256;
                int m = m0 + (gq >> 2);
                int k = k0 + (gq & 3) * 4;
                float4 t = *reinterpret_cast<const float4*>(&p.A[(size_t)m * p.K + k]);
                a_reg[i*4+0] = t.x; a_reg[i*4+1] = t.y;
                a_reg[i*4+2] = t.z; a_reg[i*4+3] = t.w;
            }
        }
        #pragma unroll
        for (int e = 0; e < B_EPT; e++) {
            int ge = tid + e*256;
            int kl = ge >> LTN;
            int n  = ge & (TN-1);
            int k  = k0 + kl;
            int nn = n0 + n;
            float v = 0.f;
            if (k < p.K && nn < p.N) v = p.Bw[(size_t)k * p.ldb + nn];
            b_reg[e] = v;
        }
    };

    auto store_tile = [&](int buf) {
        #pragma unroll
        for (int i = 0; i < 2; i++) {
            int gq = tid + i*256;
            int ml = gq >> 2;
            int kq = (gq & 3) * 4;
            #pragma unroll
            for (int j = 0; j < 4; j++) As[buf][kq+j][ml] = a_reg[i*4+j];
        }
        #pragma unroll
        for (int e = 0; e < B_EPT; e++) {
            int ge = tid + e*256;
            int kl = ge >> LTN;
            int n  = ge & (TN-1);
            Bs[buf][kl][n] = make_float2(b_reg[e], b_reg[e]);
        }
    };

    const int nTiles = (p.K + BK - 1) / BK;
    load_tile(0);
    store_tile(0);
    __syncthreads();

    for (int t = 0; t < nTiles; t++) {
        int cur = t & 1;
        if (t + 1 < nTiles) load_tile((t + 1) * BK);
        #pragma unroll
        for (int kk = 0; kk < BK; kk++) {
            unsigned long long af[MP], bf[NR];
            const ulonglong2* ap = reinterpret_cast<const ulonglong2*>(&As[cur][kk][ty*MR]);
            #pragma unroll
            for (int i = 0; i < MP/2; i++) { ulonglong2 v = ap[i]; af[2*i] = v.x; af[2*i+1] = v.y; }
            const unsigned long long* bp = reinterpret_cast<const unsigned long long*>(&Bs[cur][kk][0]);
            #pragma unroll
            for (int nr = 0; nr < NR; nr++) bf[nr] = bp[tx + nr*TX];
            #pragma unroll
            for (int mp = 0; mp < MP; mp++)
                #pragma unroll
                for (int nr = 0; nr < NR; nr++)
                    FMA2(acc[mp][nr], af[mp], bf[nr]);
        }
        if (t + 1 < nTiles) store_tile(cur ^ 1);
        __syncthreads();
    }

    if (STAT) {
        if (tid < TN) { sred[tid] = 0.f; qred[tid] = 0.f; }
        if (tid < TM) mrow[tid] = p.mf[m0 + tid];
        __syncthreads();
    }

    #pragma unroll
    for (int mp = 0; mp < MP; mp++) {
        int m = m0 + ty*MR + 2*mp;
        #pragma unroll
        for (int nr = 0; nr < NR; nr++) {
            int n = n0 + tx + nr*TX;
            if (n >= p.N) continue;
            float lo = __uint_as_float((unsigned)(acc[mp][nr] & 0xFFFFFFFFULL));
            float hi = __uint_as_float((unsigned)(acc[mp][nr] >> 32));
            if (STAT) {
                float mk0 = mrow[ty*MR + 2*mp], mk1 = mrow[ty*MR + 2*mp + 1];
                float x0 = (mk0 > 0.f) ? lo : 0.f;
                float x1 = (mk1 > 0.f) ? hi : 0.f;
                atomicAdd(&sred[n - n0], x0 + x1);
                atomicAdd(&qred[n - n0], x0*x0 + x1*x1);
            }
            if (EPI >= 1) { float bb = p.bias[n]; lo += bb; hi += bb; }
            if (EPI == 2) { lo = fmaxf(lo, 0.f); hi = fmaxf(hi, 0.f); }
            p.C[(size_t)m       * p.N + n] = lo;
            p.C[(size_t)(m + 1) * p.N + n] = hi;
        }
    }
    if (STAT) {
        __syncthreads();
        if (tid < TN && n0 + tid < p.N) {
            atomicAdd(&p.sumP[n0 + tid], sred[tid]);
            atomicAdd(&p.sqP[n0 + tid], qred[tid]);
        }
    }
}

// ---------------- launcher ----------------
static inline int ceil_div(int a, int b) { return (a + b - 1) / b; }
#define HM_SMEM64 (2 * (2*128*128 + 64*128))   // 80 KB
#define HM_SMEM32 (2 * (2*128*128 + 32*128))   // 72 KB
#define HM3_SMEM  (3 * (128*128 + 128*128))    // 96 KB

extern "C" void kernel_launch(void* const* d_in, const int* in_sizes, int n_in,
                              void* d_out, int out_size) {
    const float* x    = (const float*)d_in[0];
    const int*   mask = (const int*)  d_in[1];
    const float* W1 = (const float*)d_in[2];  const float* ga1 = (const float*)d_in[3];  const float* be1 = (const float*)d_in[4];
    const float* W2 = (const float*)d_in[5];  const float* ga2 = (const float*)d_in[6];  const float* be2 = (const float*)d_in[7];
    const float* W3 = (const float*)d_in[8];  const float* ga3 = (const float*)d_in[9];  const float* be3 = (const float*)d_in[10];
    const float* W4 = (const float*)d_in[11]; const float* ga4 = (const float*)d_in[12]; const float* be4 = (const float*)d_in[13];
    const float* Wl = (const float*)d_in[14]; const float* bl  = (const float*)d_in[15];
    const float* lw1 = (const float*)d_in[16]; const float* lb1 = (const float*)d_in[17];
    const float* lw2 = (const float*)d_in[18]; const float* lb2 = (const float*)d_in[19];
    float* out = (float*)d_out;

    float *xm, *m1, *h1, *h2, *m2, *h3, *h4, *m3, *gates, *y1f, *st;
    __half *h1h, *h1l, *p1h, *p1l, *h3h, *h3l, *p2h, *p2l, *fh, *fl, *y1h, *y1l;
    __half *w2h, *w3h, *w4h, *wlh, *l1h, *l2h;
    cudaGetSymbolAddress((void**)&xm,  g_xm);   cudaGetSymbolAddress((void**)&m1,  g_m1);
    cudaGetSymbolAddress((void**)&h1,  g_h1);   cudaGetSymbolAddress((void**)&h2,  g_h2);
    cudaGetSymbolAddress((void**)&m2,  g_m2);   cudaGetSymbolAddress((void**)&h3,  g_h3);
    cudaGetSymbolAddress((void**)&h4,  g_h4);   cudaGetSymbolAddress((void**)&m3,  g_m3);
    cudaGetSymbolAddress((void**)&gates, g_gates);
    cudaGetSymbolAddress((void**)&y1f, g_y1f);  cudaGetSymbolAddress((void**)&st,  g_stats);
    cudaGetSymbolAddress((void**)&h1h, g_h1h);  cudaGetSymbolAddress((void**)&h1l, g_h1l);
    cudaGetSymbolAddress((void**)&p1h, g_p1h);  cudaGetSymbolAddress((void**)&p1l, g_p1l);
    cudaGetSymbolAddress((void**)&h3h, g_h3h);  cudaGetSymbolAddress((void**)&h3l, g_h3l);
    cudaGetSymbolAddress((void**)&p2h, g_p2h);  cudaGetSymbolAddress((void**)&p2l, g_p2l);
    cudaGetSymbolAddress((void**)&fh,  g_flath);cudaGetSymbolAddress((void**)&fl,  g_flatl);
    cudaGetSymbolAddress((void**)&y1h, g_y1h);  cudaGetSymbolAddress((void**)&y1l, g_y1l);
    cudaGetSymbolAddress((void**)&w2h, g_w2h);
    cudaGetSymbolAddress((void**)&w3h, g_w3h);
    cudaGetSymbolAddress((void**)&w4h, g_w4h);
    cudaGetSymbolAddress((void**)&wlh, g_wlh);
    cudaGetSymbolAddress((void**)&l1h, g_l1h);
    cudaGetSymbolAddress((void**)&l2h, g_l2h);

    float *sum1 = st+0,   *sq1 = st+16;
    float *sum2 = st+32,  *sq2 = st+64;
    float *sum3 = st+128, *sq3 = st+192;
    float *sum4 = st+256, *sq4 = st+384;
    float *n1 = st+512, *n2 = st+513;

    cudaFuncSetAttribute(k_hm2<32,1,0,1,H1_,W1_,16>,  cudaFuncAttributeMaxDynamicSharedMemorySize, HM_SMEM32);
    cudaFuncSetAttribute(k_hm2<64,1,0,1,H2_,W2_,32>,  cudaFuncAttributeMaxDynamicSharedMemorySize, HM_SMEM64);
    cudaFuncSetAttribute(k_hm2<64,0,1,0,1,1,16>,      cudaFuncAttributeMaxDynamicSharedMemorySize, HM_SMEM64);
    cudaFuncSetAttribute(k_hm3<1,0,1,0,H2_,W2_,64>,   cudaFuncAttributeMaxDynamicSharedMemorySize, HM3_SMEM);
    cudaFuncSetAttribute(k_hm3<2,3,0,0,H3_,W3_,128>,  cudaFuncAttributeMaxDynamicSharedMemorySize, HM3_SMEM);
    cudaFuncSetAttribute(k_hm3<0,0,0,1,1,1,32>,       cudaFuncAttributeMaxDynamicSharedMemorySize, HM3_SMEM);

    // weight transpose -> fp16 hi
    { dim3 b(32,32);
      k_wt<0><<<dim3(ceil_div(144,32),  1),  b>>>(W2,  w2h, 144,  32,   32);
      k_wt<0><<<dim3(ceil_div(288,32),  2),  b>>>(W3,  w3h, 288,  64,   64);
      k_wt<0><<<dim3(ceil_div(576,32),  4),  b>>>(W4,  w4h, 576,  128,  128);
      k_wt<1><<<dim3(ceil_div(1152,32), 24), b>>>(Wl,  wlh, 1152, 768,  1024);
      k_wt<0><<<dim3(ceil_div(8960,32), 32), b>>>(lw1, l1h, 8960, 1024, 1024);
      k_wt<0><<<dim3(ceil_div(1024,32), 14), b>>>(lw2, l2h, 1024, 420,  420);
    }

    k_zero_stats<<<1, 1024>>>(st);
    k_prep<<<ceil_div(S1, 256), 256>>>(x, mask, xm, m1, n1);

    // conv1: 2->16 (K=18) — FFMA2 + fused stats
    { GemmP p = { nullptr, W1, nullptr, h1, S1, 16, 18, 16, xm, m1, sum1, sq1 };
      k_gemm3<32,1,0,1,H1_,W1_,2><<<dim3(1, S1/128), 256>>>(p); }
    k_apply3<4><<<ceil_div(S1*16/4, 256), 256>>>(h1, m1, S1, sum1, sq1, n1, ga1, be1, h1h, h1l);

    // conv2: 16->32 (K=144) — HMMA fp16 TN=32 + fused stats
    { GemmB p = { h1h, h1l, w2h, nullptr, h2, S1, 32, 144, m1, sum2, sq2, nullptr, nullptr };
      k_hm2<32,1,0,1,H1_,W1_,16><<<dim3(1, S1/128), 256, HM_SMEM32>>>(p); }

    // pool1 + BN2 fused -> fp16, count n2
    k_poolbn<5><<<ceil_div(S2*32, 256), 256>>>(h2, m1, sum2, sq2, n1, ga2, be2,
                                               p1h, p1l, m2, H1_, W1_, H2_, W2_, n2);

    // conv3: 32->64 (K=288) — HMMA fp16 TN=64 + fused stats
    { GemmB p = { p1h, p1l, w3h, nullptr, h3, S2, 64, 288, m2, sum3, sq3, nullptr, nullptr };
      k_hm2<64,1,0,1,H2_,W2_,32><<<dim3(1, S2/128), 256, HM_SMEM64>>>(p); }
    k_apply3<6><<<ceil_div(S2*64/4, 256), 256>>>(h3, m2, S2, sum3, sq3, n2, ga3, be3, h3h, h3l);

    // conv4: 64->128 (K=576) — HMMA fp16 TN=128 cp.async + fused stats
    { GemmB p = { h3h, h3l, w4h, nullptr, h4, S2, 128, 576, m2, sum4, sq4, nullptr, nullptr };
      k_hm3<1,0,1,0,H2_,W2_,64><<<dim3(1, S2/128), 256, HM3_SMEM>>>(p); }

    // pool2 + BN4 fused -> fp16
    k_poolbn<7><<<ceil_div(S3*128, 256), 256>>>(h4, m2, sum4, sq4, n2, ga4, be4,
                                                p2h, p2l, m3, H2_, W2_, H3_, W3_, nullptr);

    // gate conv: 128->768 (f skipped; remap in k_wt) + bias (K=1152) — HMMA cp.async,
    // gate mode: rows m = r*2048 + b, tile-uniform taps, invalid taps skipped
    { GemmB p = { p2h, p2l, wlh, bl, gates, S3, 768, 1152, nullptr, nullptr, nullptr, nullptr, nullptr };
      k_hm3<2,3,0,0,H3_,W3_,128><<<dim3(6, S3/128), 256, HM3_SMEM>>>(p); }

    // LSTM nonlinearity (gate rows r*2048+b) -> flat fp16 hi/lo in (C,H,W) order
    k_lstm<<<ceil_div(S3*256, 256), 256>>>(gates, m3, fh, fl);

    // FC1: [2048,8960]x[8960,1024] — HMMA cp.async, split-K=2 -> fp32 partials
    { GemmB p = { fh, fl, l1h, nullptr, y1f, B_, 1024, 8960, nullptr, nullptr, nullptr, nullptr, nullptr };
      k_hm3<0,0,0,1,1,1,32><<<dim3(8, B_/128, 2), 256, HM3_SMEM>>>(p); }
    k_fin<<<ceil_div(B_*1024/4, 256), 256>>>(y1f, lb1, y1h, y1l);

    // FC2: [2048,1024]x[1024,420] + bias -> out — HMMA fp16 TN=64
    { GemmB p = { y1h, y1l, l2h, lb2, out, B_, 420, 1024, nullptr, nullptr, nullptr, nullptr, nullptr };
      k_hm2<64,0,1,0,1,1,16><<<dim3(7, B_/128), 256, HM_SMEM64>>>(p); }
}